// round 2
// baseline (speedup 1.0000x reference)
#include <cuda_runtime.h>
#include <cstddef>

#define BB 4
#define HH 160
#define WW 160
#define HWSZ (HH*WW)

typedef unsigned long long ull;

// ---------------- packed f32x2 helpers -------------------------------------
__device__ __forceinline__ ull pk2(float lo, float hi) {
    ull r; asm("mov.b64 %0,{%1,%2};" : "=l"(r) : "f"(lo), "f"(hi)); return r;
}
__device__ __forceinline__ void upk2(ull v, float& lo, float& hi) {
    asm("mov.b64 {%0,%1},%2;" : "=f"(lo), "=f"(hi) : "l"(v));
}
__device__ __forceinline__ ull f2fma(ull a, ull b, ull c) {
    ull d; asm("fma.rn.f32x2 %0,%1,%2,%3;" : "=l"(d) : "l"(a), "l"(b), "l"(c)); return d;
}
__device__ __forceinline__ ull f2mul(ull a, ull b) {
    ull d; asm("mul.rn.f32x2 %0,%1,%2;" : "=l"(d) : "l"(a), "l"(b)); return d;
}

// ---------------- scratch (device globals; no allocation allowed) ----------
__device__ __align__(128) float g_A32[BB*32*HWSZ];   // relu(conv3x3(x, ba_w1))
__device__ __align__(128) float g_gmap[BB*HWSZ];     // g = 1 + sigmoid(att + edge)
__device__ __align__(128) float g_smap[BB*HWSZ];     // s = g * sum_c x
__device__ __align__(128) float g_fusion[BB*64*HWSZ];
__device__ __align__(128) float g_t[BB*64*HWSZ];
__device__ __align__(128) float g_Weff[64*64];
__device__ __align__(128) float g_beff[64];

// ---------------- K0: effective dyn1d weights (sum over K) -----------------
__global__ void build_weff(const float* __restrict__ rk5w, const float* __restrict__ rk5b,
                           const float* __restrict__ rk7w, const float* __restrict__ rk7b,
                           const float* __restrict__ lk5w, const float* __restrict__ lk5b,
                           const float* __restrict__ lk7w, const float* __restrict__ lk7b)
{
    int id = blockIdx.x*blockDim.x + threadIdx.x;
    if (id >= 64*64) return;
    int m = id >> 6, c = id & 63;
    const float* w; const float* bs; int K, o;
    if      (m < 16) { w = rk5w; bs = rk5b; K = 5; o = m;    }
    else if (m < 32) { w = rk7w; bs = rk7b; K = 7; o = m-16; }
    else if (m < 48) { w = lk5w; bs = lk5b; K = 5; o = m-32; }
    else             { w = lk7w; bs = lk7b; K = 7; o = m-48; }
    float acc = 0.f;
    for (int k = 0; k < K; k++) acc += w[(o*K + k)*64 + c];
    g_Weff[m*64 + c] = acc;
    if (c == 0) {
        float bacc = 0.f;
        for (int k = 0; k < K; k++) bacc += bs[o*K + k];
        g_beff[m] = bacc;
    }
}

// ---------------- tiled 3x3 conv (pad=1), f32x2 packed ---------------------
// Tile: 32 wide x 8 tall. 256 threads = 64 px-threads (4 vertical px each)
// x 4 oc-groups. Weights duplicated in smem so LDS.128 yields packed operands.
// EPI: 0 = bias+relu, 1 = bias+bn+relu
template<int CIN, int COUT, int EPI>
__global__ __launch_bounds__(256)
void conv3x3_k(const float* __restrict__ in, const float* __restrict__ wt,
               const float* __restrict__ bias,
               const float* __restrict__ bng, const float* __restrict__ bnb,
               const float* __restrict__ bnm, const float* __restrict__ bnv,
               float* __restrict__ out)
{
    constexpr int NOC = COUT/4;      // oc per thread
    constexpr int CH  = 4;           // ci chunk
    __shared__ float s_in[CH][10][34];
    __shared__ __align__(16) float s_w[CH][COUT][20];  // 9 taps duplicated + pad

    const int w0 = blockIdx.x*32, h0 = blockIdx.y*8;
    const int b  = blockIdx.z;
    const int tid = threadIdx.x;
    const int ocg = tid >> 6;            // 0..3
    const int pt  = tid & 63;
    const int px  = pt & 31;
    const int py0 = (pt >> 5) * 4;       // 0 or 4

    ull accA[NOC], accB[NOC];
    #pragma unroll
    for (int i = 0; i < NOC; i++) { accA[i] = 0ULL; accB[i] = 0ULL; }

    for (int c0 = 0; c0 < CIN; c0 += CH) {
        // stage input tile with halo (zero padded)
        for (int i = tid; i < CH*340; i += 256) {
            int ci = i / 340, rem = i % 340;
            int r = rem / 34, cc = rem % 34;
            int gh = h0 - 1 + r, gw = w0 - 1 + cc;
            float v = 0.f;
            if (gh >= 0 && gh < HH && gw >= 0 && gw < WW)
                v = in[((size_t)(b*CIN + c0 + ci))*HWSZ + gh*WW + gw];
            s_in[ci][r][cc] = v;
        }
        // stage weights, duplicated into adjacent lanes
        for (int i = tid; i < CH*COUT*9; i += 256) {
            int ci = i / (COUT*9), rem = i % (COUT*9);
            int oc = rem / 9, k = rem % 9;
            float w = wt[((size_t)oc*CIN + c0 + ci)*9 + k];
            s_w[ci][oc][2*k]   = w;
            s_w[ci][oc][2*k+1] = w;
        }
        __syncthreads();

        #pragma unroll 1
        for (int ci = 0; ci < CH; ci++) {
            float v[6][3];
            #pragma unroll
            for (int dr = 0; dr < 6; dr++)
                #pragma unroll
                for (int dc = 0; dc < 3; dc++)
                    v[dr][dc] = s_in[ci][py0 + dr][px + dc];

            ull pA[9], pB[9];
            #pragma unroll
            for (int dr = 0; dr < 3; dr++)
                #pragma unroll
                for (int dc = 0; dc < 3; dc++) {
                    pA[dr*3+dc] = pk2(v[dr  ][dc], v[dr+1][dc]);
                    pB[dr*3+dc] = pk2(v[dr+2][dc], v[dr+3][dc]);
                }

            #pragma unroll
            for (int oc = 0; oc < NOC; oc++) {
                const float* wp = &s_w[ci][ocg*NOC + oc][0];
                ulonglong2 a0 = *(const ulonglong2*)(wp);       // w0,w1 (dup pairs)
                ulonglong2 a1 = *(const ulonglong2*)(wp + 4);   // w2,w3
                ulonglong2 a2 = *(const ulonglong2*)(wp + 8);   // w4,w5
                ulonglong2 a3 = *(const ulonglong2*)(wp + 12);  // w6,w7
                ull        a8 = *(const ull*)(wp + 16);         // w8
                accA[oc] = f2fma(a0.x, pA[0], accA[oc]);
                accA[oc] = f2fma(a0.y, pA[1], accA[oc]);
                accA[oc] = f2fma(a1.x, pA[2], accA[oc]);
                accA[oc] = f2fma(a1.y, pA[3], accA[oc]);
                accA[oc] = f2fma(a2.x, pA[4], accA[oc]);
                accA[oc] = f2fma(a2.y, pA[5], accA[oc]);
                accA[oc] = f2fma(a3.x, pA[6], accA[oc]);
                accA[oc] = f2fma(a3.y, pA[7], accA[oc]);
                accA[oc] = f2fma(a8,   pA[8], accA[oc]);
                accB[oc] = f2fma(a0.x, pB[0], accB[oc]);
                accB[oc] = f2fma(a0.y, pB[1], accB[oc]);
                accB[oc] = f2fma(a1.x, pB[2], accB[oc]);
                accB[oc] = f2fma(a1.y, pB[3], accB[oc]);
                accB[oc] = f2fma(a2.x, pB[4], accB[oc]);
                accB[oc] = f2fma(a2.y, pB[5], accB[oc]);
                accB[oc] = f2fma(a3.x, pB[6], accB[oc]);
                accB[oc] = f2fma(a3.y, pB[7], accB[oc]);
                accB[oc] = f2fma(a8,   pB[8], accB[oc]);
            }
        }
        __syncthreads();
    }

    #pragma unroll
    for (int oc = 0; oc < NOC; oc++) {
        int goc = ocg*NOC + oc;
        float o0, o1, o2, o3;
        upk2(accA[oc], o0, o1);
        upk2(accB[oc], o2, o3);
        float bv = bias[goc];
        o0 += bv; o1 += bv; o2 += bv; o3 += bv;
        if (EPI == 1) {
            float sc = bng[goc] * rsqrtf(bnv[goc] + 1e-5f);
            float sh = bnb[goc] - bnm[goc]*sc;
            o0 = o0*sc + sh; o1 = o1*sc + sh; o2 = o2*sc + sh; o3 = o3*sc + sh;
        }
        o0 = fmaxf(o0, 0.f); o1 = fmaxf(o1, 0.f);
        o2 = fmaxf(o2, 0.f); o3 = fmaxf(o3, 0.f);
        size_t base = ((size_t)(b*COUT + goc))*HWSZ + (size_t)(h0 + py0)*WW + (w0 + px);
        out[base         ] = o0;
        out[base + WW    ] = o1;
        out[base + 2*WW  ] = o2;
        out[base + 3*WW  ] = o3;
    }
}

// ---------------- K2: edge (grouped sobel) + attention + g,s ---------------
__global__ __launch_bounds__(256)
void edge_attn_k(const float* __restrict__ x,
                 const float* __restrict__ baw2, const float* __restrict__ bab2)
{
    __shared__ float s_in[8][18][18];
    const int h0 = blockIdx.y*16, w0 = blockIdx.x*16;
    const int b  = blockIdx.z;
    const int tid = threadIdx.x;
    const int px = tid & 15, py = tid >> 4;

    float edge = 0.f, sumx = 0.f;
    for (int c0 = 0; c0 < 64; c0 += 8) {
        for (int i = tid; i < 8*324; i += 256) {
            int ci = i / 324, rem = i % 324;
            int r = rem / 18, cc = rem % 18;
            int gh = h0 - 1 + r, gw = w0 - 1 + cc;
            float v = 0.f;
            if (gh >= 0 && gh < HH && gw >= 0 && gw < WW)
                v = x[((size_t)(b*64 + c0 + ci))*HWSZ + gh*WW + gw];
            s_in[ci][r][cc] = v;
        }
        __syncthreads();
        #pragma unroll 1
        for (int ci = 0; ci < 8; ci++) {
            float v00=s_in[ci][py  ][px], v01=s_in[ci][py  ][px+1], v02=s_in[ci][py  ][px+2];
            float v10=s_in[ci][py+1][px], v11=s_in[ci][py+1][px+1], v12=s_in[ci][py+1][px+2];
            float v20=s_in[ci][py+2][px], v21=s_in[ci][py+2][px+1], v22=s_in[ci][py+2][px+2];
            sumx += v11;
            if (c0 + ci < 32) {
                float gx = (v02 - v00) + 2.f*(v12 - v10) + (v22 - v20);
                edge += fabsf(gx);
            } else {
                float gy = (v20 - v00) + 2.f*(v21 - v01) + (v22 - v02);
                edge += fabsf(gy);
            }
        }
        __syncthreads();
    }
    edge *= (1.f/32.f);

    const int pix = (h0 + py)*WW + (w0 + px);
    float att = bab2[0];
    #pragma unroll 1
    for (int j = 0; j < 32; j++)
        att += baw2[j] * g_A32[((size_t)(b*32 + j))*HWSZ + pix];

    float z = att + edge;
    float a = 1.f / (1.f + expf(-z));
    float g = 1.f + a;
    g_gmap[(size_t)b*HWSZ + pix] = g;
    g_smap[(size_t)b*HWSZ + pix] = g * sumx;
}

// ---------------- K3: fusion = s * ( g * (Weff @ x) + beff ) ---------------
// 4 pixels/thread via f32x2, 2 output-groups of 32.
__global__ __launch_bounds__(256)
void fusion_k(const float* __restrict__ x)
{
    __shared__ ull  s_wd[64*64];   // duplicated pairs, 32KB
    __shared__ float s_be[64];
    const int tid = threadIdx.x;
    for (int i = tid; i < 4096; i += 256) {
        float w = g_Weff[i];
        s_wd[i] = pk2(w, w);
    }
    if (tid < 64) s_be[tid] = g_beff[tid];
    __syncthreads();

    const int b   = blockIdx.y;
    const int mg  = tid >> 7;              // 0 or 1
    const int pt  = tid & 127;
    const int pix = blockIdx.x*512 + pt*4;

    ull acc0[32], acc1[32];
    #pragma unroll
    for (int m = 0; m < 32; m++) { acc0[m] = 0ULL; acc1[m] = 0ULL; }

    #pragma unroll 1
    for (int ci = 0; ci < 64; ci++) {
        float4 xv = *(const float4*)&x[((size_t)(b*64 + ci))*HWSZ + pix];
        ull xp0 = pk2(xv.x, xv.y);
        ull xp1 = pk2(xv.z, xv.w);
        const ull* wrow = &s_wd[(size_t)mg*32*64 + ci];
        #pragma unroll
        for (int m = 0; m < 32; m++) {
            ull w = wrow[m*64];
            acc0[m] = f2fma(w, xp0, acc0[m]);
            acc1[m] = f2fma(w, xp1, acc1[m]);
        }
    }

    float4 gv = *(const float4*)&g_gmap[(size_t)b*HWSZ + pix];
    float4 sv = *(const float4*)&g_smap[(size_t)b*HWSZ + pix];
    ull gp0 = pk2(gv.x, gv.y), gp1 = pk2(gv.z, gv.w);
    ull sp0 = pk2(sv.x, sv.y), sp1 = pk2(sv.z, sv.w);

    #pragma unroll
    for (int m = 0; m < 32; m++) {
        int gm = mg*32 + m;
        ull be = pk2(s_be[gm], s_be[gm]);
        ull r0 = f2mul(sp0, f2fma(gp0, acc0[m], be));
        ull r1 = f2mul(sp1, f2fma(gp1, acc1[m], be));
        float4 o;
        upk2(r0, o.x, o.y);
        upk2(r1, o.z, o.w);
        *(float4*)&g_fusion[((size_t)(b*64 + gm))*HWSZ + pix] = o;
    }
}

// ---------------- K5: out = fc(t) + fc_b + residual ------------------------
__global__ __launch_bounds__(256)
void fc_k(const float* __restrict__ fcw, const float* __restrict__ fcb,
          const float* __restrict__ x, float* __restrict__ out)
{
    __shared__ ull  s_wd[64*64];
    __shared__ float s_b[64];
    const int tid = threadIdx.x;
    for (int i = tid; i < 4096; i += 256) {
        float w = fcw[i];
        s_wd[i] = pk2(w, w);
    }
    if (tid < 64) s_b[tid] = fcb[tid];
    __syncthreads();

    const int b   = blockIdx.y;
    const int mg  = tid >> 7;
    const int pt  = tid & 127;
    const int pix = blockIdx.x*512 + pt*4;

    ull acc0[32], acc1[32];
    #pragma unroll
    for (int m = 0; m < 32; m++) { acc0[m] = 0ULL; acc1[m] = 0ULL; }

    #pragma unroll 1
    for (int ci = 0; ci < 64; ci++) {
        float4 tv = *(const float4*)&g_t[((size_t)(b*64 + ci))*HWSZ + pix];
        ull tp0 = pk2(tv.x, tv.y);
        ull tp1 = pk2(tv.z, tv.w);
        const ull* wrow = &s_wd[(size_t)mg*32*64 + ci];
        #pragma unroll
        for (int m = 0; m < 32; m++) {
            ull w = wrow[m*64];
            acc0[m] = f2fma(w, tp0, acc0[m]);
            acc1[m] = f2fma(w, tp1, acc1[m]);
        }
    }

    #pragma unroll
    for (int m = 0; m < 32; m++) {
        int gm = mg*32 + m;
        float a0, a1, a2, a3;
        upk2(acc0[m], a0, a1);
        upk2(acc1[m], a2, a3);
        float bv = s_b[gm];
        size_t idx = ((size_t)(b*64 + gm))*HWSZ + pix;
        float4 rv = *(const float4*)&x[idx];
        float4 o;
        o.x = a0 + bv + rv.x;
        o.y = a1 + bv + rv.y;
        o.z = a2 + bv + rv.z;
        o.w = a3 + bv + rv.w;
        *(float4*)&out[idx] = o;
    }
}

// ---------------------------------------------------------------------------
extern "C" void kernel_launch(void* const* d_in, const int* in_sizes, int n_in,
                              void* d_out, int out_size)
{
    (void)in_sizes; (void)n_in; (void)out_size;
    const float* x     = (const float*)d_in[0];
    const float* ba_w1 = (const float*)d_in[1];
    const float* ba_b1 = (const float*)d_in[2];
    const float* ba_w2 = (const float*)d_in[3];
    const float* ba_b2 = (const float*)d_in[4];
    // d_in[5..12]: offset branch — dead code in the reference, skipped.
    const float* rk5w  = (const float*)d_in[13];
    const float* rk5b  = (const float*)d_in[14];
    const float* rk7w  = (const float*)d_in[15];
    const float* rk7b  = (const float*)d_in[16];
    const float* lk5w  = (const float*)d_in[17];
    const float* lk5b  = (const float*)d_in[18];
    const float* lk7w  = (const float*)d_in[19];
    const float* lk7b  = (const float*)d_in[20];
    const float* sfw   = (const float*)d_in[21];
    const float* sfb   = (const float*)d_in[22];
    const float* sfg   = (const float*)d_in[23];
    const float* sfbb  = (const float*)d_in[24];
    const float* sfm   = (const float*)d_in[25];
    const float* sfv   = (const float*)d_in[26];
    const float* fcw   = (const float*)d_in[27];
    const float* fcb   = (const float*)d_in[28];
    float* out = (float*)d_out;

    float *pA32, *pFus, *pT;
    cudaGetSymbolAddress((void**)&pA32, g_A32);
    cudaGetSymbolAddress((void**)&pFus, g_fusion);
    cudaGetSymbolAddress((void**)&pT,   g_t);

    build_weff<<<16, 256>>>(rk5w, rk5b, rk7w, rk7b, lk5w, lk5b, lk7w, lk7b);

    dim3 cgrid(WW/32, HH/8, BB);
    conv3x3_k<64,32,0><<<cgrid, 256>>>(x, ba_w1, ba_b1,
                                       nullptr, nullptr, nullptr, nullptr, pA32);
    dim3 egrid(WW/16, HH/16, BB);
    edge_attn_k<<<egrid, 256>>>(x, ba_w2, ba_b2);
    fusion_k<<<dim3(HWSZ/512, BB), 256>>>(x);
    conv3x3_k<64,64,1><<<cgrid, 256>>>(pFus, sfw, sfb, sfg, sfbb, sfm, sfv, pT);
    fc_k<<<dim3(HWSZ/512, BB), 256>>>(fcw, fcb, x, out);
}

// round 3
// speedup vs baseline: 1.0640x; 1.0640x over previous
#include <cuda_runtime.h>
#include <cstddef>

#define BB 4
#define HH 160
#define WW 160
#define HWSZ (HH*WW)

typedef unsigned long long ull;

// ---------------- packed f32x2 helpers -------------------------------------
__device__ __forceinline__ ull pk2(float lo, float hi) {
    ull r; asm("mov.b64 %0,{%1,%2};" : "=l"(r) : "f"(lo), "f"(hi)); return r;
}
__device__ __forceinline__ void upk2(ull v, float& lo, float& hi) {
    asm("mov.b64 {%0,%1},%2;" : "=f"(lo), "=f"(hi) : "l"(v));
}
__device__ __forceinline__ ull f2fma(ull a, ull b, ull c) {
    ull d; asm("fma.rn.f32x2 %0,%1,%2,%3;" : "=l"(d) : "l"(a), "l"(b), "l"(c)); return d;
}
__device__ __forceinline__ ull f2mul(ull a, ull b) {
    ull d; asm("mul.rn.f32x2 %0,%1,%2;" : "=l"(d) : "l"(a), "l"(b)); return d;
}

// ---------------- scratch (device globals; no allocation allowed) ----------
__device__ __align__(128) float g_A32[BB*32*HWSZ];
__device__ __align__(128) float g_gmap[BB*HWSZ];
__device__ __align__(128) float g_smap[BB*HWSZ];
__device__ __align__(128) float g_fusion[BB*64*HWSZ];
__device__ __align__(128) float g_t[BB*64*HWSZ];
__device__ __align__(128) float g_Weff[64*64];
__device__ __align__(128) float g_beff[64];

// ---------------- K0: effective dyn1d weights (sum over K) -----------------
__global__ void build_weff(const float* __restrict__ rk5w, const float* __restrict__ rk5b,
                           const float* __restrict__ rk7w, const float* __restrict__ rk7b,
                           const float* __restrict__ lk5w, const float* __restrict__ lk5b,
                           const float* __restrict__ lk7w, const float* __restrict__ lk7b)
{
    int id = blockIdx.x*blockDim.x + threadIdx.x;
    if (id >= 64*64) return;
    int m = id >> 6, c = id & 63;
    const float* w; const float* bs; int K, o;
    if      (m < 16) { w = rk5w; bs = rk5b; K = 5; o = m;    }
    else if (m < 32) { w = rk7w; bs = rk7b; K = 7; o = m-16; }
    else if (m < 48) { w = lk5w; bs = lk5b; K = 5; o = m-32; }
    else             { w = lk7w; bs = lk7b; K = 7; o = m-48; }
    float acc = 0.f;
    for (int k = 0; k < K; k++) acc += w[(o*K + k)*64 + c];
    g_Weff[m*64 + c] = acc;
    if (c == 0) {
        float bacc = 0.f;
        for (int k = 0; k < K; k++) bacc += bs[o*K + k];
        g_beff[m] = bacc;
    }
}

// ---------------- tiled 3x3 conv (pad=1), f32x2, 2 vert px/thread ----------
// Tile: 32 wide x 4 tall. 256 threads = 64 px-threads (2 vertical px each)
// x 4 oc-groups of NOC. Weights duplicated in smem -> LDS.128 gives packed ops.
// EPI: 0 = bias+relu, 1 = bias+bn+relu
template<int CIN, int COUT, int EPI>
__global__ __launch_bounds__(256)
void conv3x3_k(const float* __restrict__ in, const float* __restrict__ wt,
               const float* __restrict__ bias,
               const float* __restrict__ bng, const float* __restrict__ bnb,
               const float* __restrict__ bnm, const float* __restrict__ bnv,
               float* __restrict__ out)
{
    constexpr int NOC = COUT/4;      // oc per thread (16 or 8)
    constexpr int CH  = 4;           // ci chunk
    __shared__ float s_in[CH][6][34];
    __shared__ __align__(16) float s_w[CH][COUT][20];  // 9 taps duplicated + pad

    const int w0 = blockIdx.x*32, h0 = blockIdx.y*4;
    const int b  = blockIdx.z;
    const int tid = threadIdx.x;
    const int ocg = tid >> 6;            // 0..3
    const int pt  = tid & 63;
    const int px  = pt & 31;
    const int py0 = (pt >> 5) * 2;       // 0 or 2

    ull acc[NOC];
    #pragma unroll
    for (int i = 0; i < NOC; i++) acc[i] = 0ULL;

    for (int c0 = 0; c0 < CIN; c0 += CH) {
        // stage input tile with halo (zero padded)
        for (int i = tid; i < CH*204; i += 256) {
            int ci = i / 204, rem = i % 204;
            int r = rem / 34, cc = rem % 34;
            int gh = h0 - 1 + r, gw = w0 - 1 + cc;
            float v = 0.f;
            if (gh >= 0 && gh < HH && gw >= 0 && gw < WW)
                v = in[((size_t)(b*CIN + c0 + ci))*HWSZ + gh*WW + gw];
            s_in[ci][r][cc] = v;
        }
        // stage weights, duplicated into adjacent lanes
        for (int i = tid; i < CH*COUT*9; i += 256) {
            int ci = i / (COUT*9), rem = i % (COUT*9);
            int oc = rem / 9, k = rem % 9;
            float w = wt[((size_t)oc*CIN + c0 + ci)*9 + k];
            s_w[ci][oc][2*k]   = w;
            s_w[ci][oc][2*k+1] = w;
        }
        __syncthreads();

        #pragma unroll 1
        for (int ci = 0; ci < CH; ci++) {
            float v[4][3];
            #pragma unroll
            for (int dr = 0; dr < 4; dr++)
                #pragma unroll
                for (int dc = 0; dc < 3; dc++)
                    v[dr][dc] = s_in[ci][py0 + dr][px + dc];

            ull p[9];
            #pragma unroll
            for (int dr = 0; dr < 3; dr++)
                #pragma unroll
                for (int dc = 0; dc < 3; dc++)
                    p[dr*3+dc] = pk2(v[dr][dc], v[dr+1][dc]);

            #pragma unroll
            for (int oc = 0; oc < NOC; oc++) {
                const float* wp = &s_w[ci][ocg*NOC + oc][0];
                ulonglong2 a0 = *(const ulonglong2*)(wp);       // w0,w1
                ulonglong2 a1 = *(const ulonglong2*)(wp + 4);   // w2,w3
                ulonglong2 a2 = *(const ulonglong2*)(wp + 8);   // w4,w5
                ulonglong2 a3 = *(const ulonglong2*)(wp + 12);  // w6,w7
                ull        a8 = *(const ull*)(wp + 16);         // w8
                ull t0 = acc[oc];
                t0 = f2fma(a0.x, p[0], t0);
                t0 = f2fma(a0.y, p[1], t0);
                t0 = f2fma(a1.x, p[2], t0);
                t0 = f2fma(a1.y, p[3], t0);
                t0 = f2fma(a2.x, p[4], t0);
                t0 = f2fma(a2.y, p[5], t0);
                t0 = f2fma(a3.x, p[6], t0);
                t0 = f2fma(a3.y, p[7], t0);
                t0 = f2fma(a8,   p[8], t0);
                acc[oc] = t0;
            }
        }
        __syncthreads();
    }

    #pragma unroll
    for (int oc = 0; oc < NOC; oc++) {
        int goc = ocg*NOC + oc;
        float o0, o1;
        upk2(acc[oc], o0, o1);
        float bv = bias[goc];
        o0 += bv; o1 += bv;
        if (EPI == 1) {
            float sc = bng[goc] * rsqrtf(bnv[goc] + 1e-5f);
            float sh = bnb[goc] - bnm[goc]*sc;
            o0 = o0*sc + sh; o1 = o1*sc + sh;
        }
        o0 = fmaxf(o0, 0.f); o1 = fmaxf(o1, 0.f);
        size_t base = ((size_t)(b*COUT + goc))*HWSZ + (size_t)(h0 + py0)*WW + (w0 + px);
        out[base     ] = o0;
        out[base + WW] = o1;
    }
}

// ---------------- K2: edge (grouped sobel) + attention + g,s ---------------
__global__ __launch_bounds__(256)
void edge_attn_k(const float* __restrict__ x,
                 const float* __restrict__ baw2, const float* __restrict__ bab2)
{
    __shared__ float s_in[8][18][18];
    const int h0 = blockIdx.y*16, w0 = blockIdx.x*16;
    const int b  = blockIdx.z;
    const int tid = threadIdx.x;
    const int px = tid & 15, py = tid >> 4;

    float edge = 0.f, sumx = 0.f;
    for (int c0 = 0; c0 < 64; c0 += 8) {
        for (int i = tid; i < 8*324; i += 256) {
            int ci = i / 324, rem = i % 324;
            int r = rem / 18, cc = rem % 18;
            int gh = h0 - 1 + r, gw = w0 - 1 + cc;
            float v = 0.f;
            if (gh >= 0 && gh < HH && gw >= 0 && gw < WW)
                v = x[((size_t)(b*64 + c0 + ci))*HWSZ + gh*WW + gw];
            s_in[ci][r][cc] = v;
        }
        __syncthreads();
        #pragma unroll 1
        for (int ci = 0; ci < 8; ci++) {
            float v00=s_in[ci][py  ][px], v01=s_in[ci][py  ][px+1], v02=s_in[ci][py  ][px+2];
            float v10=s_in[ci][py+1][px], v11=s_in[ci][py+1][px+1], v12=s_in[ci][py+1][px+2];
            float v20=s_in[ci][py+2][px], v21=s_in[ci][py+2][px+1], v22=s_in[ci][py+2][px+2];
            sumx += v11;
            if (c0 + ci < 32) {
                float gx = (v02 - v00) + 2.f*(v12 - v10) + (v22 - v20);
                edge += fabsf(gx);
            } else {
                float gy = (v20 - v00) + 2.f*(v21 - v01) + (v22 - v02);
                edge += fabsf(gy);
            }
        }
        __syncthreads();
    }
    edge *= (1.f/32.f);

    const int pix = (h0 + py)*WW + (w0 + px);
    float att = bab2[0];
    #pragma unroll 1
    for (int j = 0; j < 32; j++)
        att += baw2[j] * g_A32[((size_t)(b*32 + j))*HWSZ + pix];

    float z = att + edge;
    float a = 1.f / (1.f + expf(-z));
    float g = 1.f + a;
    g_gmap[(size_t)b*HWSZ + pix] = g;
    g_smap[(size_t)b*HWSZ + pix] = g * sumx;
}

// ---------------- 1x1 GEMM kernels: 64m x 128px tile, 8m x 4px /thread -----
// s_wd layout: [ci][m] duplicated pairs so 4x LDS.128 fetch 8 packed weights.
// EPI 0: fusion = s*(g*acc + beff)   EPI 1: out = acc + b + residual
template<int EPI>
__global__ __launch_bounds__(256)
void gemm1x1_k(const float* __restrict__ in, const float* __restrict__ wsrc,
               const float* __restrict__ bsrc,
               const float* __restrict__ resid, float* __restrict__ outp)
{
    __shared__ __align__(16) ull s_wd[64*64];   // [ci][m], 32KB
    __shared__ float s_b[64];
    const int tid = threadIdx.x;
    for (int i = tid; i < 4096; i += 256) {
        int ci = i >> 6, m = i & 63;
        float w = wsrc[m*64 + ci];
        s_wd[i] = pk2(w, w);
    }
    if (tid < 64) s_b[tid] = bsrc[tid];
    __syncthreads();

    const int b   = blockIdx.y;
    const int mg  = tid >> 5;                 // 0..7 -> m base = mg*8
    const int pg  = tid & 31;
    const int pix = blockIdx.x*128 + pg*4;

    ull acc[8][2];
    #pragma unroll
    for (int m = 0; m < 8; m++) { acc[m][0] = 0ULL; acc[m][1] = 0ULL; }

    #pragma unroll 2
    for (int ci = 0; ci < 64; ci++) {
        float4 xv = *(const float4*)&in[((size_t)(b*64 + ci))*HWSZ + pix];
        ull xp0 = pk2(xv.x, xv.y);
        ull xp1 = pk2(xv.z, xv.w);
        const ull* wrow = &s_wd[ci*64 + mg*8];
        ulonglong2 w01 = *(const ulonglong2*)(wrow);
        ulonglong2 w23 = *(const ulonglong2*)(wrow + 2);
        ulonglong2 w45 = *(const ulonglong2*)(wrow + 4);
        ulonglong2 w67 = *(const ulonglong2*)(wrow + 6);
        acc[0][0] = f2fma(w01.x, xp0, acc[0][0]); acc[0][1] = f2fma(w01.x, xp1, acc[0][1]);
        acc[1][0] = f2fma(w01.y, xp0, acc[1][0]); acc[1][1] = f2fma(w01.y, xp1, acc[1][1]);
        acc[2][0] = f2fma(w23.x, xp0, acc[2][0]); acc[2][1] = f2fma(w23.x, xp1, acc[2][1]);
        acc[3][0] = f2fma(w23.y, xp0, acc[3][0]); acc[3][1] = f2fma(w23.y, xp1, acc[3][1]);
        acc[4][0] = f2fma(w45.x, xp0, acc[4][0]); acc[4][1] = f2fma(w45.x, xp1, acc[4][1]);
        acc[5][0] = f2fma(w45.y, xp0, acc[5][0]); acc[5][1] = f2fma(w45.y, xp1, acc[5][1]);
        acc[6][0] = f2fma(w67.x, xp0, acc[6][0]); acc[6][1] = f2fma(w67.x, xp1, acc[6][1]);
        acc[7][0] = f2fma(w67.y, xp0, acc[7][0]); acc[7][1] = f2fma(w67.y, xp1, acc[7][1]);
    }

    if (EPI == 0) {
        float4 gv = *(const float4*)&g_gmap[(size_t)b*HWSZ + pix];
        float4 sv = *(const float4*)&g_smap[(size_t)b*HWSZ + pix];
        ull gp0 = pk2(gv.x, gv.y), gp1 = pk2(gv.z, gv.w);
        ull sp0 = pk2(sv.x, sv.y), sp1 = pk2(sv.z, sv.w);
        #pragma unroll
        for (int m = 0; m < 8; m++) {
            int gm = mg*8 + m;
            ull be = pk2(s_b[gm], s_b[gm]);
            ull r0 = f2mul(sp0, f2fma(gp0, acc[m][0], be));
            ull r1 = f2mul(sp1, f2fma(gp1, acc[m][1], be));
            float4 o;
            upk2(r0, o.x, o.y);
            upk2(r1, o.z, o.w);
            *(float4*)&outp[((size_t)(b*64 + gm))*HWSZ + pix] = o;
        }
    } else {
        #pragma unroll
        for (int m = 0; m < 8; m++) {
            int gm = mg*8 + m;
            float a0, a1, a2, a3;
            upk2(acc[m][0], a0, a1);
            upk2(acc[m][1], a2, a3);
            float bv = s_b[gm];
            size_t idx = ((size_t)(b*64 + gm))*HWSZ + pix;
            float4 rv = *(const float4*)&resid[idx];
            float4 o;
            o.x = a0 + bv + rv.x;
            o.y = a1 + bv + rv.y;
            o.z = a2 + bv + rv.z;
            o.w = a3 + bv + rv.w;
            *(float4*)&outp[idx] = o;
        }
    }
}

// ---------------------------------------------------------------------------
extern "C" void kernel_launch(void* const* d_in, const int* in_sizes, int n_in,
                              void* d_out, int out_size)
{
    (void)in_sizes; (void)n_in; (void)out_size;
    const float* x     = (const float*)d_in[0];
    const float* ba_w1 = (const float*)d_in[1];
    const float* ba_b1 = (const float*)d_in[2];
    const float* ba_w2 = (const float*)d_in[3];
    const float* ba_b2 = (const float*)d_in[4];
    // d_in[5..12]: offset branch — dead code in the reference, skipped.
    const float* rk5w  = (const float*)d_in[13];
    const float* rk5b  = (const float*)d_in[14];
    const float* rk7w  = (const float*)d_in[15];
    const float* rk7b  = (const float*)d_in[16];
    const float* lk5w  = (const float*)d_in[17];
    const float* lk5b  = (const float*)d_in[18];
    const float* lk7w  = (const float*)d_in[19];
    const float* lk7b  = (const float*)d_in[20];
    const float* sfw   = (const float*)d_in[21];
    const float* sfb   = (const float*)d_in[22];
    const float* sfg   = (const float*)d_in[23];
    const float* sfbb  = (const float*)d_in[24];
    const float* sfm   = (const float*)d_in[25];
    const float* sfv   = (const float*)d_in[26];
    const float* fcw   = (const float*)d_in[27];
    const float* fcb   = (const float*)d_in[28];
    float* out = (float*)d_out;

    float *pA32, *pFus, *pT, *pWeff, *pBeff;
    cudaGetSymbolAddress((void**)&pA32,  g_A32);
    cudaGetSymbolAddress((void**)&pFus,  g_fusion);
    cudaGetSymbolAddress((void**)&pT,    g_t);
    cudaGetSymbolAddress((void**)&pWeff, g_Weff);
    cudaGetSymbolAddress((void**)&pBeff, g_beff);

    build_weff<<<16, 256>>>(rk5w, rk5b, rk7w, rk7b, lk5w, lk5b, lk7w, lk7b);

    dim3 cgrid(WW/32, HH/4, BB);
    conv3x3_k<64,32,0><<<cgrid, 256>>>(x, ba_w1, ba_b1,
                                       nullptr, nullptr, nullptr, nullptr, pA32);
    dim3 egrid(WW/16, HH/16, BB);
    edge_attn_k<<<egrid, 256>>>(x, ba_w2, ba_b2);

    dim3 ggrid(HWSZ/128, BB);
    gemm1x1_k<0><<<ggrid, 256>>>(x, pWeff, pBeff, nullptr, pFus);
    conv3x3_k<64,64,1><<<cgrid, 256>>>(pFus, sfw, sfb, sfg, sfbb, sfm, sfv, pT);
    gemm1x1_k<1><<<ggrid, 256>>>(pT, fcw, fcb, x, out);
}

// round 4
// speedup vs baseline: 1.5049x; 1.4144x over previous
#include <cuda_runtime.h>
#include <cstddef>

#define BB 4
#define HH 160
#define WW 160
#define HWSZ (HH*WW)

typedef unsigned long long ull;

// ---------------- packed f32x2 helpers -------------------------------------
__device__ __forceinline__ ull pk2(float lo, float hi) {
    ull r; asm("mov.b64 %0,{%1,%2};" : "=l"(r) : "f"(lo), "f"(hi)); return r;
}
__device__ __forceinline__ void upk2(ull v, float& lo, float& hi) {
    asm("mov.b64 {%0,%1},%2;" : "=f"(lo), "=f"(hi) : "l"(v));
}
__device__ __forceinline__ ull f2fma(ull a, ull b, ull c) {
    ull d; asm("fma.rn.f32x2 %0,%1,%2,%3;" : "=l"(d) : "l"(a), "l"(b), "l"(c)); return d;
}
__device__ __forceinline__ ull f2mul(ull a, ull b) {
    ull d; asm("mul.rn.f32x2 %0,%1,%2;" : "=l"(d) : "l"(a), "l"(b)); return d;
}

// ---------------- scratch (device globals; no allocation allowed) ----------
__device__ __align__(128) float g_A32[BB*32*HWSZ];
__device__ __align__(128) float g_gmap[BB*HWSZ];
__device__ __align__(128) float g_smap[BB*HWSZ];
__device__ __align__(128) float g_fusion[BB*64*HWSZ];
__device__ __align__(128) float g_t[BB*64*HWSZ];
__device__ __align__(128) float g_Weff[64*64];
__device__ __align__(128) float g_beff[64];
__device__ __align__(128) float g_w1t[64*9*32];   // [ci][tap][oc]
__device__ __align__(128) float g_w2t[64*9*64];   // [ci][tap][oc], BN-folded
__device__ __align__(128) float g_b2[64];         // BN-folded bias

// ---------------- K0a: effective dyn1d weights (sum over K) ----------------
__global__ void build_weff(const float* __restrict__ rk5w, const float* __restrict__ rk5b,
                           const float* __restrict__ rk7w, const float* __restrict__ rk7b,
                           const float* __restrict__ lk5w, const float* __restrict__ lk5b,
                           const float* __restrict__ lk7w, const float* __restrict__ lk7b)
{
    int id = blockIdx.x*blockDim.x + threadIdx.x;
    if (id >= 64*64) return;
    int m = id >> 6, c = id & 63;
    const float* w; const float* bs; int K, o;
    if      (m < 16) { w = rk5w; bs = rk5b; K = 5; o = m;    }
    else if (m < 32) { w = rk7w; bs = rk7b; K = 7; o = m-16; }
    else if (m < 48) { w = lk5w; bs = lk5b; K = 5; o = m-32; }
    else             { w = lk7w; bs = lk7b; K = 7; o = m-48; }
    float acc = 0.f;
    for (int k = 0; k < K; k++) acc += w[(o*K + k)*64 + c];
    g_Weff[m*64 + c] = acc;
    if (c == 0) {
        float bacc = 0.f;
        for (int k = 0; k < K; k++) bacc += bs[o*K + k];
        g_beff[m] = bacc;
    }
}

// ---------------- K0b: transpose conv weights, fold BN into w2 -------------
__global__ void prep_w(const float* __restrict__ w1, const float* __restrict__ w2,
                       const float* __restrict__ b2, const float* __restrict__ bg,
                       const float* __restrict__ bbta, const float* __restrict__ bm,
                       const float* __restrict__ bv)
{
    int id = blockIdx.x*blockDim.x + threadIdx.x;
    if (id < 64*9*32) {
        int ci = id/(9*32); int rem = id%(9*32); int t = rem/32; int oc = rem%32;
        g_w1t[id] = w1[(oc*64 + ci)*9 + t];
    }
    if (id < 64*9*64) {
        int ci = id/(9*64); int rem = id%(9*64); int t = rem/64; int oc = rem%64;
        float sc = bg[oc] * rsqrtf(bv[oc] + 1e-5f);
        g_w2t[id] = w2[(oc*64 + ci)*9 + t] * sc;
        if (id < 64) {
            float scc = bg[id] * rsqrtf(bv[id] + 1e-5f);
            g_b2[id] = b2[id]*scc + bbta[id] - bm[id]*scc;
        }
    }
}

// ---------------- tiled 3x3 conv (pad=1), oc-pair f32x2 packing ------------
// Tile 32w x 4h, 256 thr = 64 px-threads (2 vert px) x 4 oc-groups.
// Accumulators pair (oc, oc+1); weights in smem [ci][tap][oc] -> LDS.128 = 4
// distinct weights = 2 packed pairs (no duplication). Input tile stored as
// pre-duplicated ull pairs -> 1 LDS.64 per tap value.
template<int COUT>
__global__ __launch_bounds__(256)
void conv3x3_k(const float* __restrict__ in, const float* __restrict__ wt_t,
               const float* __restrict__ bias, float* __restrict__ out)
{
    constexpr int NOC = COUT/4;      // ocs per thread
    constexpr int NPR = NOC/2;       // oc-pairs per thread
    constexpr int CH  = 8;
    __shared__ ull s_ind[CH][6][34];
    __shared__ __align__(16) float s_w[CH][9][COUT];

    const int w0 = blockIdx.x*32, h0 = blockIdx.y*4;
    const int b  = blockIdx.z;
    const int tid = threadIdx.x;
    const int ocg = tid >> 6;            // 0..3
    const int pt  = tid & 63;
    const int px  = pt & 31;
    const int py0 = (pt >> 5) * 2;       // 0 or 2

    ull acc0[NPR], acc1[NPR];
    #pragma unroll
    for (int i = 0; i < NPR; i++) { acc0[i] = 0ULL; acc1[i] = 0ULL; }

    for (int c0 = 0; c0 < 64; c0 += CH) {
        // stage input tile with halo, duplicated pairs
        for (int i = tid; i < CH*204; i += 256) {
            int ci = i / 204, rem = i % 204;
            int r = rem / 34, cc = rem % 34;
            int gh = h0 - 1 + r, gw = w0 - 1 + cc;
            float v = 0.f;
            if (gh >= 0 && gh < HH && gw >= 0 && gw < WW)
                v = in[((size_t)(b*64 + c0 + ci))*HWSZ + gh*WW + gw];
            s_ind[ci][r][cc] = pk2(v, v);
        }
        // stage weights: contiguous float4 copy from pre-transposed tensor
        {
            const float4* src = (const float4*)(wt_t + (size_t)c0*9*COUT);
            float4* dst = (float4*)&s_w[0][0][0];
            #pragma unroll
            for (int i = tid; i < CH*9*COUT/4; i += 256) dst[i] = src[i];
        }
        __syncthreads();

        #pragma unroll 1
        for (int ci = 0; ci < CH; ci++) {
            ull vd[4][3];
            #pragma unroll
            for (int r = 0; r < 4; r++)
                #pragma unroll
                for (int c = 0; c < 3; c++)
                    vd[r][c] = s_ind[ci][py0 + r][px + c];

            #pragma unroll
            for (int t = 0; t < 9; t++) {
                const int dr = t/3, dc = t%3;
                ull w_[NPR];
                const ulonglong2* wp = (const ulonglong2*)&s_w[ci][t][ocg*NOC];
                #pragma unroll
                for (int j = 0; j < NPR/2; j++) {
                    ulonglong2 ww = wp[j];
                    w_[2*j]   = ww.x;
                    w_[2*j+1] = ww.y;
                }
                #pragma unroll
                for (int pr = 0; pr < NPR; pr++) {
                    acc0[pr] = f2fma(w_[pr], vd[dr  ][dc], acc0[pr]);
                    acc1[pr] = f2fma(w_[pr], vd[dr+1][dc], acc1[pr]);
                }
            }
        }
        __syncthreads();
    }

    #pragma unroll
    for (int pr = 0; pr < NPR; pr++) {
        int oc = ocg*NOC + 2*pr;
        float o00, o01, o10, o11;
        upk2(acc0[pr], o00, o01);
        upk2(acc1[pr], o10, o11);
        float b0 = bias[oc], b1 = bias[oc+1];
        o00 = fmaxf(o00 + b0, 0.f); o01 = fmaxf(o01 + b1, 0.f);
        o10 = fmaxf(o10 + b0, 0.f); o11 = fmaxf(o11 + b1, 0.f);
        size_t base = ((size_t)(b*COUT + oc))*HWSZ + (size_t)(h0 + py0)*WW + (w0 + px);
        out[base              ] = o00;
        out[base + WW         ] = o10;
        out[base + HWSZ       ] = o01;
        out[base + HWSZ + WW  ] = o11;
    }
}

// ---------------- K2: edge (grouped sobel) + attention + g,s ---------------
__global__ __launch_bounds__(256)
void edge_attn_k(const float* __restrict__ x,
                 const float* __restrict__ baw2, const float* __restrict__ bab2)
{
    __shared__ float s_in[8][18][18];
    const int h0 = blockIdx.y*16, w0 = blockIdx.x*16;
    const int b  = blockIdx.z;
    const int tid = threadIdx.x;
    const int px = tid & 15, py = tid >> 4;

    float edge = 0.f, sumx = 0.f;
    for (int c0 = 0; c0 < 64; c0 += 8) {
        for (int i = tid; i < 8*324; i += 256) {
            int ci = i / 324, rem = i % 324;
            int r = rem / 18, cc = rem % 18;
            int gh = h0 - 1 + r, gw = w0 - 1 + cc;
            float v = 0.f;
            if (gh >= 0 && gh < HH && gw >= 0 && gw < WW)
                v = x[((size_t)(b*64 + c0 + ci))*HWSZ + gh*WW + gw];
            s_in[ci][r][cc] = v;
        }
        __syncthreads();
        #pragma unroll 1
        for (int ci = 0; ci < 8; ci++) {
            float v00=s_in[ci][py  ][px], v01=s_in[ci][py  ][px+1], v02=s_in[ci][py  ][px+2];
            float v10=s_in[ci][py+1][px], v11=s_in[ci][py+1][px+1], v12=s_in[ci][py+1][px+2];
            float v20=s_in[ci][py+2][px], v21=s_in[ci][py+2][px+1], v22=s_in[ci][py+2][px+2];
            sumx += v11;
            if (c0 + ci < 32) {
                float gx = (v02 - v00) + 2.f*(v12 - v10) + (v22 - v20);
                edge += fabsf(gx);
            } else {
                float gy = (v20 - v00) + 2.f*(v21 - v01) + (v22 - v02);
                edge += fabsf(gy);
            }
        }
        __syncthreads();
    }
    edge *= (1.f/32.f);

    const int pix = (h0 + py)*WW + (w0 + px);
    float att = bab2[0];
    #pragma unroll 1
    for (int j = 0; j < 32; j++)
        att += baw2[j] * g_A32[((size_t)(b*32 + j))*HWSZ + pix];

    float z = att + edge;
    float a = 1.f / (1.f + expf(-z));
    float g = 1.f + a;
    g_gmap[(size_t)b*HWSZ + pix] = g;
    g_smap[(size_t)b*HWSZ + pix] = g * sumx;
}

// ---------------- 1x1 GEMM: 64m x 128px tile, 8m x 4px /thread -------------
// MLP-8 batched global loads per unroll group.
// EPI 0: fusion = s*(g*acc + beff)   EPI 1: out = acc + b + residual
template<int EPI>
__global__ __launch_bounds__(256)
void gemm1x1_k(const float* __restrict__ in, const float* __restrict__ wsrc,
               const float* __restrict__ bsrc,
               const float* __restrict__ resid, float* __restrict__ outp)
{
    __shared__ __align__(16) ull s_wd[64*64];   // [ci][m], duplicated pairs
    __shared__ float s_b[64];
    const int tid = threadIdx.x;
    for (int i = tid; i < 4096; i += 256) {
        int ci = i >> 6, m = i & 63;
        float w = wsrc[m*64 + ci];
        s_wd[i] = pk2(w, w);
    }
    if (tid < 64) s_b[tid] = bsrc[tid];
    __syncthreads();

    const int b   = blockIdx.y;
    const int mg  = tid >> 5;                 // 0..7 -> m base = mg*8
    const int pg  = tid & 31;
    const int pix = blockIdx.x*128 + pg*4;

    ull acc[8][2];
    #pragma unroll
    for (int m = 0; m < 8; m++) { acc[m][0] = 0ULL; acc[m][1] = 0ULL; }

    #pragma unroll 1
    for (int c8 = 0; c8 < 8; c8++) {
        const float* bp = in + ((size_t)(b*64 + c8*8))*HWSZ + pix;
        float4 xv[8];
        #pragma unroll
        for (int j = 0; j < 8; j++)
            xv[j] = *(const float4*)(bp + (size_t)j*HWSZ);
        #pragma unroll
        for (int j = 0; j < 8; j++) {
            ull xp0 = pk2(xv[j].x, xv[j].y);
            ull xp1 = pk2(xv[j].z, xv[j].w);
            const ull* wrow = &s_wd[(c8*8 + j)*64 + mg*8];
            ulonglong2 w01 = *(const ulonglong2*)(wrow);
            ulonglong2 w23 = *(const ulonglong2*)(wrow + 2);
            ulonglong2 w45 = *(const ulonglong2*)(wrow + 4);
            ulonglong2 w67 = *(const ulonglong2*)(wrow + 6);
            acc[0][0] = f2fma(w01.x, xp0, acc[0][0]); acc[0][1] = f2fma(w01.x, xp1, acc[0][1]);
            acc[1][0] = f2fma(w01.y, xp0, acc[1][0]); acc[1][1] = f2fma(w01.y, xp1, acc[1][1]);
            acc[2][0] = f2fma(w23.x, xp0, acc[2][0]); acc[2][1] = f2fma(w23.x, xp1, acc[2][1]);
            acc[3][0] = f2fma(w23.y, xp0, acc[3][0]); acc[3][1] = f2fma(w23.y, xp1, acc[3][1]);
            acc[4][0] = f2fma(w45.x, xp0, acc[4][0]); acc[4][1] = f2fma(w45.x, xp1, acc[4][1]);
            acc[5][0] = f2fma(w45.y, xp0, acc[5][0]); acc[5][1] = f2fma(w45.y, xp1, acc[5][1]);
            acc[6][0] = f2fma(w67.x, xp0, acc[6][0]); acc[6][1] = f2fma(w67.x, xp1, acc[6][1]);
            acc[7][0] = f2fma(w67.y, xp0, acc[7][0]); acc[7][1] = f2fma(w67.y, xp1, acc[7][1]);
        }
    }

    if (EPI == 0) {
        float4 gv = *(const float4*)&g_gmap[(size_t)b*HWSZ + pix];
        float4 sv = *(const float4*)&g_smap[(size_t)b*HWSZ + pix];
        ull gp0 = pk2(gv.x, gv.y), gp1 = pk2(gv.z, gv.w);
        ull sp0 = pk2(sv.x, sv.y), sp1 = pk2(sv.z, sv.w);
        #pragma unroll
        for (int m = 0; m < 8; m++) {
            int gm = mg*8 + m;
            ull be = pk2(s_b[gm], s_b[gm]);
            ull r0 = f2mul(sp0, f2fma(gp0, acc[m][0], be));
            ull r1 = f2mul(sp1, f2fma(gp1, acc[m][1], be));
            float4 o;
            upk2(r0, o.x, o.y);
            upk2(r1, o.z, o.w);
            *(float4*)&outp[((size_t)(b*64 + gm))*HWSZ + pix] = o;
        }
    } else {
        #pragma unroll
        for (int m = 0; m < 8; m++) {
            int gm = mg*8 + m;
            float a0, a1, a2, a3;
            upk2(acc[m][0], a0, a1);
            upk2(acc[m][1], a2, a3);
            float bv = s_b[gm];
            size_t idx = ((size_t)(b*64 + gm))*HWSZ + pix;
            float4 rv = *(const float4*)&resid[idx];
            float4 o;
            o.x = a0 + bv + rv.x;
            o.y = a1 + bv + rv.y;
            o.z = a2 + bv + rv.z;
            o.w = a3 + bv + rv.w;
            *(float4*)&outp[idx] = o;
        }
    }
}

// ---------------------------------------------------------------------------
extern "C" void kernel_launch(void* const* d_in, const int* in_sizes, int n_in,
                              void* d_out, int out_size)
{
    (void)in_sizes; (void)n_in; (void)out_size;
    const float* x     = (const float*)d_in[0];
    const float* ba_w1 = (const float*)d_in[1];
    const float* ba_b1 = (const float*)d_in[2];
    const float* ba_w2 = (const float*)d_in[3];
    const float* ba_b2 = (const float*)d_in[4];
    // d_in[5..12]: offset branch — dead code in the reference, skipped.
    const float* rk5w  = (const float*)d_in[13];
    const float* rk5b  = (const float*)d_in[14];
    const float* rk7w  = (const float*)d_in[15];
    const float* rk7b  = (const float*)d_in[16];
    const float* lk5w  = (const float*)d_in[17];
    const float* lk5b  = (const float*)d_in[18];
    const float* lk7w  = (const float*)d_in[19];
    const float* lk7b  = (const float*)d_in[20];
    const float* sfw   = (const float*)d_in[21];
    const float* sfb   = (const float*)d_in[22];
    const float* sfg   = (const float*)d_in[23];
    const float* sfbb  = (const float*)d_in[24];
    const float* sfm   = (const float*)d_in[25];
    const float* sfv   = (const float*)d_in[26];
    const float* fcw   = (const float*)d_in[27];
    const float* fcb   = (const float*)d_in[28];
    float* out = (float*)d_out;

    float *pA32, *pFus, *pT, *pWeff, *pBeff, *pW1t, *pW2t, *pB2;
    cudaGetSymbolAddress((void**)&pA32,  g_A32);
    cudaGetSymbolAddress((void**)&pFus,  g_fusion);
    cudaGetSymbolAddress((void**)&pT,    g_t);
    cudaGetSymbolAddress((void**)&pWeff, g_Weff);
    cudaGetSymbolAddress((void**)&pBeff, g_beff);
    cudaGetSymbolAddress((void**)&pW1t,  g_w1t);
    cudaGetSymbolAddress((void**)&pW2t,  g_w2t);
    cudaGetSymbolAddress((void**)&pB2,   g_b2);

    build_weff<<<16, 256>>>(rk5w, rk5b, rk7w, rk7b, lk5w, lk5b, lk7w, lk7b);
    prep_w<<<144, 256>>>(ba_w1, sfw, sfb, sfg, sfbb, sfm, sfv);

    dim3 cgrid(WW/32, HH/4, BB);
    conv3x3_k<32><<<cgrid, 256>>>(x, pW1t, ba_b1, pA32);
    dim3 egrid(WW/16, HH/16, BB);
    edge_attn_k<<<egrid, 256>>>(x, ba_w2, ba_b2);

    dim3 ggrid(HWSZ/128, BB);
    gemm1x1_k<0><<<ggrid, 256>>>(x, pWeff, pBeff, nullptr, pFus);
    conv3x3_k<64><<<cgrid, 256>>>(pFus, pW2t, pB2, pT);
    gemm1x1_k<1><<<ggrid, 256>>>(pT, fcw, fcb, x, out);
}

// round 5
// speedup vs baseline: 1.5897x; 1.0564x over previous
#include <cuda_runtime.h>
#include <cstddef>

#define BB 4
#define HH 160
#define WW 160
#define HWSZ (HH*WW)

typedef unsigned long long ull;

// ---------------- packed f32x2 helpers -------------------------------------
__device__ __forceinline__ ull pk2(float lo, float hi) {
    ull r; asm("mov.b64 %0,{%1,%2};" : "=l"(r) : "f"(lo), "f"(hi)); return r;
}
__device__ __forceinline__ void upk2(ull v, float& lo, float& hi) {
    asm("mov.b64 {%0,%1},%2;" : "=f"(lo), "=f"(hi) : "l"(v));
}
__device__ __forceinline__ float lo2(ull v) {
    float a, b; upk2(v, a, b); return a;
}
__device__ __forceinline__ ull f2fma(ull a, ull b, ull c) {
    ull d; asm("fma.rn.f32x2 %0,%1,%2,%3;" : "=l"(d) : "l"(a), "l"(b), "l"(c)); return d;
}
__device__ __forceinline__ ull f2mul(ull a, ull b) {
    ull d; asm("mul.rn.f32x2 %0,%1,%2;" : "=l"(d) : "l"(a), "l"(b)); return d;
}

// ---------------- scratch (device globals; no allocation allowed) ----------
__device__ __align__(128) float g_gmap[BB*HWSZ];
__device__ __align__(128) float g_smap[BB*HWSZ];
__device__ __align__(128) float g_fusion[BB*64*HWSZ];
__device__ __align__(128) float g_t[BB*64*HWSZ];
__device__ __align__(128) float g_Weff[64*64];
__device__ __align__(128) float g_beff[64];
__device__ __align__(128) float g_w1t[64*9*32];   // [ci][tap][oc]
__device__ __align__(128) float g_w2t[64*9*64];   // [ci][tap][oc], BN-folded
__device__ __align__(128) float g_b2[64];         // BN-folded bias

// ---------------- K0a: effective dyn1d weights (sum over K) ----------------
__global__ void build_weff(const float* __restrict__ rk5w, const float* __restrict__ rk5b,
                           const float* __restrict__ rk7w, const float* __restrict__ rk7b,
                           const float* __restrict__ lk5w, const float* __restrict__ lk5b,
                           const float* __restrict__ lk7w, const float* __restrict__ lk7b)
{
    int id = blockIdx.x*blockDim.x + threadIdx.x;
    if (id >= 64*64) return;
    int m = id >> 6, c = id & 63;
    const float* w; const float* bs; int K, o;
    if      (m < 16) { w = rk5w; bs = rk5b; K = 5; o = m;    }
    else if (m < 32) { w = rk7w; bs = rk7b; K = 7; o = m-16; }
    else if (m < 48) { w = lk5w; bs = lk5b; K = 5; o = m-32; }
    else             { w = lk7w; bs = lk7b; K = 7; o = m-48; }
    float acc = 0.f;
    for (int k = 0; k < K; k++) acc += w[(o*K + k)*64 + c];
    g_Weff[m*64 + c] = acc;
    if (c == 0) {
        float bacc = 0.f;
        for (int k = 0; k < K; k++) bacc += bs[o*K + k];
        g_beff[m] = bacc;
    }
}

// ---------------- K0b: transpose conv weights, fold BN into w2 -------------
__global__ void prep_w(const float* __restrict__ w1, const float* __restrict__ w2,
                       const float* __restrict__ b2, const float* __restrict__ bg,
                       const float* __restrict__ bbta, const float* __restrict__ bm,
                       const float* __restrict__ bv)
{
    int id = blockIdx.x*blockDim.x + threadIdx.x;
    if (id < 64*9*32) {
        int ci = id/(9*32); int rem = id%(9*32); int t = rem/32; int oc = rem%32;
        g_w1t[id] = w1[(oc*64 + ci)*9 + t];
    }
    if (id < 64*9*64) {
        int ci = id/(9*64); int rem = id%(9*64); int t = rem/64; int oc = rem%64;
        float sc = bg[oc] * rsqrtf(bv[oc] + 1e-5f);
        g_w2t[id] = w2[(oc*64 + ci)*9 + t] * sc;
        if (id < 64) {
            float scc = bg[id] * rsqrtf(bv[id] + 1e-5f);
            g_b2[id] = b2[id]*scc + bbta[id] - bm[id]*scc;
        }
    }
}

// ---------------- K1: fused conv3x3<32> + sobel edge + attention -----------
// Produces g_gmap (1+sigmoid(att+edge)) and g_smap (g * sum_c x) directly.
// Tile 32w x 4h, 256 thr = 64 px-threads (2 vert px) x 4 oc-groups of 8.
// Edge/sumx distributed over oc-groups by ci mod 4; attention dot reduced
// across oc-groups in smem. No A32 tensor is ever materialized.
__global__ __launch_bounds__(256)
void conv32_edge_k(const float* __restrict__ in, const float* __restrict__ wt_t,
                   const float* __restrict__ bias,
                   const float* __restrict__ baw2, const float* __restrict__ bab2)
{
    constexpr int NOC = 8, NPR = 4, CH = 8;
    __shared__ ull s_ind[CH][6][34];
    __shared__ __align__(16) float s_w[CH][9][32];
    __shared__ float s_att[4][64][2];
    __shared__ float s_edge[4][64][2];
    __shared__ float s_sum[4][64][2];
    __shared__ float s_b1[32], s_w2[32];

    const int w0 = blockIdx.x*32, h0 = blockIdx.y*4;
    const int b  = blockIdx.z;
    const int tid = threadIdx.x;
    const int ocg = tid >> 6;            // 0..3
    const int pt  = tid & 63;
    const int px  = pt & 31;
    const int py0 = (pt >> 5) * 2;       // 0 or 2

    if (tid < 32) { s_b1[tid] = bias[tid]; s_w2[tid] = baw2[tid]; }

    ull acc0[NPR], acc1[NPR];
    #pragma unroll
    for (int i = 0; i < NPR; i++) { acc0[i] = 0ULL; acc1[i] = 0ULL; }
    float edge0 = 0.f, edge1 = 0.f, sum0 = 0.f, sum1 = 0.f;

    for (int c0 = 0; c0 < 64; c0 += CH) {
        for (int i = tid; i < CH*204; i += 256) {
            int ci = i / 204, rem = i % 204;
            int r = rem / 34, cc = rem % 34;
            int gh = h0 - 1 + r, gw = w0 - 1 + cc;
            float v = 0.f;
            if (gh >= 0 && gh < HH && gw >= 0 && gw < WW)
                v = in[((size_t)(b*64 + c0 + ci))*HWSZ + gh*WW + gw];
            s_ind[ci][r][cc] = pk2(v, v);
        }
        {
            const float4* src = (const float4*)(wt_t + (size_t)c0*9*32);
            float4* dst = (float4*)&s_w[0][0][0];
            for (int i = tid; i < CH*9*32/4; i += 256) dst[i] = src[i];
        }
        __syncthreads();

        #pragma unroll 1
        for (int ci = 0; ci < CH; ci++) {
            ull vd[4][3];
            #pragma unroll
            for (int r = 0; r < 4; r++)
                #pragma unroll
                for (int c = 0; c < 3; c++)
                    vd[r][c] = s_ind[ci][py0 + r][px + c];

            // edge + channel-sum for ci's assigned to this oc-group
            if ((ci & 3) == ocg) {
                float v00=lo2(vd[0][0]), v01=lo2(vd[0][1]), v02=lo2(vd[0][2]);
                float v10=lo2(vd[1][0]), v11=lo2(vd[1][1]), v12=lo2(vd[1][2]);
                float v20=lo2(vd[2][0]), v21=lo2(vd[2][1]), v22=lo2(vd[2][2]);
                float v30=lo2(vd[3][0]), v31=lo2(vd[3][1]), v32=lo2(vd[3][2]);
                sum0 += v11; sum1 += v21;
                if (c0 < 32) {  // sobel-x channels
                    float gx0 = (v02 - v00) + 2.f*(v12 - v10) + (v22 - v20);
                    float gx1 = (v12 - v10) + 2.f*(v22 - v20) + (v32 - v30);
                    edge0 += fabsf(gx0); edge1 += fabsf(gx1);
                } else {        // sobel-y channels
                    float gy0 = (v20 - v00) + 2.f*(v21 - v01) + (v22 - v02);
                    float gy1 = (v30 - v10) + 2.f*(v31 - v11) + (v32 - v12);
                    edge0 += fabsf(gy0); edge1 += fabsf(gy1);
                }
            }

            #pragma unroll
            for (int t = 0; t < 9; t++) {
                const int dr = t/3, dc = t%3;
                const ulonglong2* wp = (const ulonglong2*)&s_w[ci][t][ocg*NOC];
                ulonglong2 wa = wp[0], wb = wp[1];
                acc0[0] = f2fma(wa.x, vd[dr  ][dc], acc0[0]);
                acc1[0] = f2fma(wa.x, vd[dr+1][dc], acc1[0]);
                acc0[1] = f2fma(wa.y, vd[dr  ][dc], acc0[1]);
                acc1[1] = f2fma(wa.y, vd[dr+1][dc], acc1[1]);
                acc0[2] = f2fma(wb.x, vd[dr  ][dc], acc0[2]);
                acc1[2] = f2fma(wb.x, vd[dr+1][dc], acc1[2]);
                acc0[3] = f2fma(wb.y, vd[dr  ][dc], acc0[3]);
                acc1[3] = f2fma(wb.y, vd[dr+1][dc], acc1[3]);
            }
        }
        __syncthreads();
    }

    // attention partial: sum over this thread's 8 ocs of w2[oc]*relu(acc+b1)
    float attp0 = 0.f, attp1 = 0.f;
    #pragma unroll
    for (int pr = 0; pr < NPR; pr++) {
        int oc = ocg*NOC + 2*pr;
        float b0v = s_b1[oc], b1v = s_b1[oc+1];
        float w0v = s_w2[oc], w1v = s_w2[oc+1];
        float a0, a1, c0f, c1f;
        upk2(acc0[pr], a0, a1);      // (oc, oc+1) at pixel0
        upk2(acc1[pr], c0f, c1f);    // (oc, oc+1) at pixel1
        attp0 += w0v*fmaxf(a0 + b0v, 0.f) + w1v*fmaxf(a1 + b1v, 0.f);
        attp1 += w0v*fmaxf(c0f + b0v, 0.f) + w1v*fmaxf(c1f + b1v, 0.f);
    }
    s_att [ocg][pt][0] = attp0;  s_att [ocg][pt][1] = attp1;
    s_edge[ocg][pt][0] = edge0;  s_edge[ocg][pt][1] = edge1;
    s_sum [ocg][pt][0] = sum0;   s_sum [ocg][pt][1] = sum1;
    __syncthreads();

    if (ocg == 0) {
        float bb = bab2[0];
        #pragma unroll
        for (int r = 0; r < 2; r++) {
            float att = bb, ed = 0.f, sx = 0.f;
            #pragma unroll
            for (int g = 0; g < 4; g++) {
                att += s_att[g][pt][r];
                ed  += s_edge[g][pt][r];
                sx  += s_sum[g][pt][r];
            }
            float z = att + ed*(1.f/32.f);
            float a = 1.f / (1.f + expf(-z));
            float gv = 1.f + a;
            size_t pix = (size_t)b*HWSZ + (size_t)(h0 + py0 + r)*WW + (w0 + px);
            g_gmap[pix] = gv;
            g_smap[pix] = gv * sx;
        }
    }
}

// ---------------- conv3x3<64> (sf conv, BN folded) --------------------------
__global__ __launch_bounds__(256)
void conv64_k(const float* __restrict__ in, const float* __restrict__ wt_t,
              const float* __restrict__ bias, float* __restrict__ out)
{
    constexpr int COUT = 64, NOC = 16, NPR = 8, CH = 8;
    __shared__ ull s_ind[CH][6][34];
    __shared__ __align__(16) float s_w[CH][9][COUT];

    const int w0 = blockIdx.x*32, h0 = blockIdx.y*4;
    const int b  = blockIdx.z;
    const int tid = threadIdx.x;
    const int ocg = tid >> 6;
    const int pt  = tid & 63;
    const int px  = pt & 31;
    const int py0 = (pt >> 5) * 2;

    ull acc0[NPR], acc1[NPR];
    #pragma unroll
    for (int i = 0; i < NPR; i++) { acc0[i] = 0ULL; acc1[i] = 0ULL; }

    for (int c0 = 0; c0 < 64; c0 += CH) {
        for (int i = tid; i < CH*204; i += 256) {
            int ci = i / 204, rem = i % 204;
            int r = rem / 34, cc = rem % 34;
            int gh = h0 - 1 + r, gw = w0 - 1 + cc;
            float v = 0.f;
            if (gh >= 0 && gh < HH && gw >= 0 && gw < WW)
                v = in[((size_t)(b*64 + c0 + ci))*HWSZ + gh*WW + gw];
            s_ind[ci][r][cc] = pk2(v, v);
        }
        {
            const float4* src = (const float4*)(wt_t + (size_t)c0*9*COUT);
            float4* dst = (float4*)&s_w[0][0][0];
            for (int i = tid; i < CH*9*COUT/4; i += 256) dst[i] = src[i];
        }
        __syncthreads();

        #pragma unroll 1
        for (int ci = 0; ci < CH; ci++) {
            ull vd[4][3];
            #pragma unroll
            for (int r = 0; r < 4; r++)
                #pragma unroll
                for (int c = 0; c < 3; c++)
                    vd[r][c] = s_ind[ci][py0 + r][px + c];

            #pragma unroll
            for (int t = 0; t < 9; t++) {
                const int dr = t/3, dc = t%3;
                ull w_[NPR];
                const ulonglong2* wp = (const ulonglong2*)&s_w[ci][t][ocg*NOC];
                #pragma unroll
                for (int j = 0; j < NPR/2; j++) {
                    ulonglong2 ww = wp[j];
                    w_[2*j]   = ww.x;
                    w_[2*j+1] = ww.y;
                }
                #pragma unroll
                for (int pr = 0; pr < NPR; pr++) {
                    acc0[pr] = f2fma(w_[pr], vd[dr  ][dc], acc0[pr]);
                    acc1[pr] = f2fma(w_[pr], vd[dr+1][dc], acc1[pr]);
                }
            }
        }
        __syncthreads();
    }

    #pragma unroll
    for (int pr = 0; pr < NPR; pr++) {
        int oc = ocg*NOC + 2*pr;
        float o00, o01, o10, o11;
        upk2(acc0[pr], o00, o01);
        upk2(acc1[pr], o10, o11);
        float b0 = bias[oc], b1 = bias[oc+1];
        o00 = fmaxf(o00 + b0, 0.f); o01 = fmaxf(o01 + b1, 0.f);
        o10 = fmaxf(o10 + b0, 0.f); o11 = fmaxf(o11 + b1, 0.f);
        size_t base = ((size_t)(b*64 + oc))*HWSZ + (size_t)(h0 + py0)*WW + (w0 + px);
        out[base              ] = o00;
        out[base + WW         ] = o10;
        out[base + HWSZ       ] = o01;
        out[base + HWSZ + WW  ] = o11;
    }
}

// ---------------- 1x1 GEMM: 64m x 128px tile, 8m x 4px /thread -------------
template<int EPI>
__global__ __launch_bounds__(256)
void gemm1x1_k(const float* __restrict__ in, const float* __restrict__ wsrc,
               const float* __restrict__ bsrc,
               const float* __restrict__ resid, float* __restrict__ outp)
{
    __shared__ __align__(16) ull s_wd[64*64];
    __shared__ float s_b[64];
    const int tid = threadIdx.x;
    for (int i = tid; i < 4096; i += 256) {
        int ci = i >> 6, m = i & 63;
        float w = wsrc[m*64 + ci];
        s_wd[i] = pk2(w, w);
    }
    if (tid < 64) s_b[tid] = bsrc[tid];
    __syncthreads();

    const int b   = blockIdx.y;
    const int mg  = tid >> 5;
    const int pg  = tid & 31;
    const int pix = blockIdx.x*128 + pg*4;

    ull acc[8][2];
    #pragma unroll
    for (int m = 0; m < 8; m++) { acc[m][0] = 0ULL; acc[m][1] = 0ULL; }

    #pragma unroll 1
    for (int c8 = 0; c8 < 8; c8++) {
        const float* bp = in + ((size_t)(b*64 + c8*8))*HWSZ + pix;
        float4 xv[8];
        #pragma unroll
        for (int j = 0; j < 8; j++)
            xv[j] = *(const float4*)(bp + (size_t)j*HWSZ);
        #pragma unroll
        for (int j = 0; j < 8; j++) {
            ull xp0 = pk2(xv[j].x, xv[j].y);
            ull xp1 = pk2(xv[j].z, xv[j].w);
            const ull* wrow = &s_wd[(c8*8 + j)*64 + mg*8];
            ulonglong2 w01 = *(const ulonglong2*)(wrow);
            ulonglong2 w23 = *(const ulonglong2*)(wrow + 2);
            ulonglong2 w45 = *(const ulonglong2*)(wrow + 4);
            ulonglong2 w67 = *(const ulonglong2*)(wrow + 6);
            acc[0][0] = f2fma(w01.x, xp0, acc[0][0]); acc[0][1] = f2fma(w01.x, xp1, acc[0][1]);
            acc[1][0] = f2fma(w01.y, xp0, acc[1][0]); acc[1][1] = f2fma(w01.y, xp1, acc[1][1]);
            acc[2][0] = f2fma(w23.x, xp0, acc[2][0]); acc[2][1] = f2fma(w23.x, xp1, acc[2][1]);
            acc[3][0] = f2fma(w23.y, xp0, acc[3][0]); acc[3][1] = f2fma(w23.y, xp1, acc[3][1]);
            acc[4][0] = f2fma(w45.x, xp0, acc[4][0]); acc[4][1] = f2fma(w45.x, xp1, acc[4][1]);
            acc[5][0] = f2fma(w45.y, xp0, acc[5][0]); acc[5][1] = f2fma(w45.y, xp1, acc[5][1]);
            acc[6][0] = f2fma(w67.x, xp0, acc[6][0]); acc[6][1] = f2fma(w67.x, xp1, acc[6][1]);
            acc[7][0] = f2fma(w67.y, xp0, acc[7][0]); acc[7][1] = f2fma(w67.y, xp1, acc[7][1]);
        }
    }

    if (EPI == 0) {
        float4 gv = *(const float4*)&g_gmap[(size_t)b*HWSZ + pix];
        float4 sv = *(const float4*)&g_smap[(size_t)b*HWSZ + pix];
        ull gp0 = pk2(gv.x, gv.y), gp1 = pk2(gv.z, gv.w);
        ull sp0 = pk2(sv.x, sv.y), sp1 = pk2(sv.z, sv.w);
        #pragma unroll
        for (int m = 0; m < 8; m++) {
            int gm = mg*8 + m;
            ull be = pk2(s_b[gm], s_b[gm]);
            ull r0 = f2mul(sp0, f2fma(gp0, acc[m][0], be));
            ull r1 = f2mul(sp1, f2fma(gp1, acc[m][1], be));
            float4 o;
            upk2(r0, o.x, o.y);
            upk2(r1, o.z, o.w);
            *(float4*)&outp[((size_t)(b*64 + gm))*HWSZ + pix] = o;
        }
    } else {
        #pragma unroll
        for (int m = 0; m < 8; m++) {
            int gm = mg*8 + m;
            float a0, a1, a2, a3;
            upk2(acc[m][0], a0, a1);
            upk2(acc[m][1], a2, a3);
            float bv = s_b[gm];
            size_t idx = ((size_t)(b*64 + gm))*HWSZ + pix;
            float4 rv = *(const float4*)&resid[idx];
            float4 o;
            o.x = a0 + bv + rv.x;
            o.y = a1 + bv + rv.y;
            o.z = a2 + bv + rv.z;
            o.w = a3 + bv + rv.w;
            *(float4*)&outp[idx] = o;
        }
    }
}

// ---------------------------------------------------------------------------
extern "C" void kernel_launch(void* const* d_in, const int* in_sizes, int n_in,
                              void* d_out, int out_size)
{
    (void)in_sizes; (void)n_in; (void)out_size;
    const float* x     = (const float*)d_in[0];
    const float* ba_w1 = (const float*)d_in[1];
    const float* ba_b1 = (const float*)d_in[2];
    const float* ba_w2 = (const float*)d_in[3];
    const float* ba_b2 = (const float*)d_in[4];
    // d_in[5..12]: offset branch — dead code in the reference, skipped.
    const float* rk5w  = (const float*)d_in[13];
    const float* rk5b  = (const float*)d_in[14];
    const float* rk7w  = (const float*)d_in[15];
    const float* rk7b  = (const float*)d_in[16];
    const float* lk5w  = (const float*)d_in[17];
    const float* lk5b  = (const float*)d_in[18];
    const float* lk7w  = (const float*)d_in[19];
    const float* lk7b  = (const float*)d_in[20];
    const float* sfw   = (const float*)d_in[21];
    const float* sfb   = (const float*)d_in[22];
    const float* sfg   = (const float*)d_in[23];
    const float* sfbb  = (const float*)d_in[24];
    const float* sfm   = (const float*)d_in[25];
    const float* sfv   = (const float*)d_in[26];
    const float* fcw   = (const float*)d_in[27];
    const float* fcb   = (const float*)d_in[28];
    float* out = (float*)d_out;

    float *pFus, *pT, *pWeff, *pBeff, *pW1t, *pW2t, *pB2;
    cudaGetSymbolAddress((void**)&pFus,  g_fusion);
    cudaGetSymbolAddress((void**)&pT,    g_t);
    cudaGetSymbolAddress((void**)&pWeff, g_Weff);
    cudaGetSymbolAddress((void**)&pBeff, g_beff);
    cudaGetSymbolAddress((void**)&pW1t,  g_w1t);
    cudaGetSymbolAddress((void**)&pW2t,  g_w2t);
    cudaGetSymbolAddress((void**)&pB2,   g_b2);

    build_weff<<<16, 256>>>(rk5w, rk5b, rk7w, rk7b, lk5w, lk5b, lk7w, lk7b);
    prep_w<<<144, 256>>>(ba_w1, sfw, sfb, sfg, sfbb, sfm, sfv);

    dim3 cgrid(WW/32, HH/4, BB);
    conv32_edge_k<<<cgrid, 256>>>(x, pW1t, ba_b1, ba_w2, ba_b2);

    dim3 ggrid(HWSZ/128, BB);
    gemm1x1_k<0><<<ggrid, 256>>>(x, pWeff, pBeff, nullptr, pFus);
    conv64_k<<<cgrid, 256>>>(pFus, pW2t, pB2, pT);
    gemm1x1_k<1><<<ggrid, 256>>>(pT, fcw, fcb, x, out);
}

// round 6
// speedup vs baseline: 1.7178x; 1.0806x over previous
#include <cuda_runtime.h>
#include <cstddef>

#define BB 4
#define HH 160
#define WW 160
#define HWSZ (HH*WW)

typedef unsigned long long ull;

// ---------------- packed f32x2 helpers -------------------------------------
__device__ __forceinline__ ull pk2(float lo, float hi) {
    ull r; asm("mov.b64 %0,{%1,%2};" : "=l"(r) : "f"(lo), "f"(hi)); return r;
}
__device__ __forceinline__ void upk2(ull v, float& lo, float& hi) {
    asm("mov.b64 {%0,%1},%2;" : "=f"(lo), "=f"(hi) : "l"(v));
}
__device__ __forceinline__ float lo2(ull v) {
    float a, b; upk2(v, a, b); return a;
}
__device__ __forceinline__ ull f2fma(ull a, ull b, ull c) {
    ull d; asm("fma.rn.f32x2 %0,%1,%2,%3;" : "=l"(d) : "l"(a), "l"(b), "l"(c)); return d;
}
__device__ __forceinline__ ull f2mul(ull a, ull b) {
    ull d; asm("mul.rn.f32x2 %0,%1,%2;" : "=l"(d) : "l"(a), "l"(b)); return d;
}

// ---------------- scratch (device globals; no allocation allowed) ----------
__device__ __align__(128) float g_gmap[BB*HWSZ];
__device__ __align__(128) float g_smap[BB*HWSZ];
__device__ __align__(128) float g_fusion[BB*64*HWSZ];
__device__ __align__(128) float g_t[BB*64*HWSZ];
__device__ __align__(128) float g_Weff[64*64];
__device__ __align__(128) float g_beff[64];
__device__ __align__(128) float g_w1t[64*9*32];   // [ci][tap][oc]
__device__ __align__(128) float g_w2t[64*9*64];   // [ci][tap][oc], BN-folded
__device__ __align__(128) float g_b2[64];         // BN-folded bias

// ---------------- K0a: effective dyn1d weights (sum over K) ----------------
__global__ void build_weff(const float* __restrict__ rk5w, const float* __restrict__ rk5b,
                           const float* __restrict__ rk7w, const float* __restrict__ rk7b,
                           const float* __restrict__ lk5w, const float* __restrict__ lk5b,
                           const float* __restrict__ lk7w, const float* __restrict__ lk7b)
{
    int id = blockIdx.x*blockDim.x + threadIdx.x;
    if (id >= 64*64) return;
    int m = id >> 6, c = id & 63;
    const float* w; const float* bs; int K, o;
    if      (m < 16) { w = rk5w; bs = rk5b; K = 5; o = m;    }
    else if (m < 32) { w = rk7w; bs = rk7b; K = 7; o = m-16; }
    else if (m < 48) { w = lk5w; bs = lk5b; K = 5; o = m-32; }
    else             { w = lk7w; bs = lk7b; K = 7; o = m-48; }
    float acc = 0.f;
    for (int k = 0; k < K; k++) acc += w[(o*K + k)*64 + c];
    g_Weff[m*64 + c] = acc;
    if (c == 0) {
        float bacc = 0.f;
        for (int k = 0; k < K; k++) bacc += bs[o*K + k];
        g_beff[m] = bacc;
    }
}

// ---------------- K0b: transpose conv weights, fold BN into w2 -------------
__global__ void prep_w(const float* __restrict__ w1, const float* __restrict__ w2,
                       const float* __restrict__ b2, const float* __restrict__ bg,
                       const float* __restrict__ bbta, const float* __restrict__ bm,
                       const float* __restrict__ bv)
{
    int id = blockIdx.x*blockDim.x + threadIdx.x;
    if (id < 64*9*32) {
        int ci = id/(9*32); int rem = id%(9*32); int t = rem/32; int oc = rem%32;
        g_w1t[id] = w1[(oc*64 + ci)*9 + t];
    }
    if (id < 64*9*64) {
        int ci = id/(9*64); int rem = id%(9*64); int t = rem/64; int oc = rem%64;
        float sc = bg[oc] * rsqrtf(bv[oc] + 1e-5f);
        g_w2t[id] = w2[(oc*64 + ci)*9 + t] * sc;
        if (id < 64) {
            float scc = bg[id] * rsqrtf(bv[id] + 1e-5f);
            g_b2[id] = b2[id]*scc + bbta[id] - bm[id]*scc;
        }
    }
}

// ---------------- K1: fused conv3x3<32> + sobel edge + attention -----------
// Tile 32w x 8h. 256 thr = 64 px-threads (4 vert px) x 4 oc-groups of 8.
__global__ __launch_bounds__(256)
void conv32_edge_k(const float* __restrict__ in, const float* __restrict__ wt_t,
                   const float* __restrict__ bias,
                   const float* __restrict__ baw2, const float* __restrict__ bab2)
{
    constexpr int CH = 8;
    __shared__ ull s_ind[CH][10][34];
    __shared__ __align__(16) float s_w[CH][9][32];
    __shared__ float s_att[4][64][4];
    __shared__ float s_edge[4][64][4];
    __shared__ float s_sum[4][64][4];
    __shared__ float s_b1[32], s_w2[32];

    const int w0 = blockIdx.x*32, h0 = blockIdx.y*8;
    const int b  = blockIdx.z;
    const int tid = threadIdx.x;
    const int ocg = tid >> 6;            // 0..3
    const int pt  = tid & 63;
    const int px  = pt & 31;
    const int py0 = (pt >> 5) * 4;       // 0 or 4

    if (tid < 32) { s_b1[tid] = bias[tid]; s_w2[tid] = baw2[tid]; }

    ull acc[4][4];                       // [m-pair][px]
    #pragma unroll
    for (int i = 0; i < 4; i++)
        #pragma unroll
        for (int p = 0; p < 4; p++) acc[i][p] = 0ULL;
    float edge[4] = {0.f,0.f,0.f,0.f};
    float sumx[4] = {0.f,0.f,0.f,0.f};

    for (int c0 = 0; c0 < 64; c0 += CH) {
        for (int i = tid; i < CH*340; i += 256) {
            int ci = i / 340, rem = i % 340;
            int r = rem / 34, cc = rem % 34;
            int gh = h0 - 1 + r, gw = w0 - 1 + cc;
            float v = 0.f;
            if (gh >= 0 && gh < HH && gw >= 0 && gw < WW)
                v = in[((size_t)(b*64 + c0 + ci))*HWSZ + gh*WW + gw];
            s_ind[ci][r][cc] = pk2(v, v);
        }
        {
            const float4* src = (const float4*)(wt_t + (size_t)c0*9*32);
            float4* dst = (float4*)&s_w[0][0][0];
            for (int i = tid; i < CH*9*32/4; i += 256) dst[i] = src[i];
        }
        __syncthreads();

        #pragma unroll 1
        for (int ci = 0; ci < CH; ci++) {
            ull vd[6][3];
            #pragma unroll
            for (int r = 0; r < 6; r++)
                #pragma unroll
                for (int c = 0; c < 3; c++)
                    vd[r][c] = s_ind[ci][py0 + r][px + c];

            if ((ci & 3) == ocg) {
                #pragma unroll
                for (int j = 0; j < 4; j++) {
                    float a00=lo2(vd[j  ][0]), a01=lo2(vd[j  ][1]), a02=lo2(vd[j  ][2]);
                    float a10=lo2(vd[j+1][0]), a11=lo2(vd[j+1][1]), a12=lo2(vd[j+1][2]);
                    float a20=lo2(vd[j+2][0]), a21=lo2(vd[j+2][1]), a22=lo2(vd[j+2][2]);
                    sumx[j] += a11;
                    if (c0 < 32) {
                        float gx = (a02 - a00) + 2.f*(a12 - a10) + (a22 - a20);
                        edge[j] += fabsf(gx);
                    } else {
                        float gy = (a20 - a00) + 2.f*(a21 - a01) + (a22 - a02);
                        edge[j] += fabsf(gy);
                    }
                }
            }

            #pragma unroll
            for (int t = 0; t < 9; t++) {
                const int dr = t/3, dc = t%3;
                const ulonglong2* wp = (const ulonglong2*)&s_w[ci][t][ocg*8];
                ulonglong2 wa = wp[0], wb = wp[1];   // 4 m-pairs
                #pragma unroll
                for (int p = 0; p < 4; p++) {
                    ull v = vd[dr + p][dc];
                    acc[0][p] = f2fma(wa.x, v, acc[0][p]);
                    acc[1][p] = f2fma(wa.y, v, acc[1][p]);
                    acc[2][p] = f2fma(wb.x, v, acc[2][p]);
                    acc[3][p] = f2fma(wb.y, v, acc[3][p]);
                }
            }
        }
        __syncthreads();
    }

    // attention partials per pixel
    float attp[4] = {0.f,0.f,0.f,0.f};
    #pragma unroll
    for (int mp = 0; mp < 4; mp++) {
        int oc = ocg*8 + 2*mp;
        float b0v = s_b1[oc], b1v = s_b1[oc+1];
        float w0v = s_w2[oc], w1v = s_w2[oc+1];
        #pragma unroll
        for (int p = 0; p < 4; p++) {
            float alo, ahi;
            upk2(acc[mp][p], alo, ahi);
            attp[p] += w0v*fmaxf(alo + b0v, 0.f) + w1v*fmaxf(ahi + b1v, 0.f);
        }
    }
    #pragma unroll
    for (int p = 0; p < 4; p++) {
        s_att [ocg][pt][p] = attp[p];
        s_edge[ocg][pt][p] = edge[p];
        s_sum [ocg][pt][p] = sumx[p];
    }
    __syncthreads();

    if (ocg == 0) {
        float bb = bab2[0];
        #pragma unroll
        for (int p = 0; p < 4; p++) {
            float att = bb, ed = 0.f, sx = 0.f;
            #pragma unroll
            for (int g = 0; g < 4; g++) {
                att += s_att[g][pt][p];
                ed  += s_edge[g][pt][p];
                sx  += s_sum[g][pt][p];
            }
            float z = att + ed*(1.f/32.f);
            float a = 1.f / (1.f + expf(-z));
            float gv = 1.f + a;
            size_t pix = (size_t)b*HWSZ + (size_t)(h0 + py0 + p)*WW + (w0 + px);
            g_gmap[pix] = gv;
            g_smap[pix] = gv * sx;
        }
    }
}

// ---------------- conv3x3<64> (sf conv, BN folded), 4 vert px/thread -------
// Tile 32w x 4h. 256 thr = 32 px-threads x 8 oc-groups of 8.
__global__ __launch_bounds__(256)
void conv64_k(const float* __restrict__ in, const float* __restrict__ wt_t,
              const float* __restrict__ bias, float* __restrict__ out)
{
    constexpr int CH = 8;
    __shared__ ull s_ind[CH][6][34];
    __shared__ __align__(16) float s_w[CH][9][64];

    const int w0 = blockIdx.x*32, h0 = blockIdx.y*4;
    const int b  = blockIdx.z;
    const int tid = threadIdx.x;
    const int ocg = tid >> 5;            // 0..7
    const int px  = tid & 31;

    ull acc[4][4];
    #pragma unroll
    for (int i = 0; i < 4; i++)
        #pragma unroll
        for (int p = 0; p < 4; p++) acc[i][p] = 0ULL;

    for (int c0 = 0; c0 < 64; c0 += CH) {
        for (int i = tid; i < CH*204; i += 256) {
            int ci = i / 204, rem = i % 204;
            int r = rem / 34, cc = rem % 34;
            int gh = h0 - 1 + r, gw = w0 - 1 + cc;
            float v = 0.f;
            if (gh >= 0 && gh < HH && gw >= 0 && gw < WW)
                v = in[((size_t)(b*64 + c0 + ci))*HWSZ + gh*WW + gw];
            s_ind[ci][r][cc] = pk2(v, v);
        }
        {
            const float4* src = (const float4*)(wt_t + (size_t)c0*9*64);
            float4* dst = (float4*)&s_w[0][0][0];
            for (int i = tid; i < CH*9*64/4; i += 256) dst[i] = src[i];
        }
        __syncthreads();

        #pragma unroll 1
        for (int ci = 0; ci < CH; ci++) {
            ull vd[6][3];
            #pragma unroll
            for (int r = 0; r < 6; r++)
                #pragma unroll
                for (int c = 0; c < 3; c++)
                    vd[r][c] = s_ind[ci][r][px + c];

            #pragma unroll
            for (int t = 0; t < 9; t++) {
                const int dr = t/3, dc = t%3;
                const ulonglong2* wp = (const ulonglong2*)&s_w[ci][t][ocg*8];
                ulonglong2 wa = wp[0], wb = wp[1];
                #pragma unroll
                for (int p = 0; p < 4; p++) {
                    ull v = vd[dr + p][dc];
                    acc[0][p] = f2fma(wa.x, v, acc[0][p]);
                    acc[1][p] = f2fma(wa.y, v, acc[1][p]);
                    acc[2][p] = f2fma(wb.x, v, acc[2][p]);
                    acc[3][p] = f2fma(wb.y, v, acc[3][p]);
                }
            }
        }
        __syncthreads();
    }

    #pragma unroll
    for (int mp = 0; mp < 4; mp++) {
        int oc = ocg*8 + 2*mp;
        float b0 = bias[oc], b1 = bias[oc+1];
        #pragma unroll
        for (int p = 0; p < 4; p++) {
            float olo, ohi;
            upk2(acc[mp][p], olo, ohi);
            olo = fmaxf(olo + b0, 0.f);
            ohi = fmaxf(ohi + b1, 0.f);
            size_t base = (size_t)(h0 + p)*WW + (w0 + px);
            out[((size_t)(b*64 + oc  ))*HWSZ + base] = olo;
            out[((size_t)(b*64 + oc+1))*HWSZ + base] = ohi;
        }
    }
}

// ---------------- 1x1 GEMM: 64m x 256px block, 16m x 4px /thread -----------
// m-pair packing: raw float weights in smem (LDS.128 = 4 ready m-pairs),
// pixels duplicated via 1 mov each (ALU pipe is idle).
// EPI 0: fusion = s*(g*acc + beff)   EPI 1: out = acc + b + residual
template<int EPI>
__global__ __launch_bounds__(256)
void gemm1x1_k(const float* __restrict__ in, const float* __restrict__ wsrc,
               const float* __restrict__ bsrc,
               const float* __restrict__ resid, float* __restrict__ outp)
{
    __shared__ __align__(16) float s_w[64][64];   // [ci][m], 16KB
    __shared__ float s_b[64];
    const int tid = threadIdx.x;
    for (int i = tid; i < 4096; i += 256) {
        int ci = i >> 6, m = i & 63;
        s_w[ci][m] = wsrc[m*64 + ci];
    }
    if (tid < 64) s_b[tid] = bsrc[tid];
    __syncthreads();

    const int b    = blockIdx.y;
    const int w    = tid >> 5;
    const int lane = tid & 31;
    const int mg2  = w >> 1;                  // 0..3 -> m base = mg2*16
    const int pxg  = w & 1;
    const int mbase = mg2*16;
    const int pix  = blockIdx.x*256 + pxg*128 + lane*4;

    ull acc[8][4];                            // [m-pair][px]
    #pragma unroll
    for (int m = 0; m < 8; m++)
        #pragma unroll
        for (int p = 0; p < 4; p++) acc[m][p] = 0ULL;

    #pragma unroll 1
    for (int c4 = 0; c4 < 16; c4++) {
        const float* bp = in + ((size_t)(b*64 + c4*4))*HWSZ + pix;
        float4 xv[4];
        #pragma unroll
        for (int j = 0; j < 4; j++)
            xv[j] = *(const float4*)(bp + (size_t)j*HWSZ);
        #pragma unroll
        for (int j = 0; j < 4; j++) {
            ull xd0 = pk2(xv[j].x, xv[j].x);
            ull xd1 = pk2(xv[j].y, xv[j].y);
            ull xd2 = pk2(xv[j].z, xv[j].z);
            ull xd3 = pk2(xv[j].w, xv[j].w);
            const ulonglong2* wp = (const ulonglong2*)&s_w[c4*4 + j][mbase];
            ulonglong2 wA = wp[0], wB = wp[1], wC = wp[2], wD = wp[3];
            acc[0][0]=f2fma(wA.x,xd0,acc[0][0]); acc[0][1]=f2fma(wA.x,xd1,acc[0][1]);
            acc[0][2]=f2fma(wA.x,xd2,acc[0][2]); acc[0][3]=f2fma(wA.x,xd3,acc[0][3]);
            acc[1][0]=f2fma(wA.y,xd0,acc[1][0]); acc[1][1]=f2fma(wA.y,xd1,acc[1][1]);
            acc[1][2]=f2fma(wA.y,xd2,acc[1][2]); acc[1][3]=f2fma(wA.y,xd3,acc[1][3]);
            acc[2][0]=f2fma(wB.x,xd0,acc[2][0]); acc[2][1]=f2fma(wB.x,xd1,acc[2][1]);
            acc[2][2]=f2fma(wB.x,xd2,acc[2][2]); acc[2][3]=f2fma(wB.x,xd3,acc[2][3]);
            acc[3][0]=f2fma(wB.y,xd0,acc[3][0]); acc[3][1]=f2fma(wB.y,xd1,acc[3][1]);
            acc[3][2]=f2fma(wB.y,xd2,acc[3][2]); acc[3][3]=f2fma(wB.y,xd3,acc[3][3]);
            acc[4][0]=f2fma(wC.x,xd0,acc[4][0]); acc[4][1]=f2fma(wC.x,xd1,acc[4][1]);
            acc[4][2]=f2fma(wC.x,xd2,acc[4][2]); acc[4][3]=f2fma(wC.x,xd3,acc[4][3]);
            acc[5][0]=f2fma(wC.y,xd0,acc[5][0]); acc[5][1]=f2fma(wC.y,xd1,acc[5][1]);
            acc[5][2]=f2fma(wC.y,xd2,acc[5][2]); acc[5][3]=f2fma(wC.y,xd3,acc[5][3]);
            acc[6][0]=f2fma(wD.x,xd0,acc[6][0]); acc[6][1]=f2fma(wD.x,xd1,acc[6][1]);
            acc[6][2]=f2fma(wD.x,xd2,acc[6][2]); acc[6][3]=f2fma(wD.x,xd3,acc[6][3]);
            acc[7][0]=f2fma(wD.y,xd0,acc[7][0]); acc[7][1]=f2fma(wD.y,xd1,acc[7][1]);
            acc[7][2]=f2fma(wD.y,xd2,acc[7][2]); acc[7][3]=f2fma(wD.y,xd3,acc[7][3]);
        }
    }

    if (EPI == 0) {
        float4 gv = *(const float4*)&g_gmap[(size_t)b*HWSZ + pix];
        float4 sv = *(const float4*)&g_smap[(size_t)b*HWSZ + pix];
        float gs[4] = {gv.x, gv.y, gv.z, gv.w};
        float ss[4] = {sv.x, sv.y, sv.z, sv.w};
        #pragma unroll
        for (int mp = 0; mp < 8; mp++) {
            int ch = mbase + 2*mp;
            float b0 = s_b[ch], b1 = s_b[ch+1];
            float lo[4], hi[4];
            #pragma unroll
            for (int p = 0; p < 4; p++) {
                float alo, ahi;
                upk2(acc[mp][p], alo, ahi);
                lo[p] = ss[p] * (gs[p]*alo + b0);
                hi[p] = ss[p] * (gs[p]*ahi + b1);
            }
            float4 vlo = {lo[0], lo[1], lo[2], lo[3]};
            float4 vhi = {hi[0], hi[1], hi[2], hi[3]};
            *(float4*)&outp[((size_t)(b*64 + ch  ))*HWSZ + pix] = vlo;
            *(float4*)&outp[((size_t)(b*64 + ch+1))*HWSZ + pix] = vhi;
        }
    } else {
        #pragma unroll
        for (int mp = 0; mp < 8; mp++) {
            int ch = mbase + 2*mp;
            float b0 = s_b[ch], b1 = s_b[ch+1];
            size_t i0 = ((size_t)(b*64 + ch  ))*HWSZ + pix;
            size_t i1 = ((size_t)(b*64 + ch+1))*HWSZ + pix;
            float4 r0 = *(const float4*)&resid[i0];
            float4 r1 = *(const float4*)&resid[i1];
            float lo[4], hi[4];
            #pragma unroll
            for (int p = 0; p < 4; p++) {
                float alo, ahi;
                upk2(acc[mp][p], alo, ahi);
                lo[p] = alo + b0;
                hi[p] = ahi + b1;
            }
            float4 vlo = {lo[0]+r0.x, lo[1]+r0.y, lo[2]+r0.z, lo[3]+r0.w};
            float4 vhi = {hi[0]+r1.x, hi[1]+r1.y, hi[2]+r1.z, hi[3]+r1.w};
            *(float4*)&outp[i0] = vlo;
            *(float4*)&outp[i1] = vhi;
        }
    }
}

// ---------------------------------------------------------------------------
extern "C" void kernel_launch(void* const* d_in, const int* in_sizes, int n_in,
                              void* d_out, int out_size)
{
    (void)in_sizes; (void)n_in; (void)out_size;
    const float* x     = (const float*)d_in[0];
    const float* ba_w1 = (const float*)d_in[1];
    const float* ba_b1 = (const float*)d_in[2];
    const float* ba_w2 = (const float*)d_in[3];
    const float* ba_b2 = (const float*)d_in[4];
    // d_in[5..12]: offset branch — dead code in the reference, skipped.
    const float* rk5w  = (const float*)d_in[13];
    const float* rk5b  = (const float*)d_in[14];
    const float* rk7w  = (const float*)d_in[15];
    const float* rk7b  = (const float*)d_in[16];
    const float* lk5w  = (const float*)d_in[17];
    const float* lk5b  = (const float*)d_in[18];
    const float* lk7w  = (const float*)d_in[19];
    const float* lk7b  = (const float*)d_in[20];
    const float* sfw   = (const float*)d_in[21];
    const float* sfb   = (const float*)d_in[22];
    const float* sfg   = (const float*)d_in[23];
    const float* sfbb  = (const float*)d_in[24];
    const float* sfm   = (const float*)d_in[25];
    const float* sfv   = (const float*)d_in[26];
    const float* fcw   = (const float*)d_in[27];
    const float* fcb   = (const float*)d_in[28];
    float* out = (float*)d_out;

    float *pFus, *pT, *pWeff, *pBeff, *pW1t, *pW2t, *pB2;
    cudaGetSymbolAddress((void**)&pFus,  g_fusion);
    cudaGetSymbolAddress((void**)&pT,    g_t);
    cudaGetSymbolAddress((void**)&pWeff, g_Weff);
    cudaGetSymbolAddress((void**)&pBeff, g_beff);
    cudaGetSymbolAddress((void**)&pW1t,  g_w1t);
    cudaGetSymbolAddress((void**)&pW2t,  g_w2t);
    cudaGetSymbolAddress((void**)&pB2,   g_b2);

    build_weff<<<16, 256>>>(rk5w, rk5b, rk7w, rk7b, lk5w, lk5b, lk7w, lk7b);
    prep_w<<<144, 256>>>(ba_w1, sfw, sfb, sfg, sfbb, sfm, sfv);

    conv32_edge_k<<<dim3(WW/32, HH/8, BB), 256>>>(x, pW1t, ba_b1, ba_w2, ba_b2);

    dim3 ggrid(HWSZ/256, BB);
    gemm1x1_k<0><<<ggrid, 256>>>(x, pWeff, pBeff, nullptr, pFus);
    conv64_k<<<dim3(WW/32, HH/4, BB), 256>>>(pFus, pW2t, pB2, pT);
    gemm1x1_k<1><<<ggrid, 256>>>(pT, fcw, fcb, x, out);
}

// round 7
// speedup vs baseline: 1.7810x; 1.0368x over previous
#include <cuda_runtime.h>
#include <cstddef>

#define BB 4
#define HH 160
#define WW 160
#define HWSZ (HH*WW)

typedef unsigned long long ull;

// ---------------- packed f32x2 helpers -------------------------------------
__device__ __forceinline__ ull pk2(float lo, float hi) {
    ull r; asm("mov.b64 %0,{%1,%2};" : "=l"(r) : "f"(lo), "f"(hi)); return r;
}
__device__ __forceinline__ void upk2(ull v, float& lo, float& hi) {
    asm("mov.b64 {%0,%1},%2;" : "=f"(lo), "=f"(hi) : "l"(v));
}
__device__ __forceinline__ float lo2(ull v) {
    float a, b; upk2(v, a, b); return a;
}
__device__ __forceinline__ ull f2fma(ull a, ull b, ull c) {
    ull d; asm("fma.rn.f32x2 %0,%1,%2,%3;" : "=l"(d) : "l"(a), "l"(b), "l"(c)); return d;
}

// ---------------- scratch (device globals; no allocation allowed) ----------
__device__ __align__(128) float g_gmap[BB*HWSZ];
__device__ __align__(128) float g_smap[BB*HWSZ];
__device__ __align__(128) float g_fusion[BB*64*HWSZ];
__device__ __align__(128) float g_Weff[64*64];
__device__ __align__(128) float g_beff[64];
__device__ __align__(128) float g_w1t[64*9*32];   // [ci][tap][oc]
__device__ __align__(128) float g_w2t[64*9*64];   // [ci][tap][oc], BN-folded
__device__ __align__(128) float g_b2[64];         // BN-folded bias

// ---------------- K0a: effective dyn1d weights (sum over K) ----------------
__global__ void build_weff(const float* __restrict__ rk5w, const float* __restrict__ rk5b,
                           const float* __restrict__ rk7w, const float* __restrict__ rk7b,
                           const float* __restrict__ lk5w, const float* __restrict__ lk5b,
                           const float* __restrict__ lk7w, const float* __restrict__ lk7b)
{
    int id = blockIdx.x*blockDim.x + threadIdx.x;
    if (id >= 64*64) return;
    int m = id >> 6, c = id & 63;
    const float* w; const float* bs; int K, o;
    if      (m < 16) { w = rk5w; bs = rk5b; K = 5; o = m;    }
    else if (m < 32) { w = rk7w; bs = rk7b; K = 7; o = m-16; }
    else if (m < 48) { w = lk5w; bs = lk5b; K = 5; o = m-32; }
    else             { w = lk7w; bs = lk7b; K = 7; o = m-48; }
    float acc = 0.f;
    for (int k = 0; k < K; k++) acc += w[(o*K + k)*64 + c];
    g_Weff[m*64 + c] = acc;
    if (c == 0) {
        float bacc = 0.f;
        for (int k = 0; k < K; k++) bacc += bs[o*K + k];
        g_beff[m] = bacc;
    }
}

// ---------------- K0b: transpose conv weights, fold BN into w2 -------------
__global__ void prep_w(const float* __restrict__ w1, const float* __restrict__ w2,
                       const float* __restrict__ b2, const float* __restrict__ bg,
                       const float* __restrict__ bbta, const float* __restrict__ bm,
                       const float* __restrict__ bv)
{
    int id = blockIdx.x*blockDim.x + threadIdx.x;
    if (id < 64*9*32) {
        int ci = id/(9*32); int rem = id%(9*32); int t = rem/32; int oc = rem%32;
        g_w1t[id] = w1[(oc*64 + ci)*9 + t];
    }
    if (id < 64*9*64) {
        int ci = id/(9*64); int rem = id%(9*64); int t = rem/64; int oc = rem%64;
        float sc = bg[oc] * rsqrtf(bv[oc] + 1e-5f);
        g_w2t[id] = w2[(oc*64 + ci)*9 + t] * sc;
        if (id < 64) {
            float scc = bg[id] * rsqrtf(bv[id] + 1e-5f);
            g_b2[id] = b2[id]*scc + bbta[id] - bm[id]*scc;
        }
    }
}

// ---------------- K1: fused conv3x3<32> + sobel edge + attention -----------
// Tile 32w x 8h. 256 thr = 64 px-threads (4 vert px) x 4 oc-groups of 8.
__global__ __launch_bounds__(256)
void conv32_edge_k(const float* __restrict__ in, const float* __restrict__ wt_t,
                   const float* __restrict__ bias,
                   const float* __restrict__ baw2, const float* __restrict__ bab2)
{
    constexpr int CH = 8;
    __shared__ ull s_ind[CH][10][34];
    __shared__ __align__(16) float s_w[CH][9][32];
    __shared__ float s_att[4][64][4];
    __shared__ float s_edge[4][64][4];
    __shared__ float s_sum[4][64][4];
    __shared__ float s_b1[32], s_w2[32];

    const int w0 = blockIdx.x*32, h0 = blockIdx.y*8;
    const int b  = blockIdx.z;
    const int tid = threadIdx.x;
    const int ocg = tid >> 6;            // 0..3
    const int pt  = tid & 63;
    const int px  = pt & 31;
    const int py0 = (pt >> 5) * 4;       // 0 or 4

    if (tid < 32) { s_b1[tid] = bias[tid]; s_w2[tid] = baw2[tid]; }

    ull acc[4][4];                       // [m-pair][px]
    #pragma unroll
    for (int i = 0; i < 4; i++)
        #pragma unroll
        for (int p = 0; p < 4; p++) acc[i][p] = 0ULL;
    float edge[4] = {0.f,0.f,0.f,0.f};
    float sumx[4] = {0.f,0.f,0.f,0.f};

    for (int c0 = 0; c0 < 64; c0 += CH) {
        for (int i = tid; i < CH*340; i += 256) {
            int ci = i / 340, rem = i % 340;
            int r = rem / 34, cc = rem % 34;
            int gh = h0 - 1 + r, gw = w0 - 1 + cc;
            float v = 0.f;
            if (gh >= 0 && gh < HH && gw >= 0 && gw < WW)
                v = in[((size_t)(b*64 + c0 + ci))*HWSZ + gh*WW + gw];
            s_ind[ci][r][cc] = pk2(v, v);
        }
        {
            const float4* src = (const float4*)(wt_t + (size_t)c0*9*32);
            float4* dst = (float4*)&s_w[0][0][0];
            for (int i = tid; i < CH*9*32/4; i += 256) dst[i] = src[i];
        }
        __syncthreads();

        #pragma unroll 1
        for (int ci = 0; ci < CH; ci++) {
            ull vd[6][3];
            #pragma unroll
            for (int r = 0; r < 6; r++)
                #pragma unroll
                for (int c = 0; c < 3; c++)
                    vd[r][c] = s_ind[ci][py0 + r][px + c];

            if ((ci & 3) == ocg) {
                #pragma unroll
                for (int j = 0; j < 4; j++) {
                    float a00=lo2(vd[j  ][0]), a01=lo2(vd[j  ][1]), a02=lo2(vd[j  ][2]);
                    float a10=lo2(vd[j+1][0]), a11=lo2(vd[j+1][1]), a12=lo2(vd[j+1][2]);
                    float a20=lo2(vd[j+2][0]), a21=lo2(vd[j+2][1]), a22=lo2(vd[j+2][2]);
                    sumx[j] += a11;
                    if (c0 < 32) {
                        float gx = (a02 - a00) + 2.f*(a12 - a10) + (a22 - a20);
                        edge[j] += fabsf(gx);
                    } else {
                        float gy = (a20 - a00) + 2.f*(a21 - a01) + (a22 - a02);
                        edge[j] += fabsf(gy);
                    }
                }
            }

            #pragma unroll
            for (int t = 0; t < 9; t++) {
                const int dr = t/3, dc = t%3;
                const ulonglong2* wp = (const ulonglong2*)&s_w[ci][t][ocg*8];
                ulonglong2 wa = wp[0], wb = wp[1];
                #pragma unroll
                for (int p = 0; p < 4; p++) {
                    ull v = vd[dr + p][dc];
                    acc[0][p] = f2fma(wa.x, v, acc[0][p]);
                    acc[1][p] = f2fma(wa.y, v, acc[1][p]);
                    acc[2][p] = f2fma(wb.x, v, acc[2][p]);
                    acc[3][p] = f2fma(wb.y, v, acc[3][p]);
                }
            }
        }
        __syncthreads();
    }

    float attp[4] = {0.f,0.f,0.f,0.f};
    #pragma unroll
    for (int mp = 0; mp < 4; mp++) {
        int oc = ocg*8 + 2*mp;
        float b0v = s_b1[oc], b1v = s_b1[oc+1];
        float w0v = s_w2[oc], w1v = s_w2[oc+1];
        #pragma unroll
        for (int p = 0; p < 4; p++) {
            float alo, ahi;
            upk2(acc[mp][p], alo, ahi);
            attp[p] += w0v*fmaxf(alo + b0v, 0.f) + w1v*fmaxf(ahi + b1v, 0.f);
        }
    }
    #pragma unroll
    for (int p = 0; p < 4; p++) {
        s_att [ocg][pt][p] = attp[p];
        s_edge[ocg][pt][p] = edge[p];
        s_sum [ocg][pt][p] = sumx[p];
    }
    __syncthreads();

    if (ocg == 0) {
        float bb = bab2[0];
        #pragma unroll
        for (int p = 0; p < 4; p++) {
            float att = bb, ed = 0.f, sx = 0.f;
            #pragma unroll
            for (int g = 0; g < 4; g++) {
                att += s_att[g][pt][p];
                ed  += s_edge[g][pt][p];
                sx  += s_sum[g][pt][p];
            }
            float z = att + ed*(1.f/32.f);
            float a = 1.f / (1.f + expf(-z));
            float gv = 1.f + a;
            size_t pix = (size_t)b*HWSZ + (size_t)(h0 + py0 + p)*WW + (w0 + px);
            g_gmap[pix] = gv;
            g_smap[pix] = gv * sx;
        }
    }
}

// ---------------- K3: fusion GEMM, m-split for occupancy -------------------
// Block: 32m x 256px. Thread: 8m x 4px (16 ull accs).
// fusion = s * ( g * (Weff @ x) + beff )
__global__ __launch_bounds__(256)
void fusion_k(const float* __restrict__ in, const float* __restrict__ wsrc,
              const float* __restrict__ bsrc, float* __restrict__ outp)
{
    __shared__ __align__(16) float s_w[64][32];   // [ci][m-half], 8KB
    __shared__ float s_b[32];
    const int tid = threadIdx.x;
    const int ms  = blockIdx.y;          // m-split 0/1
    const int b   = blockIdx.z;
    for (int i = tid; i < 2048; i += 256) {
        int ci = i >> 5, m = i & 31;
        s_w[ci][m] = wsrc[(ms*32 + m)*64 + ci];
    }
    if (tid < 32) s_b[tid] = bsrc[ms*32 + tid];
    __syncthreads();

    const int mg    = tid >> 6;          // 0..3
    const int mbase = mg*8;
    const int slot  = tid & 63;
    const int pix   = blockIdx.x*256 + slot*4;

    ull acc[4][4];
    #pragma unroll
    for (int m = 0; m < 4; m++)
        #pragma unroll
        for (int p = 0; p < 4; p++) acc[m][p] = 0ULL;

    #pragma unroll 1
    for (int c4 = 0; c4 < 16; c4++) {
        const float* bp = in + ((size_t)(b*64 + c4*4))*HWSZ + pix;
        float4 xv[4];
        #pragma unroll
        for (int j = 0; j < 4; j++)
            xv[j] = *(const float4*)(bp + (size_t)j*HWSZ);
        #pragma unroll
        for (int j = 0; j < 4; j++) {
            ull xd0 = pk2(xv[j].x, xv[j].x);
            ull xd1 = pk2(xv[j].y, xv[j].y);
            ull xd2 = pk2(xv[j].z, xv[j].z);
            ull xd3 = pk2(xv[j].w, xv[j].w);
            const ulonglong2* wp = (const ulonglong2*)&s_w[c4*4 + j][mbase];
            ulonglong2 wA = wp[0], wB = wp[1];
            acc[0][0]=f2fma(wA.x,xd0,acc[0][0]); acc[0][1]=f2fma(wA.x,xd1,acc[0][1]);
            acc[0][2]=f2fma(wA.x,xd2,acc[0][2]); acc[0][3]=f2fma(wA.x,xd3,acc[0][3]);
            acc[1][0]=f2fma(wA.y,xd0,acc[1][0]); acc[1][1]=f2fma(wA.y,xd1,acc[1][1]);
            acc[1][2]=f2fma(wA.y,xd2,acc[1][2]); acc[1][3]=f2fma(wA.y,xd3,acc[1][3]);
            acc[2][0]=f2fma(wB.x,xd0,acc[2][0]); acc[2][1]=f2fma(wB.x,xd1,acc[2][1]);
            acc[2][2]=f2fma(wB.x,xd2,acc[2][2]); acc[2][3]=f2fma(wB.x,xd3,acc[2][3]);
            acc[3][0]=f2fma(wB.y,xd0,acc[3][0]); acc[3][1]=f2fma(wB.y,xd1,acc[3][1]);
            acc[3][2]=f2fma(wB.y,xd2,acc[3][2]); acc[3][3]=f2fma(wB.y,xd3,acc[3][3]);
        }
    }

    float4 gv = *(const float4*)&g_gmap[(size_t)b*HWSZ + pix];
    float4 sv = *(const float4*)&g_smap[(size_t)b*HWSZ + pix];
    float gs[4] = {gv.x, gv.y, gv.z, gv.w};
    float ss[4] = {sv.x, sv.y, sv.z, sv.w};
    #pragma unroll
    for (int mp = 0; mp < 4; mp++) {
        int ch = ms*32 + mbase + 2*mp;
        float b0 = s_b[mbase + 2*mp], b1 = s_b[mbase + 2*mp + 1];
        float lo[4], hi[4];
        #pragma unroll
        for (int p = 0; p < 4; p++) {
            float alo, ahi;
            upk2(acc[mp][p], alo, ahi);
            lo[p] = ss[p] * (gs[p]*alo + b0);
            hi[p] = ss[p] * (gs[p]*ahi + b1);
        }
        float4 vlo = {lo[0], lo[1], lo[2], lo[3]};
        float4 vhi = {hi[0], hi[1], hi[2], hi[3]};
        *(float4*)&outp[((size_t)(b*64 + ch  ))*HWSZ + pix] = vlo;
        *(float4*)&outp[((size_t)(b*64 + ch+1))*HWSZ + pix] = vhi;
    }
}

// ---------------- K4: fused conv3x3<64> (BN folded) + fc 1x1 + residual ----
// Phase 1: conv (tile 32w x 4h, 8 oc-groups of 8, 4 vert px/thread),
//          write relu(conv) t-tile to smem.
// Phase 2: fc GEMM over t-tile from smem + fc bias + residual -> out.
__global__ __launch_bounds__(256)
void conv64fc_k(const float* __restrict__ in, const float* __restrict__ wt_t,
                const float* __restrict__ bias,
                const float* __restrict__ fcw, const float* __restrict__ fcb,
                const float* __restrict__ resid, float* __restrict__ out)
{
    constexpr int CH = 8;
    __shared__ __align__(16) char s_u[32768];
    ull   (*s_ind)[6][34] = (ull(*)[6][34])s_u;              // 13056 B
    float (*s_w)[9][64]   = (float(*)[9][64])(s_u + 13056);  // 18432 B
    float (*s_t)[128]     = (float(*)[128])s_u;              // 32768 B (phase 2)
    __shared__ __align__(16) float s_fcw[64][64];            // 16KB
    __shared__ float s_fcb[64];

    const int w0 = blockIdx.x*32, h0 = blockIdx.y*4;
    const int b  = blockIdx.z;
    const int tid = threadIdx.x;
    const int ocg = tid >> 5;            // 0..7
    const int px  = tid & 31;

    // stage fc weights (consumed in phase 2; ordered by the loop syncs)
    for (int i = tid; i < 4096; i += 256) {
        int ci = i >> 6, m = i & 63;
        s_fcw[ci][m] = fcw[m*64 + ci];
    }
    if (tid < 64) s_fcb[tid] = fcb[tid];

    ull acc[4][4];
    #pragma unroll
    for (int i = 0; i < 4; i++)
        #pragma unroll
        for (int p = 0; p < 4; p++) acc[i][p] = 0ULL;

    for (int c0 = 0; c0 < 64; c0 += CH) {
        for (int i = tid; i < CH*204; i += 256) {
            int ci = i / 204, rem = i % 204;
            int r = rem / 34, cc = rem % 34;
            int gh = h0 - 1 + r, gw = w0 - 1 + cc;
            float v = 0.f;
            if (gh >= 0 && gh < HH && gw >= 0 && gw < WW)
                v = in[((size_t)(b*64 + c0 + ci))*HWSZ + gh*WW + gw];
            s_ind[ci][r][cc] = pk2(v, v);
        }
        {
            const float4* src = (const float4*)(wt_t + (size_t)c0*9*64);
            float4* dst = (float4*)&s_w[0][0][0];
            for (int i = tid; i < CH*9*64/4; i += 256) dst[i] = src[i];
        }
        __syncthreads();

        #pragma unroll 1
        for (int ci = 0; ci < CH; ci++) {
            ull vd[6][3];
            #pragma unroll
            for (int r = 0; r < 6; r++)
                #pragma unroll
                for (int c = 0; c < 3; c++)
                    vd[r][c] = s_ind[ci][r][px + c];

            #pragma unroll
            for (int t = 0; t < 9; t++) {
                const int dr = t/3, dc = t%3;
                const ulonglong2* wp = (const ulonglong2*)&s_w[ci][t][ocg*8];
                ulonglong2 wa = wp[0], wb = wp[1];
                #pragma unroll
                for (int p = 0; p < 4; p++) {
                    ull v = vd[dr + p][dc];
                    acc[0][p] = f2fma(wa.x, v, acc[0][p]);
                    acc[1][p] = f2fma(wa.y, v, acc[1][p]);
                    acc[2][p] = f2fma(wb.x, v, acc[2][p]);
                    acc[3][p] = f2fma(wb.y, v, acc[3][p]);
                }
            }
        }
        __syncthreads();
    }

    // phase 1 epilogue: bias(+BN folded)+relu -> s_t[ch][row*32+w]
    #pragma unroll
    for (int mp = 0; mp < 4; mp++) {
        int oc = ocg*8 + 2*mp;
        float b0 = bias[oc], b1 = bias[oc+1];
        #pragma unroll
        for (int p = 0; p < 4; p++) {
            float olo, ohi;
            upk2(acc[mp][p], olo, ohi);
            s_t[oc  ][p*32 + px] = fmaxf(olo + b0, 0.f);
            s_t[oc+1][p*32 + px] = fmaxf(ohi + b1, 0.f);
        }
    }
    __syncthreads();

    // phase 2: fc GEMM. thread = 8m (mg) x 4px (slot)
    const int mg2   = tid >> 5;          // 0..7
    const int mb2   = mg2*8;
    const int slot  = tid & 31;
    const int row   = slot >> 3;         // 0..3
    const int pcol  = (slot & 7) * 4;    // 0..28
    const int p0    = row*32 + pcol;

    ull facc[4][4];
    #pragma unroll
    for (int m = 0; m < 4; m++)
        #pragma unroll
        for (int p = 0; p < 4; p++) facc[m][p] = 0ULL;

    #pragma unroll 4
    for (int ci = 0; ci < 64; ci++) {
        float4 tv = *(const float4*)&s_t[ci][p0];
        ull xd0 = pk2(tv.x, tv.x);
        ull xd1 = pk2(tv.y, tv.y);
        ull xd2 = pk2(tv.z, tv.z);
        ull xd3 = pk2(tv.w, tv.w);
        const ulonglong2* wp = (const ulonglong2*)&s_fcw[ci][mb2];
        ulonglong2 wA = wp[0], wB = wp[1];
        facc[0][0]=f2fma(wA.x,xd0,facc[0][0]); facc[0][1]=f2fma(wA.x,xd1,facc[0][1]);
        facc[0][2]=f2fma(wA.x,xd2,facc[0][2]); facc[0][3]=f2fma(wA.x,xd3,facc[0][3]);
        facc[1][0]=f2fma(wA.y,xd0,facc[1][0]); facc[1][1]=f2fma(wA.y,xd1,facc[1][1]);
        facc[1][2]=f2fma(wA.y,xd2,facc[1][2]); facc[1][3]=f2fma(wA.y,xd3,facc[1][3]);
        facc[2][0]=f2fma(wB.x,xd0,facc[2][0]); facc[2][1]=f2fma(wB.x,xd1,facc[2][1]);
        facc[2][2]=f2fma(wB.x,xd2,facc[2][2]); facc[2][3]=f2fma(wB.x,xd3,facc[2][3]);
        facc[3][0]=f2fma(wB.y,xd0,facc[3][0]); facc[3][1]=f2fma(wB.y,xd1,facc[3][1]);
        facc[3][2]=f2fma(wB.y,xd2,facc[3][2]); facc[3][3]=f2fma(wB.y,xd3,facc[3][3]);
    }

    #pragma unroll
    for (int mp = 0; mp < 4; mp++) {
        int ch = mb2 + 2*mp;
        float b0 = s_fcb[ch], b1 = s_fcb[ch+1];
        size_t i0 = ((size_t)(b*64 + ch  ))*HWSZ + (size_t)(h0 + row)*WW + w0 + pcol;
        size_t i1 = i0 + HWSZ;
        float4 r0 = *(const float4*)&resid[i0];
        float4 r1 = *(const float4*)&resid[i1];
        float lo[4], hi[4];
        #pragma unroll
        for (int p = 0; p < 4; p++) {
            float alo, ahi;
            upk2(facc[mp][p], alo, ahi);
            lo[p] = alo + b0;
            hi[p] = ahi + b1;
        }
        float4 vlo = {lo[0]+r0.x, lo[1]+r0.y, lo[2]+r0.z, lo[3]+r0.w};
        float4 vhi = {hi[0]+r1.x, hi[1]+r1.y, hi[2]+r1.z, hi[3]+r1.w};
        *(float4*)&out[i0] = vlo;
        *(float4*)&out[i1] = vhi;
    }
}

// ---------------------------------------------------------------------------
extern "C" void kernel_launch(void* const* d_in, const int* in_sizes, int n_in,
                              void* d_out, int out_size)
{
    (void)in_sizes; (void)n_in; (void)out_size;
    const float* x     = (const float*)d_in[0];
    const float* ba_w1 = (const float*)d_in[1];
    const float* ba_b1 = (const float*)d_in[2];
    const float* ba_w2 = (const float*)d_in[3];
    const float* ba_b2 = (const float*)d_in[4];
    // d_in[5..12]: offset branch — dead code in the reference, skipped.
    const float* rk5w  = (const float*)d_in[13];
    const float* rk5b  = (const float*)d_in[14];
    const float* rk7w  = (const float*)d_in[15];
    const float* rk7b  = (const float*)d_in[16];
    const float* lk5w  = (const float*)d_in[17];
    const float* lk5b  = (const float*)d_in[18];
    const float* lk7w  = (const float*)d_in[19];
    const float* lk7b  = (const float*)d_in[20];
    const float* sfw   = (const float*)d_in[21];
    const float* sfb   = (const float*)d_in[22];
    const float* sfg   = (const float*)d_in[23];
    const float* sfbb  = (const float*)d_in[24];
    const float* sfm   = (const float*)d_in[25];
    const float* sfv   = (const float*)d_in[26];
    const float* fcw   = (const float*)d_in[27];
    const float* fcb   = (const float*)d_in[28];
    float* out = (float*)d_out;

    float *pFus, *pWeff, *pBeff, *pW1t, *pW2t, *pB2;
    cudaGetSymbolAddress((void**)&pFus,  g_fusion);
    cudaGetSymbolAddress((void**)&pWeff, g_Weff);
    cudaGetSymbolAddress((void**)&pBeff, g_beff);
    cudaGetSymbolAddress((void**)&pW1t,  g_w1t);
    cudaGetSymbolAddress((void**)&pW2t,  g_w2t);
    cudaGetSymbolAddress((void**)&pB2,   g_b2);

    build_weff<<<16, 256>>>(rk5w, rk5b, rk7w, rk7b, lk5w, lk5b, lk7w, lk7b);
    prep_w<<<144, 256>>>(ba_w1, sfw, sfb, sfg, sfbb, sfm, sfv);

    conv32_edge_k<<<dim3(WW/32, HH/8, BB), 256>>>(x, pW1t, ba_b1, ba_w2, ba_b2);
    fusion_k<<<dim3(HWSZ/256, 2, BB), 256>>>(x, pWeff, pBeff, pFus);
    conv64fc_k<<<dim3(WW/32, HH/4, BB), 256>>>(pFus, pW2t, pB2, fcw, fcb, x, out);
}

// round 8
// speedup vs baseline: 1.9890x; 1.1168x over previous
#include <cuda_runtime.h>
#include <cstddef>

#define BB 4
#define HH 160
#define WW 160
#define HWSZ (HH*WW)

typedef unsigned long long ull;

// ---------------- packed f32x2 helpers -------------------------------------
__device__ __forceinline__ ull pk2(float lo, float hi) {
    ull r; asm("mov.b64 %0,{%1,%2};" : "=l"(r) : "f"(lo), "f"(hi)); return r;
}
__device__ __forceinline__ void upk2(ull v, float& lo, float& hi) {
    asm("mov.b64 {%0,%1},%2;" : "=f"(lo), "=f"(hi) : "l"(v));
}
__device__ __forceinline__ float lo2(ull v) {
    float a, b; upk2(v, a, b); return a;
}
__device__ __forceinline__ ull f2fma(ull a, ull b, ull c) {
    ull d; asm("fma.rn.f32x2 %0,%1,%2,%3;" : "=l"(d) : "l"(a), "l"(b), "l"(c)); return d;
}

// ---------------- scratch (device globals; no allocation allowed) ----------
__device__ __align__(128) float g_gmap[BB*HWSZ];
__device__ __align__(128) float g_smap[BB*HWSZ];
__device__ __align__(128) float g_fusion[BB*64*HWSZ];
__device__ __align__(128) float g_Weff[64*64];
__device__ __align__(128) float g_beff[64];
__device__ __align__(128) float g_w1t[64*9*32];   // [ci][tap][oc]
__device__ __align__(128) float g_w2t[64*9*64];   // [ci][tap][oc], BN-folded
__device__ __align__(128) float g_b2[64];         // BN-folded bias

// ---------------- K0a: effective dyn1d weights (sum over K) ----------------
__global__ void build_weff(const float* __restrict__ rk5w, const float* __restrict__ rk5b,
                           const float* __restrict__ rk7w, const float* __restrict__ rk7b,
                           const float* __restrict__ lk5w, const float* __restrict__ lk5b,
                           const float* __restrict__ lk7w, const float* __restrict__ lk7b)
{
    int id = blockIdx.x*blockDim.x + threadIdx.x;
    if (id >= 64*64) return;
    int m = id >> 6, c = id & 63;
    const float* w; const float* bs; int K, o;
    if      (m < 16) { w = rk5w; bs = rk5b; K = 5; o = m;    }
    else if (m < 32) { w = rk7w; bs = rk7b; K = 7; o = m-16; }
    else if (m < 48) { w = lk5w; bs = lk5b; K = 5; o = m-32; }
    else             { w = lk7w; bs = lk7b; K = 7; o = m-48; }
    float acc = 0.f;
    for (int k = 0; k < K; k++) acc += w[(o*K + k)*64 + c];
    g_Weff[m*64 + c] = acc;
    if (c == 0) {
        float bacc = 0.f;
        for (int k = 0; k < K; k++) bacc += bs[o*K + k];
        g_beff[m] = bacc;
    }
}

// ---------------- K0b: transpose conv weights, fold BN into w2 -------------
__global__ void prep_w(const float* __restrict__ w1, const float* __restrict__ w2,
                       const float* __restrict__ b2, const float* __restrict__ bg,
                       const float* __restrict__ bbta, const float* __restrict__ bm,
                       const float* __restrict__ bv)
{
    int id = blockIdx.x*blockDim.x + threadIdx.x;
    if (id < 64*9*32) {
        int ci = id/(9*32); int rem = id%(9*32); int t = rem/32; int oc = rem%32;
        g_w1t[id] = w1[(oc*64 + ci)*9 + t];
    }
    if (id < 64*9*64) {
        int ci = id/(9*64); int rem = id%(9*64); int t = rem/64; int oc = rem%64;
        float sc = bg[oc] * rsqrtf(bv[oc] + 1e-5f);
        g_w2t[id] = w2[(oc*64 + ci)*9 + t] * sc;
        if (id < 64) {
            float scc = bg[id] * rsqrtf(bv[id] + 1e-5f);
            g_b2[id] = b2[id]*scc + bbta[id] - bm[id]*scc;
        }
    }
}

// ---------------- K1: fused conv3x3<32> + sobel edge + attention -----------
// Tile 32w x 8h. Register-prefetch pipeline over ci chunks.
__global__ __launch_bounds__(256)
void conv32_edge_k(const float* __restrict__ in, const float* __restrict__ wt_t,
                   const float* __restrict__ bias,
                   const float* __restrict__ baw2, const float* __restrict__ bab2)
{
    constexpr int CH = 8;
    constexpr int NIN = 11;   // ceil(8*340/256)
    constexpr int NW  = 3;    // ceil(8*9*32/4/256)
    __shared__ ull s_ind[CH][10][34];
    __shared__ __align__(16) float s_w[CH][9][32];
    __shared__ float s_att[4][64][4];
    __shared__ float s_edge[4][64][4];
    __shared__ float s_sum[4][64][4];
    __shared__ float s_b1[32], s_w2[32];

    const int w0 = blockIdx.x*32, h0 = blockIdx.y*8;
    const int b  = blockIdx.z;
    const int tid = threadIdx.x;
    const int ocg = tid >> 6;
    const int pt  = tid & 63;
    const int px  = pt & 31;
    const int py0 = (pt >> 5) * 4;

    if (tid < 32) { s_b1[tid] = bias[tid]; s_w2[tid] = baw2[tid]; }

    float  rin[NIN];
    float4 rw[NW];

    // prefetch chunk 0
    {
        const int c0 = 0;
        #pragma unroll
        for (int k = 0; k < NIN; k++) {
            int i = tid + k*256;
            float v = 0.f;
            if (i < CH*340) {
                int ci = i / 340, rem = i % 340;
                int r = rem / 34, cc = rem % 34;
                int gh = h0 - 1 + r, gw = w0 - 1 + cc;
                if (gh >= 0 && gh < HH && gw >= 0 && gw < WW)
                    v = in[((size_t)(b*64 + c0 + ci))*HWSZ + gh*WW + gw];
            }
            rin[k] = v;
        }
        const float4* src = (const float4*)(wt_t + (size_t)c0*9*32);
        #pragma unroll
        for (int k = 0; k < NW; k++) {
            int i = tid + k*256;
            rw[k] = (i < CH*9*32/4) ? src[i] : make_float4(0.f,0.f,0.f,0.f);
        }
    }

    ull acc[4][4];
    #pragma unroll
    for (int i = 0; i < 4; i++)
        #pragma unroll
        for (int p = 0; p < 4; p++) acc[i][p] = 0ULL;
    float edge[4] = {0.f,0.f,0.f,0.f};
    float sumx[4] = {0.f,0.f,0.f,0.f};

    for (int c0 = 0; c0 < 64; c0 += CH) {
        // store staged registers to smem
        #pragma unroll
        for (int k = 0; k < NIN; k++) {
            int i = tid + k*256;
            if (i < CH*340) {
                int ci = i / 340, rem = i % 340;
                int r = rem / 34, cc = rem % 34;
                s_ind[ci][r][cc] = pk2(rin[k], rin[k]);
            }
        }
        {
            float4* dst = (float4*)&s_w[0][0][0];
            #pragma unroll
            for (int k = 0; k < NW; k++) {
                int i = tid + k*256;
                if (i < CH*9*32/4) dst[i] = rw[k];
            }
        }
        __syncthreads();

        // prefetch next chunk (latency overlapped with compute below)
        if (c0 + CH < 64) {
            const int cn = c0 + CH;
            #pragma unroll
            for (int k = 0; k < NIN; k++) {
                int i = tid + k*256;
                float v = 0.f;
                if (i < CH*340) {
                    int ci = i / 340, rem = i % 340;
                    int r = rem / 34, cc = rem % 34;
                    int gh = h0 - 1 + r, gw = w0 - 1 + cc;
                    if (gh >= 0 && gh < HH && gw >= 0 && gw < WW)
                        v = in[((size_t)(b*64 + cn + ci))*HWSZ + gh*WW + gw];
                }
                rin[k] = v;
            }
            const float4* src = (const float4*)(wt_t + (size_t)cn*9*32);
            #pragma unroll
            for (int k = 0; k < NW; k++) {
                int i = tid + k*256;
                if (i < CH*9*32/4) rw[k] = src[i];
            }
        }

        #pragma unroll 1
        for (int ci = 0; ci < CH; ci++) {
            ull vd[6][3];
            #pragma unroll
            for (int r = 0; r < 6; r++)
                #pragma unroll
                for (int c = 0; c < 3; c++)
                    vd[r][c] = s_ind[ci][py0 + r][px + c];

            if ((ci & 3) == ocg) {
                #pragma unroll
                for (int j = 0; j < 4; j++) {
                    float a00=lo2(vd[j  ][0]), a01=lo2(vd[j  ][1]), a02=lo2(vd[j  ][2]);
                    float a10=lo2(vd[j+1][0]), a11=lo2(vd[j+1][1]), a12=lo2(vd[j+1][2]);
                    float a20=lo2(vd[j+2][0]), a21=lo2(vd[j+2][1]), a22=lo2(vd[j+2][2]);
                    sumx[j] += a11;
                    if (c0 < 32) {
                        float gx = (a02 - a00) + 2.f*(a12 - a10) + (a22 - a20);
                        edge[j] += fabsf(gx);
                    } else {
                        float gy = (a20 - a00) + 2.f*(a21 - a01) + (a22 - a02);
                        edge[j] += fabsf(gy);
                    }
                }
            }

            #pragma unroll
            for (int t = 0; t < 9; t++) {
                const int dr = t/3, dc = t%3;
                const ulonglong2* wp = (const ulonglong2*)&s_w[ci][t][ocg*8];
                ulonglong2 wa = wp[0], wb = wp[1];
                #pragma unroll
                for (int p = 0; p < 4; p++) {
                    ull v = vd[dr + p][dc];
                    acc[0][p] = f2fma(wa.x, v, acc[0][p]);
                    acc[1][p] = f2fma(wa.y, v, acc[1][p]);
                    acc[2][p] = f2fma(wb.x, v, acc[2][p]);
                    acc[3][p] = f2fma(wb.y, v, acc[3][p]);
                }
            }
        }
        __syncthreads();
    }

    float attp[4] = {0.f,0.f,0.f,0.f};
    #pragma unroll
    for (int mp = 0; mp < 4; mp++) {
        int oc = ocg*8 + 2*mp;
        float b0v = s_b1[oc], b1v = s_b1[oc+1];
        float w0v = s_w2[oc], w1v = s_w2[oc+1];
        #pragma unroll
        for (int p = 0; p < 4; p++) {
            float alo, ahi;
            upk2(acc[mp][p], alo, ahi);
            attp[p] += w0v*fmaxf(alo + b0v, 0.f) + w1v*fmaxf(ahi + b1v, 0.f);
        }
    }
    #pragma unroll
    for (int p = 0; p < 4; p++) {
        s_att [ocg][pt][p] = attp[p];
        s_edge[ocg][pt][p] = edge[p];
        s_sum [ocg][pt][p] = sumx[p];
    }
    __syncthreads();

    if (ocg == 0) {
        float bb = bab2[0];
        #pragma unroll
        for (int p = 0; p < 4; p++) {
            float att = bb, ed = 0.f, sx = 0.f;
            #pragma unroll
            for (int g = 0; g < 4; g++) {
                att += s_att[g][pt][p];
                ed  += s_edge[g][pt][p];
                sx  += s_sum[g][pt][p];
            }
            float z = att + ed*(1.f/32.f);
            float a = 1.f / (1.f + expf(-z));
            float gv = 1.f + a;
            size_t pix = (size_t)b*HWSZ + (size_t)(h0 + py0 + p)*WW + (w0 + px);
            g_gmap[pix] = gv;
            g_smap[pix] = gv * sx;
        }
    }
}

// ---------------- K3: fusion GEMM, m-split, prefetched loads ---------------
__global__ __launch_bounds__(256)
void fusion_k(const float* __restrict__ in, const float* __restrict__ wsrc,
              const float* __restrict__ bsrc, float* __restrict__ outp)
{
    __shared__ __align__(16) float s_w[64][32];
    __shared__ float s_b[32];
    const int tid = threadIdx.x;
    const int ms  = blockIdx.y;
    const int b   = blockIdx.z;
    for (int i = tid; i < 2048; i += 256) {
        int ci = i >> 5, m = i & 31;
        s_w[ci][m] = wsrc[(ms*32 + m)*64 + ci];
    }
    if (tid < 32) s_b[tid] = bsrc[ms*32 + tid];
    __syncthreads();

    const int mg    = tid >> 6;
    const int mbase = mg*8;
    const int slot  = tid & 63;
    const int pix   = blockIdx.x*256 + slot*4;
    const float* basep = in + (size_t)b*64*HWSZ + pix;

    ull acc[4][4];
    #pragma unroll
    for (int m = 0; m < 4; m++)
        #pragma unroll
        for (int p = 0; p < 4; p++) acc[m][p] = 0ULL;

    float4 xv[4];
    #pragma unroll
    for (int j = 0; j < 4; j++)
        xv[j] = *(const float4*)(basep + (size_t)j*HWSZ);

    #pragma unroll 1
    for (int c4 = 0; c4 < 16; c4++) {
        float4 xn[4];
        if (c4 < 15) {
            const float* bp = basep + (size_t)(c4+1)*4*HWSZ;
            #pragma unroll
            for (int j = 0; j < 4; j++)
                xn[j] = *(const float4*)(bp + (size_t)j*HWSZ);
        }
        #pragma unroll
        for (int j = 0; j < 4; j++) {
            ull xd0 = pk2(xv[j].x, xv[j].x);
            ull xd1 = pk2(xv[j].y, xv[j].y);
            ull xd2 = pk2(xv[j].z, xv[j].z);
            ull xd3 = pk2(xv[j].w, xv[j].w);
            const ulonglong2* wp = (const ulonglong2*)&s_w[c4*4 + j][mbase];
            ulonglong2 wA = wp[0], wB = wp[1];
            acc[0][0]=f2fma(wA.x,xd0,acc[0][0]); acc[0][1]=f2fma(wA.x,xd1,acc[0][1]);
            acc[0][2]=f2fma(wA.x,xd2,acc[0][2]); acc[0][3]=f2fma(wA.x,xd3,acc[0][3]);
            acc[1][0]=f2fma(wA.y,xd0,acc[1][0]); acc[1][1]=f2fma(wA.y,xd1,acc[1][1]);
            acc[1][2]=f2fma(wA.y,xd2,acc[1][2]); acc[1][3]=f2fma(wA.y,xd3,acc[1][3]);
            acc[2][0]=f2fma(wB.x,xd0,acc[2][0]); acc[2][1]=f2fma(wB.x,xd1,acc[2][1]);
            acc[2][2]=f2fma(wB.x,xd2,acc[2][2]); acc[2][3]=f2fma(wB.x,xd3,acc[2][3]);
            acc[3][0]=f2fma(wB.y,xd0,acc[3][0]); acc[3][1]=f2fma(wB.y,xd1,acc[3][1]);
            acc[3][2]=f2fma(wB.y,xd2,acc[3][2]); acc[3][3]=f2fma(wB.y,xd3,acc[3][3]);
        }
        if (c4 < 15) {
            #pragma unroll
            for (int j = 0; j < 4; j++) xv[j] = xn[j];
        }
    }

    float4 gv = *(const float4*)&g_gmap[(size_t)b*HWSZ + pix];
    float4 sv = *(const float4*)&g_smap[(size_t)b*HWSZ + pix];
    float gs[4] = {gv.x, gv.y, gv.z, gv.w};
    float ss[4] = {sv.x, sv.y, sv.z, sv.w};
    #pragma unroll
    for (int mp = 0; mp < 4; mp++) {
        int ch = ms*32 + mbase + 2*mp;
        float b0 = s_b[mbase + 2*mp], b1 = s_b[mbase + 2*mp + 1];
        float lo[4], hi[4];
        #pragma unroll
        for (int p = 0; p < 4; p++) {
            float alo, ahi;
            upk2(acc[mp][p], alo, ahi);
            lo[p] = ss[p] * (gs[p]*alo + b0);
            hi[p] = ss[p] * (gs[p]*ahi + b1);
        }
        float4 vlo = {lo[0], lo[1], lo[2], lo[3]};
        float4 vhi = {hi[0], hi[1], hi[2], hi[3]};
        *(float4*)&outp[((size_t)(b*64 + ch  ))*HWSZ + pix] = vlo;
        *(float4*)&outp[((size_t)(b*64 + ch+1))*HWSZ + pix] = vhi;
    }
}

// ---------------- K4: fused conv3x3<64> + fc 1x1 + residual ----------------
__global__ __launch_bounds__(256)
void conv64fc_k(const float* __restrict__ in, const float* __restrict__ wt_t,
                const float* __restrict__ bias,
                const float* __restrict__ fcw, const float* __restrict__ fcb,
                const float* __restrict__ resid, float* __restrict__ out)
{
    constexpr int CH = 8;
    constexpr int NIN = 7;    // ceil(8*204/256)
    constexpr int NW  = 5;    // ceil(8*9*64/4/256)
    __shared__ __align__(16) char s_u[32768];
    ull   (*s_ind)[6][34] = (ull(*)[6][34])s_u;              // 13056 B
    float (*s_w)[9][64]   = (float(*)[9][64])(s_u + 13056);  // 18432 B
    float (*s_t)[128]     = (float(*)[128])s_u;              // 32768 B (phase 2)
    __shared__ __align__(16) float s_fcw[64][64];
    __shared__ float s_fcb[64];

    const int w0 = blockIdx.x*32, h0 = blockIdx.y*4;
    const int b  = blockIdx.z;
    const int tid = threadIdx.x;
    const int ocg = tid >> 5;
    const int px  = tid & 31;

    for (int i = tid; i < 4096; i += 256) {
        int ci = i >> 6, m = i & 63;
        s_fcw[ci][m] = fcw[m*64 + ci];
    }
    if (tid < 64) s_fcb[tid] = fcb[tid];

    float  rin[NIN];
    float4 rw[NW];
    {
        const int c0 = 0;
        #pragma unroll
        for (int k = 0; k < NIN; k++) {
            int i = tid + k*256;
            float v = 0.f;
            if (i < CH*204) {
                int ci = i / 204, rem = i % 204;
                int r = rem / 34, cc = rem % 34;
                int gh = h0 - 1 + r, gw = w0 - 1 + cc;
                if (gh >= 0 && gh < HH && gw >= 0 && gw < WW)
                    v = in[((size_t)(b*64 + c0 + ci))*HWSZ + gh*WW + gw];
            }
            rin[k] = v;
        }
        const float4* src = (const float4*)(wt_t + (size_t)c0*9*64);
        #pragma unroll
        for (int k = 0; k < NW; k++) {
            int i = tid + k*256;
            rw[k] = (i < CH*9*64/4) ? src[i] : make_float4(0.f,0.f,0.f,0.f);
        }
    }

    ull acc[4][4];
    #pragma unroll
    for (int i = 0; i < 4; i++)
        #pragma unroll
        for (int p = 0; p < 4; p++) acc[i][p] = 0ULL;

    for (int c0 = 0; c0 < 64; c0 += CH) {
        #pragma unroll
        for (int k = 0; k < NIN; k++) {
            int i = tid + k*256;
            if (i < CH*204) {
                int ci = i / 204, rem = i % 204;
                int r = rem / 34, cc = rem % 34;
                s_ind[ci][r][cc] = pk2(rin[k], rin[k]);
            }
        }
        {
            float4* dst = (float4*)&s_w[0][0][0];
            #pragma unroll
            for (int k = 0; k < NW; k++) {
                int i = tid + k*256;
                if (i < CH*9*64/4) dst[i] = rw[k];
            }
        }
        __syncthreads();

        if (c0 + CH < 64) {
            const int cn = c0 + CH;
            #pragma unroll
            for (int k = 0; k < NIN; k++) {
                int i = tid + k*256;
                float v = 0.f;
                if (i < CH*204) {
                    int ci = i / 204, rem = i % 204;
                    int r = rem / 34, cc = rem % 34;
                    int gh = h0 - 1 + r, gw = w0 - 1 + cc;
                    if (gh >= 0 && gh < HH && gw >= 0 && gw < WW)
                        v = in[((size_t)(b*64 + cn + ci))*HWSZ + gh*WW + gw];
                }
                rin[k] = v;
            }
            const float4* src = (const float4*)(wt_t + (size_t)cn*9*64);
            #pragma unroll
            for (int k = 0; k < NW; k++) {
                int i = tid + k*256;
                if (i < CH*9*64/4) rw[k] = src[i];
            }
        }

        #pragma unroll 1
        for (int ci = 0; ci < CH; ci++) {
            ull vd[6][3];
            #pragma unroll
            for (int r = 0; r < 6; r++)
                #pragma unroll
                for (int c = 0; c < 3; c++)
                    vd[r][c] = s_ind[ci][r][px + c];

            #pragma unroll
            for (int t = 0; t < 9; t++) {
                const int dr = t/3, dc = t%3;
                const ulonglong2* wp = (const ulonglong2*)&s_w[ci][t][ocg*8];
                ulonglong2 wa = wp[0], wb = wp[1];
                #pragma unroll
                for (int p = 0; p < 4; p++) {
                    ull v = vd[dr + p][dc];
                    acc[0][p] = f2fma(wa.x, v, acc[0][p]);
                    acc[1][p] = f2fma(wa.y, v, acc[1][p]);
                    acc[2][p] = f2fma(wb.x, v, acc[2][p]);
                    acc[3][p] = f2fma(wb.y, v, acc[3][p]);
                }
            }
        }
        __syncthreads();
    }

    #pragma unroll
    for (int mp = 0; mp < 4; mp++) {
        int oc = ocg*8 + 2*mp;
        float b0 = bias[oc], b1 = bias[oc+1];
        #pragma unroll
        for (int p = 0; p < 4; p++) {
            float olo, ohi;
            upk2(acc[mp][p], olo, ohi);
            s_t[oc  ][p*32 + px] = fmaxf(olo + b0, 0.f);
            s_t[oc+1][p*32 + px] = fmaxf(ohi + b1, 0.f);
        }
    }
    __syncthreads();

    const int mg2   = tid >> 5;
    const int mb2   = mg2*8;
    const int slot  = tid & 31;
    const int row   = slot >> 3;
    const int pcol  = (slot & 7) * 4;
    const int p0    = row*32 + pcol;

    ull facc[4][4];
    #pragma unroll
    for (int m = 0; m < 4; m++)
        #pragma unroll
        for (int p = 0; p < 4; p++) facc[m][p] = 0ULL;

    #pragma unroll 4
    for (int ci = 0; ci < 64; ci++) {
        float4 tv = *(const float4*)&s_t[ci][p0];
        ull xd0 = pk2(tv.x, tv.x);
        ull xd1 = pk2(tv.y, tv.y);
        ull xd2 = pk2(tv.z, tv.z);
        ull xd3 = pk2(tv.w, tv.w);
        const ulonglong2* wp = (const ulonglong2*)&s_fcw[ci][mb2];
        ulonglong2 wA = wp[0], wB = wp[1];
        facc[0][0]=f2fma(wA.x,xd0,facc[0][0]); facc[0][1]=f2fma(wA.x,xd1,facc[0][1]);
        facc[0][2]=f2fma(wA.x,xd2,facc[0][2]); facc[0][3]=f2fma(wA.x,xd3,facc[0][3]);
        facc[1][0]=f2fma(wA.y,xd0,facc[1][0]); facc[1][1]=f2fma(wA.y,xd1,facc[1][1]);
        facc[1][2]=f2fma(wA.y,xd2,facc[1][2]); facc[1][3]=f2fma(wA.y,xd3,facc[1][3]);
        facc[2][0]=f2fma(wB.x,xd0,facc[2][0]); facc[2][1]=f2fma(wB.x,xd1,facc[2][1]);
        facc[2][2]=f2fma(wB.x,xd2,facc[2][2]); facc[2][3]=f2fma(wB.x,xd3,facc[2][3]);
        facc[3][0]=f2fma(wB.y,xd0,facc[3][0]); facc[3][1]=f2fma(wB.y,xd1,facc[3][1]);
        facc[3][2]=f2fma(wB.y,xd2,facc[3][2]); facc[3][3]=f2fma(wB.y,xd3,facc[3][3]);
    }

    #pragma unroll
    for (int mp = 0; mp < 4; mp++) {
        int ch = mb2 + 2*mp;
        float b0 = s_fcb[ch], b1 = s_fcb[ch+1];
        size_t i0 = ((size_t)(b*64 + ch  ))*HWSZ + (size_t)(h0 + row)*WW + w0 + pcol;
        size_t i1 = i0 + HWSZ;
        float4 r0 = *(const float4*)&resid[i0];
        float4 r1 = *(const float4*)&resid[i1];
        float lo[4], hi[4];
        #pragma unroll
        for (int p = 0; p < 4; p++) {
            float alo, ahi;
            upk2(facc[mp][p], alo, ahi);
            lo[p] = alo + b0;
            hi[p] = ahi + b1;
        }
        float4 vlo = {lo[0]+r0.x, lo[1]+r0.y, lo[2]+r0.z, lo[3]+r0.w};
        float4 vhi = {hi[0]+r1.x, hi[1]+r1.y, hi[2]+r1.z, hi[3]+r1.w};
        *(float4*)&out[i0] = vlo;
        *(float4*)&out[i1] = vhi;
    }
}

// ---------------------------------------------------------------------------
extern "C" void kernel_launch(void* const* d_in, const int* in_sizes, int n_in,
                              void* d_out, int out_size)
{
    (void)in_sizes; (void)n_in; (void)out_size;
    const float* x     = (const float*)d_in[0];
    const float* ba_w1 = (const float*)d_in[1];
    const float* ba_b1 = (const float*)d_in[2];
    const float* ba_w2 = (const float*)d_in[3];
    const float* ba_b2 = (const float*)d_in[4];
    // d_in[5..12]: offset branch — dead code in the reference, skipped.
    const float* rk5w  = (const float*)d_in[13];
    const float* rk5b  = (const float*)d_in[14];
    const float* rk7w  = (const float*)d_in[15];
    const float* rk7b  = (const float*)d_in[16];
    const float* lk5w  = (const float*)d_in[17];
    const float* lk5b  = (const float*)d_in[18];
    const float* lk7w  = (const float*)d_in[19];
    const float* lk7b  = (const float*)d_in[20];
    const float* sfw   = (const float*)d_in[21];
    const float* sfb   = (const float*)d_in[22];
    const float* sfg   = (const float*)d_in[23];
    const float* sfbb  = (const float*)d_in[24];
    const float* sfm   = (const float*)d_in[25];
    const float* sfv   = (const float*)d_in[26];
    const float* fcw   = (const float*)d_in[27];
    const float* fcb   = (const float*)d_in[28];
    float* out = (float*)d_out;

    float *pFus, *pWeff, *pBeff, *pW1t, *pW2t, *pB2;
    cudaGetSymbolAddress((void**)&pFus,  g_fusion);
    cudaGetSymbolAddress((void**)&pWeff, g_Weff);
    cudaGetSymbolAddress((void**)&pBeff, g_beff);
    cudaGetSymbolAddress((void**)&pW1t,  g_w1t);
    cudaGetSymbolAddress((void**)&pW2t,  g_w2t);
    cudaGetSymbolAddress((void**)&pB2,   g_b2);

    build_weff<<<16, 256>>>(rk5w, rk5b, rk7w, rk7b, lk5w, lk5b, lk7w, lk7b);
    prep_w<<<144, 256>>>(ba_w1, sfw, sfb, sfg, sfbb, sfm, sfv);

    conv32_edge_k<<<dim3(WW/32, HH/8, BB), 256>>>(x, pW1t, ba_b1, ba_w2, ba_b2);
    fusion_k<<<dim3(HWSZ/256, 2, BB), 256>>>(x, pWeff, pBeff, pFus);
    conv64fc_k<<<dim3(WW/32, HH/4, BB), 256>>>(pFus, pW2t, pB2, fcw, fcb, x, out);
}

// round 10
// speedup vs baseline: 2.5080x; 1.2609x over previous
#include <cuda_runtime.h>
#include <cuda_bf16.h>
#include <cstdint>
#include <cstddef>

#define BB 4
#define HH 160
#define WW 160
#define HWSZ (HH*WW)

typedef unsigned long long ull;

// ---------------- packed f32x2 helpers (fp32 kernels) ----------------------
__device__ __forceinline__ ull pk2(float lo, float hi) {
    ull r; asm("mov.b64 %0,{%1,%2};" : "=l"(r) : "f"(lo), "f"(hi)); return r;
}
__device__ __forceinline__ void upk2(ull v, float& lo, float& hi) {
    asm("mov.b64 {%0,%1},%2;" : "=f"(lo), "=f"(hi) : "l"(v));
}
__device__ __forceinline__ float lo2(ull v) {
    float a, b; upk2(v, a, b); return a;
}
__device__ __forceinline__ ull f2fma(ull a, ull b, ull c) {
    ull d; asm("fma.rn.f32x2 %0,%1,%2,%3;" : "=l"(d) : "l"(a), "l"(b), "l"(c)); return d;
}

// ---------------- bf16 mma.sync helpers ------------------------------------
__device__ __forceinline__ void mma_bf16(float d[4], const uint32_t a[4],
                                         uint32_t b0, uint32_t b1) {
    asm volatile(
        "mma.sync.aligned.m16n8k16.row.col.f32.bf16.bf16.f32 "
        "{%0,%1,%2,%3}, {%4,%5,%6,%7}, {%8,%9}, {%0,%1,%2,%3};"
        : "+f"(d[0]), "+f"(d[1]), "+f"(d[2]), "+f"(d[3])
        : "r"(a[0]), "r"(a[1]), "r"(a[2]), "r"(a[3]), "r"(b0), "r"(b1));
}
__device__ __forceinline__ uint32_t bfpack2(float x, float y) {
    __nv_bfloat162 h = __halves2bfloat162(__float2bfloat16(x), __float2bfloat16(y));
    return *(uint32_t*)&h;
}

// ---------------- scratch (device globals; no allocation allowed) ----------
__device__ __align__(128) float g_gmap[BB*HWSZ];
__device__ __align__(128) float g_smap[BB*HWSZ];
__device__ __align__(128) float g_fusion[BB*64*HWSZ];
__device__ __align__(128) float g_Weff[64*64];
__device__ __align__(128) float g_beff[64];
__device__ __align__(128) float g_w1t[64*9*32];   // [ci][tap][oc]
__device__ __align__(128) float g_b2[64];         // BN-folded bias
__device__ __align__(128) uint4 g_wf[9216];       // conv weight frags [t][kh][ks][nt][lane]
__device__ __align__(128) uint4 g_fcf[1024];      // fc weight frags [ks][nt][lane]

// ---------------- K0a: effective dyn1d weights (sum over K) ----------------
__global__ void build_weff(const float* __restrict__ rk5w, const float* __restrict__ rk5b,
                           const float* __restrict__ rk7w, const float* __restrict__ rk7b,
                           const float* __restrict__ lk5w, const float* __restrict__ lk5b,
                           const float* __restrict__ lk7w, const float* __restrict__ lk7b)
{
    int id = blockIdx.x*blockDim.x + threadIdx.x;
    if (id >= 64*64) return;
    int m = id >> 6, c = id & 63;
    const float* w; const float* bs; int K, o;
    if      (m < 16) { w = rk5w; bs = rk5b; K = 5; o = m;    }
    else if (m < 32) { w = rk7w; bs = rk7b; K = 7; o = m-16; }
    else if (m < 48) { w = lk5w; bs = lk5b; K = 5; o = m-32; }
    else             { w = lk7w; bs = lk7b; K = 7; o = m-48; }
    float acc = 0.f;
    for (int k = 0; k < K; k++) acc += w[(o*K + k)*64 + c];
    g_Weff[m*64 + c] = acc;
    if (c == 0) {
        float bacc = 0.f;
        for (int k = 0; k < K; k++) bacc += bs[o*K + k];
        g_beff[m] = bacc;
    }
}

// ---------------- K0b: transpose conv1 weights + fold BN bias --------------
__global__ void prep_w(const float* __restrict__ w1, const float* __restrict__ b2s,
                       const float* __restrict__ bg, const float* __restrict__ bbta,
                       const float* __restrict__ bm, const float* __restrict__ bv)
{
    int id = blockIdx.x*blockDim.x + threadIdx.x;
    if (id < 64*9*32) {
        int ci = id/(9*32); int rem = id%(9*32); int t = rem/32; int oc = rem%32;
        g_w1t[id] = w1[(oc*64 + ci)*9 + t];
    }
    if (id < 64) {
        float scc = bg[id] * rsqrtf(bv[id] + 1e-5f);
        g_b2[id] = b2s[id]*scc + bbta[id] - bm[id]*scc;
    }
}

// ---------------- K0c: pack mma B-fragments (hi/lo split, BN folded) -------
__global__ void prep_frag(const float* __restrict__ sfw, const float* __restrict__ bg,
                          const float* __restrict__ bv, const float* __restrict__ fcw)
{
    int id = blockIdx.x*blockDim.x + threadIdx.x;
    if (id < 9216) {
        int lane = id & 31; int rem = id >> 5;
        int nt = rem & 7; rem >>= 3;
        int ks = rem & 1; rem >>= 1;
        int kh = rem & 1; int t = rem >> 1;
        int n  = nt*8 + (lane >> 2);
        int k0 = kh*32 + ks*16 + (lane & 3)*2;
        float sc = bg[n] * rsqrtf(bv[n] + 1e-5f);
        float w00 = sfw[(n*64 + k0    )*9 + t] * sc;
        float w01 = sfw[(n*64 + k0 + 1)*9 + t] * sc;
        float w08 = sfw[(n*64 + k0 + 8)*9 + t] * sc;
        float w09 = sfw[(n*64 + k0 + 9)*9 + t] * sc;
        __nv_bfloat16 h00 = __float2bfloat16(w00), h01 = __float2bfloat16(w01);
        __nv_bfloat16 h08 = __float2bfloat16(w08), h09 = __float2bfloat16(w09);
        uint4 rec;
        rec.x = bfpack2(w00, w01);  // hi pair uses rn of w; recompute consistently:
        rec.x = (uint32_t)(*(uint16_t*)&h00) | ((uint32_t)(*(uint16_t*)&h01) << 16);
        rec.y = (uint32_t)(*(uint16_t*)&h08) | ((uint32_t)(*(uint16_t*)&h09) << 16);
        rec.z = bfpack2(w00 - __bfloat162float(h00), w01 - __bfloat162float(h01));
        rec.w = bfpack2(w08 - __bfloat162float(h08), w09 - __bfloat162float(h09));
        g_wf[id] = rec;
    } else if (id < 10240) {
        int fid = id - 9216;
        int lane = fid & 31; int rem = fid >> 5;
        int nt = rem & 7; int ks = rem >> 3;
        int n  = nt*8 + (lane >> 2);
        int k0 = ks*16 + (lane & 3)*2;
        float w00 = fcw[n*64 + k0    ];
        float w01 = fcw[n*64 + k0 + 1];
        float w08 = fcw[n*64 + k0 + 8];
        float w09 = fcw[n*64 + k0 + 9];
        __nv_bfloat16 h00 = __float2bfloat16(w00), h01 = __float2bfloat16(w01);
        __nv_bfloat16 h08 = __float2bfloat16(w08), h09 = __float2bfloat16(w09);
        uint4 rec;
        rec.x = (uint32_t)(*(uint16_t*)&h00) | ((uint32_t)(*(uint16_t*)&h01) << 16);
        rec.y = (uint32_t)(*(uint16_t*)&h08) | ((uint32_t)(*(uint16_t*)&h09) << 16);
        rec.z = bfpack2(w00 - __bfloat162float(h00), w01 - __bfloat162float(h01));
        rec.w = bfpack2(w08 - __bfloat162float(h08), w09 - __bfloat162float(h09));
        g_fcf[fid] = rec;
    }
}

// ---------------- K1: fused conv3x3<32> + sobel edge + attention -----------
// (unchanged from R8 — known good)
__global__ __launch_bounds__(256)
void conv32_edge_k(const float* __restrict__ in, const float* __restrict__ wt_t,
                   const float* __restrict__ bias,
                   const float* __restrict__ baw2, const float* __restrict__ bab2)
{
    constexpr int CH = 8;
    constexpr int NIN = 11;
    constexpr int NW  = 3;
    __shared__ ull s_ind[CH][10][34];
    __shared__ __align__(16) float s_w[CH][9][32];
    __shared__ float s_att[4][64][4];
    __shared__ float s_edge[4][64][4];
    __shared__ float s_sum[4][64][4];
    __shared__ float s_b1[32], s_w2[32];

    const int w0 = blockIdx.x*32, h0 = blockIdx.y*8;
    const int b  = blockIdx.z;
    const int tid = threadIdx.x;
    const int ocg = tid >> 6;
    const int pt  = tid & 63;
    const int px  = pt & 31;
    const int py0 = (pt >> 5) * 4;

    if (tid < 32) { s_b1[tid] = bias[tid]; s_w2[tid] = baw2[tid]; }

    float  rin[NIN];
    float4 rw[NW];
    {
        const int c0 = 0;
        #pragma unroll
        for (int k = 0; k < NIN; k++) {
            int i = tid + k*256;
            float v = 0.f;
            if (i < CH*340) {
                int ci = i / 340, rem = i % 340;
                int r = rem / 34, cc = rem % 34;
                int gh = h0 - 1 + r, gw = w0 - 1 + cc;
                if (gh >= 0 && gh < HH && gw >= 0 && gw < WW)
                    v = in[((size_t)(b*64 + c0 + ci))*HWSZ + gh*WW + gw];
            }
            rin[k] = v;
        }
        const float4* src = (const float4*)(wt_t + (size_t)c0*9*32);
        #pragma unroll
        for (int k = 0; k < NW; k++) {
            int i = tid + k*256;
            rw[k] = (i < CH*9*32/4) ? src[i] : make_float4(0.f,0.f,0.f,0.f);
        }
    }

    ull acc[4][4];
    #pragma unroll
    for (int i = 0; i < 4; i++)
        #pragma unroll
        for (int p = 0; p < 4; p++) acc[i][p] = 0ULL;
    float edge[4] = {0.f,0.f,0.f,0.f};
    float sumx[4] = {0.f,0.f,0.f,0.f};

    for (int c0 = 0; c0 < 64; c0 += CH) {
        #pragma unroll
        for (int k = 0; k < NIN; k++) {
            int i = tid + k*256;
            if (i < CH*340) {
                int ci = i / 340, rem = i % 340;
                int r = rem / 34, cc = rem % 34;
                s_ind[ci][r][cc] = pk2(rin[k], rin[k]);
            }
        }
        {
            float4* dst = (float4*)&s_w[0][0][0];
            #pragma unroll
            for (int k = 0; k < NW; k++) {
                int i = tid + k*256;
                if (i < CH*9*32/4) dst[i] = rw[k];
            }
        }
        __syncthreads();

        if (c0 + CH < 64) {
            const int cn = c0 + CH;
            #pragma unroll
            for (int k = 0; k < NIN; k++) {
                int i = tid + k*256;
                float v = 0.f;
                if (i < CH*340) {
                    int ci = i / 340, rem = i % 340;
                    int r = rem / 34, cc = rem % 34;
                    int gh = h0 - 1 + r, gw = w0 - 1 + cc;
                    if (gh >= 0 && gh < HH && gw >= 0 && gw < WW)
                        v = in[((size_t)(b*64 + cn + ci))*HWSZ + gh*WW + gw];
                }
                rin[k] = v;
            }
            const float4* src = (const float4*)(wt_t + (size_t)cn*9*32);
            #pragma unroll
            for (int k = 0; k < NW; k++) {
                int i = tid + k*256;
                if (i < CH*9*32/4) rw[k] = src[i];
            }
        }

        #pragma unroll 1
        for (int ci = 0; ci < CH; ci++) {
            ull vd[6][3];
            #pragma unroll
            for (int r = 0; r < 6; r++)
                #pragma unroll
                for (int c = 0; c < 3; c++)
                    vd[r][c] = s_ind[ci][py0 + r][px + c];

            if ((ci & 3) == ocg) {
                #pragma unroll
                for (int j = 0; j < 4; j++) {
                    float a00=lo2(vd[j  ][0]), a01=lo2(vd[j  ][1]), a02=lo2(vd[j  ][2]);
                    float a10=lo2(vd[j+1][0]), a11=lo2(vd[j+1][1]), a12=lo2(vd[j+1][2]);
                    float a20=lo2(vd[j+2][0]), a21=lo2(vd[j+2][1]), a22=lo2(vd[j+2][2]);
                    sumx[j] += a11;
                    if (c0 < 32) {
                        float gx = (a02 - a00) + 2.f*(a12 - a10) + (a22 - a20);
                        edge[j] += fabsf(gx);
                    } else {
                        float gy = (a20 - a00) + 2.f*(a21 - a01) + (a22 - a02);
                        edge[j] += fabsf(gy);
                    }
                }
            }

            #pragma unroll
            for (int t = 0; t < 9; t++) {
                const int dr = t/3, dc = t%3;
                const ulonglong2* wp = (const ulonglong2*)&s_w[ci][t][ocg*8];
                ulonglong2 wa = wp[0], wb = wp[1];
                #pragma unroll
                for (int p = 0; p < 4; p++) {
                    ull v = vd[dr + p][dc];
                    acc[0][p] = f2fma(wa.x, v, acc[0][p]);
                    acc[1][p] = f2fma(wa.y, v, acc[1][p]);
                    acc[2][p] = f2fma(wb.x, v, acc[2][p]);
                    acc[3][p] = f2fma(wb.y, v, acc[3][p]);
                }
            }
        }
        __syncthreads();
    }

    float attp[4] = {0.f,0.f,0.f,0.f};
    #pragma unroll
    for (int mp = 0; mp < 4; mp++) {
        int oc = ocg*8 + 2*mp;
        float b0v = s_b1[oc], b1v = s_b1[oc+1];
        float w0v = s_w2[oc], w1v = s_w2[oc+1];
        #pragma unroll
        for (int p = 0; p < 4; p++) {
            float alo, ahi;
            upk2(acc[mp][p], alo, ahi);
            attp[p] += w0v*fmaxf(alo + b0v, 0.f) + w1v*fmaxf(ahi + b1v, 0.f);
        }
    }
    #pragma unroll
    for (int p = 0; p < 4; p++) {
        s_att [ocg][pt][p] = attp[p];
        s_edge[ocg][pt][p] = edge[p];
        s_sum [ocg][pt][p] = sumx[p];
    }
    __syncthreads();

    if (ocg == 0) {
        float bb = bab2[0];
        #pragma unroll
        for (int p = 0; p < 4; p++) {
            float att = bb, ed = 0.f, sx = 0.f;
            #pragma unroll
            for (int g = 0; g < 4; g++) {
                att += s_att[g][pt][p];
                ed  += s_edge[g][pt][p];
                sx  += s_sum[g][pt][p];
            }
            float z = att + ed*(1.f/32.f);
            float a = 1.f / (1.f + expf(-z));
            float gv = 1.f + a;
            size_t pix = (size_t)b*HWSZ + (size_t)(h0 + py0 + p)*WW + (w0 + px);
            g_gmap[pix] = gv;
            g_smap[pix] = gv * sx;
        }
    }
}

// ---------------- K3: fusion GEMM, m-split, prefetched loads (unchanged) ---
__global__ __launch_bounds__(256)
void fusion_k(const float* __restrict__ in, const float* __restrict__ wsrc,
              const float* __restrict__ bsrc, float* __restrict__ outp)
{
    __shared__ __align__(16) float s_w[64][32];
    __shared__ float s_b[32];
    const int tid = threadIdx.x;
    const int ms  = blockIdx.y;
    const int b   = blockIdx.z;
    for (int i = tid; i < 2048; i += 256) {
        int ci = i >> 5, m = i & 31;
        s_w[ci][m] = wsrc[(ms*32 + m)*64 + ci];
    }
    if (tid < 32) s_b[tid] = bsrc[ms*32 + tid];
    __syncthreads();

    const int mg    = tid >> 6;
    const int mbase = mg*8;
    const int slot  = tid & 63;
    const int pix   = blockIdx.x*256 + slot*4;
    const float* basep = in + (size_t)b*64*HWSZ + pix;

    ull acc[4][4];
    #pragma unroll
    for (int m = 0; m < 4; m++)
        #pragma unroll
        for (int p = 0; p < 4; p++) acc[m][p] = 0ULL;

    float4 xv[4];
    #pragma unroll
    for (int j = 0; j < 4; j++)
        xv[j] = *(const float4*)(basep + (size_t)j*HWSZ);

    #pragma unroll 1
    for (int c4 = 0; c4 < 16; c4++) {
        float4 xn[4];
        if (c4 < 15) {
            const float* bp = basep + (size_t)(c4+1)*4*HWSZ;
            #pragma unroll
            for (int j = 0; j < 4; j++)
                xn[j] = *(const float4*)(bp + (size_t)j*HWSZ);
        }
        #pragma unroll
        for (int j = 0; j < 4; j++) {
            ull xd0 = pk2(xv[j].x, xv[j].x);
            ull xd1 = pk2(xv[j].y, xv[j].y);
            ull xd2 = pk2(xv[j].z, xv[j].z);
            ull xd3 = pk2(xv[j].w, xv[j].w);
            const ulonglong2* wp = (const ulonglong2*)&s_w[c4*4 + j][mbase];
            ulonglong2 wA = wp[0], wB = wp[1];
            acc[0][0]=f2fma(wA.x,xd0,acc[0][0]); acc[0][1]=f2fma(wA.x,xd1,acc[0][1]);
            acc[0][2]=f2fma(wA.x,xd2,acc[0][2]); acc[0][3]=f2fma(wA.x,xd3,acc[0][3]);
            acc[1][0]=f2fma(wA.y,xd0,acc[1][0]); acc[1][1]=f2fma(wA.y,xd1,acc[1][1]);
            acc[1][2]=f2fma(wA.y,xd2,acc[1][2]); acc[1][3]=f2fma(wA.y,xd3,acc[1][3]);
            acc[2][0]=f2fma(wB.x,xd0,acc[2][0]); acc[2][1]=f2fma(wB.x,xd1,acc[2][1]);
            acc[2][2]=f2fma(wB.x,xd2,acc[2][2]); acc[2][3]=f2fma(wB.x,xd3,acc[2][3]);
            acc[3][0]=f2fma(wB.y,xd0,acc[3][0]); acc[3][1]=f2fma(wB.y,xd1,acc[3][1]);
            acc[3][2]=f2fma(wB.y,xd2,acc[3][2]); acc[3][3]=f2fma(wB.y,xd3,acc[3][3]);
        }
        if (c4 < 15) {
            #pragma unroll
            for (int j = 0; j < 4; j++) xv[j] = xn[j];
        }
    }

    float4 gv = *(const float4*)&g_gmap[(size_t)b*HWSZ + pix];
    float4 sv = *(const float4*)&g_smap[(size_t)b*HWSZ + pix];
    float gs[4] = {gv.x, gv.y, gv.z, gv.w};
    float ss[4] = {sv.x, sv.y, sv.z, sv.w};
    #pragma unroll
    for (int mp = 0; mp < 4; mp++) {
        int ch = ms*32 + mbase + 2*mp;
        float b0 = s_b[mbase + 2*mp], b1 = s_b[mbase + 2*mp + 1];
        float lo[4], hi[4];
        #pragma unroll
        for (int p = 0; p < 4; p++) {
            float alo, ahi;
            upk2(acc[mp][p], alo, ahi);
            lo[p] = ss[p] * (gs[p]*alo + b0);
            hi[p] = ss[p] * (gs[p]*ahi + b1);
        }
        float4 vlo = {lo[0], lo[1], lo[2], lo[3]};
        float4 vhi = {hi[0], hi[1], hi[2], hi[3]};
        *(float4*)&outp[((size_t)(b*64 + ch  ))*HWSZ + pix] = vlo;
        *(float4*)&outp[((size_t)(b*64 + ch+1))*HWSZ + pix] = vhi;
    }
}

// ---------------- K4: conv3x3<64> + fc + residual via bf16 mma.sync --------
// Block = 32w x 4h px tile (M=128), N=64 oc, 256 thr = 8 warps.
// Warp w owns M-rows w*16..w*16+15. hi/lo split, 3 mma per product.
__global__ __launch_bounds__(256)
void conv64fc_mma(const float* __restrict__ fus,
                  const uint4* __restrict__ wf, const float* __restrict__ b2,
                  const uint4* __restrict__ fcf, const float* __restrict__ fcb,
                  const float* __restrict__ resid, float* __restrict__ out)
{
    __shared__ __align__(16) uint16_t s_buf[2*128*68];   // 34816 B (conv uses 26112)
    __shared__ float s_b2[64], s_fcb[64];

    const int tid = threadIdx.x;
    const int wid = tid >> 5, lane = tid & 31;
    const int g = lane >> 2, t2 = (lane & 3) * 2;
    const int b  = blockIdx.z;
    const int w0 = blockIdx.x*32, h0 = blockIdx.y*4;

    if (tid < 64) { s_b2[tid] = b2[tid]; s_fcb[tid] = fcb[tid]; }

    uint16_t* s_hi = s_buf;          // [6][34][32] bf16
    uint16_t* s_lo = s_buf + 6528;

    const int m0 = wid*16 + g, m1 = m0 + 8;
    const int ph0 = m0 >> 5, pw0 = m0 & 31;
    const int ph1 = m1 >> 5, pw1 = m1 & 31;

    float d[8][4];
    #pragma unroll
    for (int nt = 0; nt < 8; nt++)
        #pragma unroll
        for (int i = 0; i < 4; i++) d[nt][i] = 0.f;

    for (int kh = 0; kh < 2; kh++) {
        if (kh) __syncthreads();
        // stage halo k-half: fp32 -> bf16 hi/lo planes
        #pragma unroll
        for (int it = 0; it < 13; it++) {
            int idx = tid + it*256;
            if (idx < 3264) {
                int hw = idx >> 4, cp = idx & 15;
                int h = hw / 34, w = hw % 34;
                int gh = h0 - 1 + h, gw = w0 - 1 + w;
                bool inb = (gh >= 0 && gh < HH && gw >= 0 && gw < WW);
                int ci = kh*32 + cp*2;
                const float* fp = fus + ((size_t)(b*64 + ci))*HWSZ + (inb ? gh*WW + gw : 0);
                float v0 = inb ? fp[0] : 0.f;
                float v1 = inb ? fp[HWSZ] : 0.f;
                __nv_bfloat16 h0b = __float2bfloat16(v0);
                __nv_bfloat16 h1b = __float2bfloat16(v1);
                uint32_t hiw = (uint32_t)(*(uint16_t*)&h0b) | ((uint32_t)(*(uint16_t*)&h1b) << 16);
                uint32_t low = bfpack2(v0 - __bfloat162float(h0b), v1 - __bfloat162float(h1b));
                *(uint32_t*)&s_hi[hw*32 + cp*2] = hiw;
                *(uint32_t*)&s_lo[hw*32 + cp*2] = low;
            }
        }
        __syncthreads();

        for (int t = 0; t < 9; t++) {
            const int dr = t/3, dc = t%3;
            const int r0 = ((ph0 + dr)*34 + pw0 + dc)*32;
            const int r1 = ((ph1 + dr)*34 + pw1 + dc)*32;
            #pragma unroll
            for (int ks = 0; ks < 2; ks++) {
                uint4 bfr[8];
                const uint4* wp = wf + (size_t)(((t*2 + kh)*2 + ks)*8)*32 + lane;
                #pragma unroll
                for (int nt = 0; nt < 8; nt++) bfr[nt] = wp[nt*32];

                const int k = ks*16 + t2;
                uint32_t ah[4], al[4];
                ah[0] = *(const uint32_t*)&s_hi[r0 + k];
                ah[1] = *(const uint32_t*)&s_hi[r1 + k];
                ah[2] = *(const uint32_t*)&s_hi[r0 + k + 8];
                ah[3] = *(const uint32_t*)&s_hi[r1 + k + 8];
                al[0] = *(const uint32_t*)&s_lo[r0 + k];
                al[1] = *(const uint32_t*)&s_lo[r1 + k];
                al[2] = *(const uint32_t*)&s_lo[r0 + k + 8];
                al[3] = *(const uint32_t*)&s_lo[r1 + k + 8];

                #pragma unroll
                for (int nt = 0; nt < 8; nt++) {
                    mma_bf16(d[nt], ah, bfr[nt].x, bfr[nt].y);   // ah * bh
                    mma_bf16(d[nt], al, bfr[nt].x, bfr[nt].y);   // al * bh
                    mma_bf16(d[nt], ah, bfr[nt].z, bfr[nt].w);   // ah * bl
                }
            }
        }
    }
    __syncthreads();   // all halo reads done before aliasing with fc A

    // fc A = relu(conv + bias) -> [128][68] bf16 hi/lo (padded rows)
    uint16_t* f_hi = s_buf;
    uint16_t* f_lo = s_buf + 128*68;
    #pragma unroll
    for (int nt = 0; nt < 8; nt++) {
        int oc = nt*8 + t2;
        float b0v = s_b2[oc], b1v = s_b2[oc+1];
        float v00 = fmaxf(d[nt][0] + b0v, 0.f);
        float v01 = fmaxf(d[nt][1] + b1v, 0.f);
        float v10 = fmaxf(d[nt][2] + b0v, 0.f);
        float v11 = fmaxf(d[nt][3] + b1v, 0.f);
        __nv_bfloat16 h00 = __float2bfloat16(v00), h01 = __float2bfloat16(v01);
        __nv_bfloat16 h10 = __float2bfloat16(v10), h11 = __float2bfloat16(v11);
        *(uint32_t*)&f_hi[m0*68 + oc] =
            (uint32_t)(*(uint16_t*)&h00) | ((uint32_t)(*(uint16_t*)&h01) << 16);
        *(uint32_t*)&f_hi[m1*68 + oc] =
            (uint32_t)(*(uint16_t*)&h10) | ((uint32_t)(*(uint16_t*)&h11) << 16);
        *(uint32_t*)&f_lo[m0*68 + oc] =
            bfpack2(v00 - __bfloat162float(h00), v01 - __bfloat162float(h01));
        *(uint32_t*)&f_lo[m1*68 + oc] =
            bfpack2(v10 - __bfloat162float(h10), v11 - __bfloat162float(h11));
    }
    __syncthreads();

    float e[8][4];
    #pragma unroll
    for (int nt = 0; nt < 8; nt++)
        #pragma unroll
        for (int i = 0; i < 4; i++) e[nt][i] = 0.f;

    #pragma unroll
    for (int ks = 0; ks < 4; ks++) {
        uint4 bfr[8];
        const uint4* wp = fcf + (ks*8)*32 + lane;
        #pragma unroll
        for (int nt = 0; nt < 8; nt++) bfr[nt] = wp[nt*32];

        const int k = ks*16 + t2;
        uint32_t ah[4], al[4];
        ah[0] = *(const uint32_t*)&f_hi[m0*68 + k];
        ah[1] = *(const uint32_t*)&f_hi[m1*68 + k];
        ah[2] = *(const uint32_t*)&f_hi[m0*68 + k + 8];
        ah[3] = *(const uint32_t*)&f_hi[m1*68 + k + 8];
        al[0] = *(const uint32_t*)&f_lo[m0*68 + k];
        al[1] = *(const uint32_t*)&f_lo[m1*68 + k];
        al[2] = *(const uint32_t*)&f_lo[m0*68 + k + 8];
        al[3] = *(const uint32_t*)&f_lo[m1*68 + k + 8];

        #pragma unroll
        for (int nt = 0; nt < 8; nt++) {
            mma_bf16(e[nt], ah, bfr[nt].x, bfr[nt].y);
            mma_bf16(e[nt], al, bfr[nt].x, bfr[nt].y);
            mma_bf16(e[nt], ah, bfr[nt].z, bfr[nt].w);
        }
    }

    // epilogue: + fc bias + residual
    const size_t base = (size_t)b*64*HWSZ;
    const int p0 = (h0 + ph0)*WW + w0 + pw0;
    const int p1 = (h0 + ph1)*WW + w0 + pw1;
    #pragma unroll
    for (int nt = 0; nt < 8; nt++) {
        int oc = nt*8 + t2;
        size_t i00 = base + (size_t)oc*HWSZ + p0;
        size_t i01 = i00 + HWSZ;
        size_t i10 = base + (size_t)oc*HWSZ + p1;
        size_t i11 = i10 + HWSZ;
        out[i00] = e[nt][0] + s_fcb[oc]   + resid[i00];
        out[i01] = e[nt][1] + s_fcb[oc+1] + resid[i01];
        out[i10] = e[nt][2] + s_fcb[oc]   + resid[i10];
        out[i11] = e[nt][3] + s_fcb[oc+1] + resid[i11];
    }
}

// ---------------------------------------------------------------------------
extern "C" void kernel_launch(void* const* d_in, const int* in_sizes, int n_in,
                              void* d_out, int out_size)
{
    (void)in_sizes; (void)n_in; (void)out_size;
    const float* x     = (const float*)d_in[0];
    const float* ba_w1 = (const float*)d_in[1];
    const float* ba_b1 = (const float*)d_in[2];
    const float* ba_w2 = (const float*)d_in[3];
    const float* ba_b2 = (const float*)d_in[4];
    // d_in[5..12]: offset branch — dead code in the reference, skipped.
    const float* rk5w  = (const float*)d_in[13];
    const float* rk5b  = (const float*)d_in[14];
    const float* rk7w  = (const float*)d_in[15];
    const float* rk7b  = (const float*)d_in[16];
    const float* lk5w  = (const float*)d_in[17];
    const float* lk5b  = (const float*)d_in[18];
    const float* lk7w  = (const float*)d_in[19];
    const float* lk7b  = (const float*)d_in[20];
    const float* sfw   = (const float*)d_in[21];
    const float* sfb   = (const float*)d_in[22];
    const float* sfg   = (const float*)d_in[23];
    const float* sfbb  = (const float*)d_in[24];
    const float* sfm   = (const float*)d_in[25];
    const float* sfv   = (const float*)d_in[26];
    const float* fcw   = (const float*)d_in[27];
    const float* fcb   = (const float*)d_in[28];
    float* out = (float*)d_out;

    float *pFus, *pWeff, *pBeff, *pW1t, *pB2;
    uint4 *pWf, *pFcf;
    cudaGetSymbolAddress((void**)&pFus,  g_fusion);
    cudaGetSymbolAddress((void**)&pWeff, g_Weff);
    cudaGetSymbolAddress((void**)&pBeff, g_beff);
    cudaGetSymbolAddress((void**)&pW1t,  g_w1t);
    cudaGetSymbolAddress((void**)&pB2,   g_b2);
    cudaGetSymbolAddress((void**)&pWf,   g_wf);
    cudaGetSymbolAddress((void**)&pFcf,  g_fcf);

    build_weff<<<16, 256>>>(rk5w, rk5b, rk7w, rk7b, lk5w, lk5b, lk7w, lk7b);
    prep_w<<<72, 256>>>(ba_w1, sfb, sfg, sfbb, sfm, sfv);
    prep_frag<<<40, 256>>>(sfw, sfg, sfv, fcw);

    conv32_edge_k<<<dim3(WW/32, HH/8, BB), 256>>>(x, pW1t, ba_b1, ba_w2, ba_b2);
    fusion_k<<<dim3(HWSZ/256, 2, BB), 256>>>(x, pWeff, pBeff, pFus);
    conv64fc_mma<<<dim3(WW/32, HH/4, BB), 256>>>(pFus, pWf, pB2, pFcf, fcb, x, out);
}

// round 11
// speedup vs baseline: 2.6639x; 1.0622x over previous
#include <cuda_runtime.h>
#include <cuda_bf16.h>
#include <cstdint>
#include <cstddef>

#define BB 4
#define HH 160
#define WW 160
#define HWSZ (HH*WW)

typedef unsigned long long ull;

// ---------------- packed f32x2 helpers (fp32 kernels) ----------------------
__device__ __forceinline__ ull pk2(float lo, float hi) {
    ull r; asm("mov.b64 %0,{%1,%2};" : "=l"(r) : "f"(lo), "f"(hi)); return r;
}
__device__ __forceinline__ void upk2(ull v, float& lo, float& hi) {
    asm("mov.b64 {%0,%1},%2;" : "=f"(lo), "=f"(hi) : "l"(v));
}
__device__ __forceinline__ ull f2fma(ull a, ull b, ull c) {
    ull d; asm("fma.rn.f32x2 %0,%1,%2,%3;" : "=l"(d) : "l"(a), "l"(b), "l"(c)); return d;
}

// ---------------- bf16 mma.sync helpers ------------------------------------
__device__ __forceinline__ void mma_bf16(float d[4], const uint32_t a[4],
                                         uint32_t b0, uint32_t b1) {
    asm volatile(
        "mma.sync.aligned.m16n8k16.row.col.f32.bf16.bf16.f32 "
        "{%0,%1,%2,%3}, {%4,%5,%6,%7}, {%8,%9}, {%0,%1,%2,%3};"
        : "+f"(d[0]), "+f"(d[1]), "+f"(d[2]), "+f"(d[3])
        : "r"(a[0]), "r"(a[1]), "r"(a[2]), "r"(a[3]), "r"(b0), "r"(b1));
}
__device__ __forceinline__ uint32_t bfpack2(float x, float y) {
    __nv_bfloat162 h = __halves2bfloat162(__float2bfloat16(x), __float2bfloat16(y));
    return *(uint32_t*)&h;
}
__device__ __forceinline__ float bfunp_lo(uint32_t v) {
    __nv_bfloat162 h = *(__nv_bfloat162*)&v;
    return __bfloat162float(__low2bfloat16(h));
}
__device__ __forceinline__ float bfunp_hi(uint32_t v) {
    __nv_bfloat162 h = *(__nv_bfloat162*)&v;
    return __bfloat162float(__high2bfloat16(h));
}

// ---------------- scratch (device globals; no allocation allowed) ----------
__device__ __align__(128) float g_gmap[BB*HWSZ];
__device__ __align__(128) float g_smap[BB*HWSZ];
__device__ __align__(128) float g_fusion[BB*64*HWSZ];
__device__ __align__(128) float g_Weff[64*64];
__device__ __align__(128) float g_beff[64];
__device__ __align__(128) float g_b2[64];         // BN-folded bias
__device__ __align__(128) uint4 g_wf[9216];       // conv64 frags [t][kh][ks][nt8][lane]
__device__ __align__(128) uint4 g_fcf[1024];      // fc frags [ks][nt8][lane]
__device__ __align__(128) uint4 g_wf1[4608];      // conv32 frags [t][kh][ks][nt4][lane]

// ---------------- K0a: effective dyn1d weights (sum over K) ----------------
__global__ void build_weff(const float* __restrict__ rk5w, const float* __restrict__ rk5b,
                           const float* __restrict__ rk7w, const float* __restrict__ rk7b,
                           const float* __restrict__ lk5w, const float* __restrict__ lk5b,
                           const float* __restrict__ lk7w, const float* __restrict__ lk7b)
{
    int id = blockIdx.x*blockDim.x + threadIdx.x;
    if (id >= 64*64) return;
    int m = id >> 6, c = id & 63;
    const float* w; const float* bs; int K, o;
    if      (m < 16) { w = rk5w; bs = rk5b; K = 5; o = m;    }
    else if (m < 32) { w = rk7w; bs = rk7b; K = 7; o = m-16; }
    else if (m < 48) { w = lk5w; bs = lk5b; K = 5; o = m-32; }
    else             { w = lk7w; bs = lk7b; K = 7; o = m-48; }
    float acc = 0.f;
    for (int k = 0; k < K; k++) acc += w[(o*K + k)*64 + c];
    g_Weff[m*64 + c] = acc;
    if (c == 0) {
        float bacc = 0.f;
        for (int k = 0; k < K; k++) bacc += bs[o*K + k];
        g_beff[m] = bacc;
    }
}

// ---------------- K0b: BN-folded bias for conv64 ---------------------------
__global__ void prep_b(const float* __restrict__ b2s, const float* __restrict__ bg,
                       const float* __restrict__ bbta, const float* __restrict__ bm,
                       const float* __restrict__ bv)
{
    int id = blockIdx.x*blockDim.x + threadIdx.x;
    if (id < 64) {
        float scc = bg[id] * rsqrtf(bv[id] + 1e-5f);
        g_b2[id] = b2s[id]*scc + bbta[id] - bm[id]*scc;
    }
}

// ---------------- K0c: pack mma B-fragments (hi/lo split) ------------------
__global__ void prep_frag(const float* __restrict__ sfw, const float* __restrict__ bg,
                          const float* __restrict__ bv, const float* __restrict__ fcw,
                          const float* __restrict__ w1)
{
    int id = blockIdx.x*blockDim.x + threadIdx.x;
    if (id < 9216) {
        int lane = id & 31; int rem = id >> 5;
        int nt = rem & 7; rem >>= 3;
        int ks = rem & 1; rem >>= 1;
        int kh = rem & 1; int t = rem >> 1;
        int n  = nt*8 + (lane >> 2);
        int k0 = kh*32 + ks*16 + (lane & 3)*2;
        float sc = bg[n] * rsqrtf(bv[n] + 1e-5f);
        float w00 = sfw[(n*64 + k0    )*9 + t] * sc;
        float w01 = sfw[(n*64 + k0 + 1)*9 + t] * sc;
        float w08 = sfw[(n*64 + k0 + 8)*9 + t] * sc;
        float w09 = sfw[(n*64 + k0 + 9)*9 + t] * sc;
        __nv_bfloat16 h00 = __float2bfloat16(w00), h01 = __float2bfloat16(w01);
        __nv_bfloat16 h08 = __float2bfloat16(w08), h09 = __float2bfloat16(w09);
        uint4 rec;
        rec.x = (uint32_t)(*(uint16_t*)&h00) | ((uint32_t)(*(uint16_t*)&h01) << 16);
        rec.y = (uint32_t)(*(uint16_t*)&h08) | ((uint32_t)(*(uint16_t*)&h09) << 16);
        rec.z = bfpack2(w00 - __bfloat162float(h00), w01 - __bfloat162float(h01));
        rec.w = bfpack2(w08 - __bfloat162float(h08), w09 - __bfloat162float(h09));
        g_wf[id] = rec;
    } else if (id < 10240) {
        int fid = id - 9216;
        int lane = fid & 31; int rem = fid >> 5;
        int nt = rem & 7; int ks = rem >> 3;
        int n  = nt*8 + (lane >> 2);
        int k0 = ks*16 + (lane & 3)*2;
        float w00 = fcw[n*64 + k0    ];
        float w01 = fcw[n*64 + k0 + 1];
        float w08 = fcw[n*64 + k0 + 8];
        float w09 = fcw[n*64 + k0 + 9];
        __nv_bfloat16 h00 = __float2bfloat16(w00), h01 = __float2bfloat16(w01);
        __nv_bfloat16 h08 = __float2bfloat16(w08), h09 = __float2bfloat16(w09);
        uint4 rec;
        rec.x = (uint32_t)(*(uint16_t*)&h00) | ((uint32_t)(*(uint16_t*)&h01) << 16);
        rec.y = (uint32_t)(*(uint16_t*)&h08) | ((uint32_t)(*(uint16_t*)&h09) << 16);
        rec.z = bfpack2(w00 - __bfloat162float(h00), w01 - __bfloat162float(h01));
        rec.w = bfpack2(w08 - __bfloat162float(h08), w09 - __bfloat162float(h09));
        g_fcf[fid] = rec;
    } else if (id < 14848) {
        int fid = id - 10240;
        int lane = fid & 31; int rem = fid >> 5;
        int nt = rem & 3; rem >>= 2;
        int ks = rem & 1; rem >>= 1;
        int kh = rem & 1; int t = rem >> 1;
        int n  = nt*8 + (lane >> 2);          // oc 0..31
        int k0 = kh*32 + ks*16 + (lane & 3)*2;
        float w00 = w1[(n*64 + k0    )*9 + t];
        float w01 = w1[(n*64 + k0 + 1)*9 + t];
        float w08 = w1[(n*64 + k0 + 8)*9 + t];
        float w09 = w1[(n*64 + k0 + 9)*9 + t];
        __nv_bfloat16 h00 = __float2bfloat16(w00), h01 = __float2bfloat16(w01);
        __nv_bfloat16 h08 = __float2bfloat16(w08), h09 = __float2bfloat16(w09);
        uint4 rec;
        rec.x = (uint32_t)(*(uint16_t*)&h00) | ((uint32_t)(*(uint16_t*)&h01) << 16);
        rec.y = (uint32_t)(*(uint16_t*)&h08) | ((uint32_t)(*(uint16_t*)&h09) << 16);
        rec.z = bfpack2(w00 - __bfloat162float(h00), w01 - __bfloat162float(h01));
        rec.w = bfpack2(w08 - __bfloat162float(h08), w09 - __bfloat162float(h09));
        g_wf1[fid] = rec;
    }
}

// ---------------- K1: conv3x3<32> + sobel edge + attention via mma.sync ----
// Block = 32w x 4h (M=128 px), N=32 oc, 256 thr = 8 warps.
__global__ __launch_bounds__(256)
void conv32_edge_mma(const float* __restrict__ x,
                     const uint4* __restrict__ wf1, const float* __restrict__ b1,
                     const float* __restrict__ baw2, const float* __restrict__ bab2)
{
    __shared__ __align__(16) uint16_t s_hi[6528];   // [6][34][32] bf16
    __shared__ __align__(16) uint16_t s_lo[6528];
    __shared__ float s_ep[2][128], s_sp[2][128];
    __shared__ float s_b1[32], s_w2[32];

    const int tid = threadIdx.x;
    const int wid = tid >> 5, lane = tid & 31;
    const int g = lane >> 2, t2 = (lane & 3) * 2;
    const int b  = blockIdx.z;
    const int w0 = blockIdx.x*32, h0 = blockIdx.y*4;

    if (tid < 32) { s_b1[tid] = b1[tid]; s_w2[tid] = baw2[tid]; }

    const int m0 = wid*16 + g, m1 = m0 + 8;
    const int ph0 = m0 >> 5, pw0 = m0 & 31;
    const int ph1 = m1 >> 5, pw1 = m1 & 31;

    // edge/sum assignment: pixel p = tid&127, ci-group cig = tid>>7 (16 ch)
    const int ep  = tid & 127;
    const int cig = tid >> 7;
    const int eph = ep >> 5, epw = ep & 31;

    float d[4][4];
    #pragma unroll
    for (int nt = 0; nt < 4; nt++)
        #pragma unroll
        for (int i = 0; i < 4; i++) d[nt][i] = 0.f;
    float edge_acc = 0.f, sum_acc = 0.f;

    for (int kh = 0; kh < 2; kh++) {
        if (kh) __syncthreads();
        // stage halo k-half: fp32 -> bf16 hi/lo planes
        #pragma unroll
        for (int it = 0; it < 13; it++) {
            int idx = tid + it*256;
            if (idx < 3264) {
                int hw = idx >> 4, cp = idx & 15;
                int h = hw / 34, w = hw % 34;
                int gh = h0 - 1 + h, gw = w0 - 1 + w;
                bool inb = (gh >= 0 && gh < HH && gw >= 0 && gw < WW);
                int ci = kh*32 + cp*2;
                const float* fp = x + ((size_t)(b*64 + ci))*HWSZ + (inb ? gh*WW + gw : 0);
                float v0 = inb ? fp[0] : 0.f;
                float v1 = inb ? fp[HWSZ] : 0.f;
                __nv_bfloat16 h0b = __float2bfloat16(v0);
                __nv_bfloat16 h1b = __float2bfloat16(v1);
                uint32_t hiw = (uint32_t)(*(uint16_t*)&h0b) | ((uint32_t)(*(uint16_t*)&h1b) << 16);
                uint32_t low = bfpack2(v0 - __bfloat162float(h0b), v1 - __bfloat162float(h1b));
                *(uint32_t*)&s_hi[hw*32 + cp*2] = hiw;
                *(uint32_t*)&s_lo[hw*32 + cp*2] = low;
            }
        }
        __syncthreads();

        // ---- edge + channel-sum partials from staged planes ----
        {
            // reconstruct 16 channels at 7 positions: corners/edges of 3x3 + center
            // kh==0: sobel-x needs cols {0,2} of rows {0,1,2}; kh==1: rows {0,2} of cols {0,1,2}
            float v[7][16];
            const int base_h = eph, base_w = epw;
            #pragma unroll
            for (int ppos = 0; ppos < 7; ppos++) {
                int dh, dw;
                if (ppos < 6) {
                    if (kh == 0) { dh = ppos >> 1; dw = (ppos & 1) * 2; }
                    else         { dh = (ppos & 1) * 2; dw = ppos >> 1; }
                } else { dh = 1; dw = 1; }
                int hw = (base_h + dh)*34 + (base_w + dw);
                const uint4* ph_ = (const uint4*)&s_hi[hw*32 + cig*16];
                const uint4* pl_ = (const uint4*)&s_lo[hw*32 + cig*16];
                #pragma unroll
                for (int q = 0; q < 2; q++) {
                    uint4 hv = ph_[q], lv = pl_[q];
                    const uint32_t hw_[4] = {hv.x, hv.y, hv.z, hv.w};
                    const uint32_t lw_[4] = {lv.x, lv.y, lv.z, lv.w};
                    #pragma unroll
                    for (int r = 0; r < 4; r++) {
                        v[ppos][q*8 + r*2    ] = bfunp_lo(hw_[r]) + bfunp_lo(lw_[r]);
                        v[ppos][q*8 + r*2 + 1] = bfunp_hi(hw_[r]) + bfunp_hi(lw_[r]);
                    }
                }
            }
            float e = 0.f, s = 0.f;
            #pragma unroll
            for (int c = 0; c < 16; c++) {
                s += v[6][c];
                // positions 0..5 map (r0c0,r0c2),(r1c0,r1c2),(r2c0,r2c2) for kh=0
                //                    (r0c0,r2c0),(r0c1,r2c1),(r0c2,r2c2) for kh=1
                float gsum = (v[1][c] - v[0][c]) + 2.f*(v[3][c] - v[2][c]) + (v[5][c] - v[4][c]);
                e += fabsf(gsum);
            }
            edge_acc += e;
            sum_acc  += s;
        }

        // ---- conv MMAs ----
        for (int t = 0; t < 9; t++) {
            const int dr = t/3, dc = t%3;
            const int r0 = ((ph0 + dr)*34 + pw0 + dc)*32;
            const int r1 = ((ph1 + dr)*34 + pw1 + dc)*32;
            #pragma unroll
            for (int ks = 0; ks < 2; ks++) {
                uint4 bfr[4];
                const uint4* wp = wf1 + (size_t)(((t*2 + kh)*2 + ks)*4)*32 + lane;
                #pragma unroll
                for (int nt = 0; nt < 4; nt++) bfr[nt] = wp[nt*32];

                const int k = ks*16 + t2;
                uint32_t ah[4], al[4];
                ah[0] = *(const uint32_t*)&s_hi[r0 + k];
                ah[1] = *(const uint32_t*)&s_hi[r1 + k];
                ah[2] = *(const uint32_t*)&s_hi[r0 + k + 8];
                ah[3] = *(const uint32_t*)&s_hi[r1 + k + 8];
                al[0] = *(const uint32_t*)&s_lo[r0 + k];
                al[1] = *(const uint32_t*)&s_lo[r1 + k];
                al[2] = *(const uint32_t*)&s_lo[r0 + k + 8];
                al[3] = *(const uint32_t*)&s_lo[r1 + k + 8];

                #pragma unroll
                for (int nt = 0; nt < 4; nt++) {
                    mma_bf16(d[nt], ah, bfr[nt].x, bfr[nt].y);
                    mma_bf16(d[nt], al, bfr[nt].x, bfr[nt].y);
                    mma_bf16(d[nt], ah, bfr[nt].z, bfr[nt].w);
                }
            }
        }
    }

    s_ep[cig][ep] = edge_acc;
    s_sp[cig][ep] = sum_acc;

    // ---- attention partial from D fragments ----
    float att0 = 0.f, att1 = 0.f;
    #pragma unroll
    for (int nt = 0; nt < 4; nt++) {
        int oc = nt*8 + t2;
        float b0v = s_b1[oc], b1v = s_b1[oc+1];
        float w0v = s_w2[oc], w1v = s_w2[oc+1];
        att0 += w0v*fmaxf(d[nt][0] + b0v, 0.f) + w1v*fmaxf(d[nt][1] + b1v, 0.f);
        att1 += w0v*fmaxf(d[nt][2] + b0v, 0.f) + w1v*fmaxf(d[nt][3] + b1v, 0.f);
    }
    att0 += __shfl_xor_sync(0xFFFFFFFF, att0, 1);
    att0 += __shfl_xor_sync(0xFFFFFFFF, att0, 2);
    att1 += __shfl_xor_sync(0xFFFFFFFF, att1, 1);
    att1 += __shfl_xor_sync(0xFFFFFFFF, att1, 2);
    __syncthreads();

    if ((lane & 3) == 0) {
        float bb = bab2[0];
        #pragma unroll
        for (int r = 0; r < 2; r++) {
            int m = r ? m1 : m0;
            float att = (r ? att1 : att0) + bb;
            float ed = (s_ep[0][m] + s_ep[1][m]) * (1.f/32.f);
            float sx =  s_sp[0][m] + s_sp[1][m];
            float z = att + ed;
            float a = 1.f / (1.f + expf(-z));
            float gv = 1.f + a;
            int mh = m >> 5, mw = m & 31;
            size_t pix = (size_t)b*HWSZ + (size_t)(h0 + mh)*WW + (w0 + mw);
            g_gmap[pix] = gv;
            g_smap[pix] = gv * sx;
        }
    }
}

// ---------------- K3: fusion GEMM, m-split, prefetched loads (unchanged) ---
__global__ __launch_bounds__(256)
void fusion_k(const float* __restrict__ in, const float* __restrict__ wsrc,
              const float* __restrict__ bsrc, float* __restrict__ outp)
{
    __shared__ __align__(16) float s_w[64][32];
    __shared__ float s_b[32];
    const int tid = threadIdx.x;
    const int ms  = blockIdx.y;
    const int b   = blockIdx.z;
    for (int i = tid; i < 2048; i += 256) {
        int ci = i >> 5, m = i & 31;
        s_w[ci][m] = wsrc[(ms*32 + m)*64 + ci];
    }
    if (tid < 32) s_b[tid] = bsrc[ms*32 + tid];
    __syncthreads();

    const int mg    = tid >> 6;
    const int mbase = mg*8;
    const int slot  = tid & 63;
    const int pix   = blockIdx.x*256 + slot*4;
    const float* basep = in + (size_t)b*64*HWSZ + pix;

    ull acc[4][4];
    #pragma unroll
    for (int m = 0; m < 4; m++)
        #pragma unroll
        for (int p = 0; p < 4; p++) acc[m][p] = 0ULL;

    float4 xv[4];
    #pragma unroll
    for (int j = 0; j < 4; j++)
        xv[j] = *(const float4*)(basep + (size_t)j*HWSZ);

    #pragma unroll 1
    for (int c4 = 0; c4 < 16; c4++) {
        float4 xn[4];
        if (c4 < 15) {
            const float* bp = basep + (size_t)(c4+1)*4*HWSZ;
            #pragma unroll
            for (int j = 0; j < 4; j++)
                xn[j] = *(const float4*)(bp + (size_t)j*HWSZ);
        }
        #pragma unroll
        for (int j = 0; j < 4; j++) {
            ull xd0 = pk2(xv[j].x, xv[j].x);
            ull xd1 = pk2(xv[j].y, xv[j].y);
            ull xd2 = pk2(xv[j].z, xv[j].z);
            ull xd3 = pk2(xv[j].w, xv[j].w);
            const ulonglong2* wp = (const ulonglong2*)&s_w[c4*4 + j][mbase];
            ulonglong2 wA = wp[0], wB = wp[1];
            acc[0][0]=f2fma(wA.x,xd0,acc[0][0]); acc[0][1]=f2fma(wA.x,xd1,acc[0][1]);
            acc[0][2]=f2fma(wA.x,xd2,acc[0][2]); acc[0][3]=f2fma(wA.x,xd3,acc[0][3]);
            acc[1][0]=f2fma(wA.y,xd0,acc[1][0]); acc[1][1]=f2fma(wA.y,xd1,acc[1][1]);
            acc[1][2]=f2fma(wA.y,xd2,acc[1][2]); acc[1][3]=f2fma(wA.y,xd3,acc[1][3]);
            acc[2][0]=f2fma(wB.x,xd0,acc[2][0]); acc[2][1]=f2fma(wB.x,xd1,acc[2][1]);
            acc[2][2]=f2fma(wB.x,xd2,acc[2][2]); acc[2][3]=f2fma(wB.x,xd3,acc[2][3]);
            acc[3][0]=f2fma(wB.y,xd0,acc[3][0]); acc[3][1]=f2fma(wB.y,xd1,acc[3][1]);
            acc[3][2]=f2fma(wB.y,xd2,acc[3][2]); acc[3][3]=f2fma(wB.y,xd3,acc[3][3]);
        }
        if (c4 < 15) {
            #pragma unroll
            for (int j = 0; j < 4; j++) xv[j] = xn[j];
        }
    }

    float4 gv = *(const float4*)&g_gmap[(size_t)b*HWSZ + pix];
    float4 sv = *(const float4*)&g_smap[(size_t)b*HWSZ + pix];
    float gs[4] = {gv.x, gv.y, gv.z, gv.w};
    float ss[4] = {sv.x, sv.y, sv.z, sv.w};
    #pragma unroll
    for (int mp = 0; mp < 4; mp++) {
        int ch = ms*32 + mbase + 2*mp;
        float b0 = s_b[mbase + 2*mp], b1 = s_b[mbase + 2*mp + 1];
        float lo[4], hi[4];
        #pragma unroll
        for (int p = 0; p < 4; p++) {
            float alo, ahi;
            upk2(acc[mp][p], alo, ahi);
            lo[p] = ss[p] * (gs[p]*alo + b0);
            hi[p] = ss[p] * (gs[p]*ahi + b1);
        }
        float4 vlo = {lo[0], lo[1], lo[2], lo[3]};
        float4 vhi = {hi[0], hi[1], hi[2], hi[3]};
        *(float4*)&outp[((size_t)(b*64 + ch  ))*HWSZ + pix] = vlo;
        *(float4*)&outp[((size_t)(b*64 + ch+1))*HWSZ + pix] = vhi;
    }
}

// ---------------- K4: conv3x3<64> + fc + residual via bf16 mma.sync --------
// (unchanged from R10 — known good)
__global__ __launch_bounds__(256)
void conv64fc_mma(const float* __restrict__ fus,
                  const uint4* __restrict__ wf, const float* __restrict__ b2,
                  const uint4* __restrict__ fcf, const float* __restrict__ fcb,
                  const float* __restrict__ resid, float* __restrict__ out)
{
    __shared__ __align__(16) uint16_t s_buf[2*128*68];
    __shared__ float s_b2[64], s_fcb[64];

    const int tid = threadIdx.x;
    const int wid = tid >> 5, lane = tid & 31;
    const int g = lane >> 2, t2 = (lane & 3) * 2;
    const int b  = blockIdx.z;
    const int w0 = blockIdx.x*32, h0 = blockIdx.y*4;

    if (tid < 64) { s_b2[tid] = b2[tid]; s_fcb[tid] = fcb[tid]; }

    uint16_t* s_hi = s_buf;
    uint16_t* s_lo = s_buf + 6528;

    const int m0 = wid*16 + g, m1 = m0 + 8;
    const int ph0 = m0 >> 5, pw0 = m0 & 31;
    const int ph1 = m1 >> 5, pw1 = m1 & 31;

    float d[8][4];
    #pragma unroll
    for (int nt = 0; nt < 8; nt++)
        #pragma unroll
        for (int i = 0; i < 4; i++) d[nt][i] = 0.f;

    for (int kh = 0; kh < 2; kh++) {
        if (kh) __syncthreads();
        #pragma unroll
        for (int it = 0; it < 13; it++) {
            int idx = tid + it*256;
            if (idx < 3264) {
                int hw = idx >> 4, cp = idx & 15;
                int h = hw / 34, w = hw % 34;
                int gh = h0 - 1 + h, gw = w0 - 1 + w;
                bool inb = (gh >= 0 && gh < HH && gw >= 0 && gw < WW);
                int ci = kh*32 + cp*2;
                const float* fp = fus + ((size_t)(b*64 + ci))*HWSZ + (inb ? gh*WW + gw : 0);
                float v0 = inb ? fp[0] : 0.f;
                float v1 = inb ? fp[HWSZ] : 0.f;
                __nv_bfloat16 h0b = __float2bfloat16(v0);
                __nv_bfloat16 h1b = __float2bfloat16(v1);
                uint32_t hiw = (uint32_t)(*(uint16_t*)&h0b) | ((uint32_t)(*(uint16_t*)&h1b) << 16);
                uint32_t low = bfpack2(v0 - __bfloat162float(h0b), v1 - __bfloat162float(h1b));
                *(uint32_t*)&s_hi[hw*32 + cp*2] = hiw;
                *(uint32_t*)&s_lo[hw*32 + cp*2] = low;
            }
        }
        __syncthreads();

        for (int t = 0; t < 9; t++) {
            const int dr = t/3, dc = t%3;
            const int r0 = ((ph0 + dr)*34 + pw0 + dc)*32;
            const int r1 = ((ph1 + dr)*34 + pw1 + dc)*32;
            #pragma unroll
            for (int ks = 0; ks < 2; ks++) {
                uint4 bfr[8];
                const uint4* wp = wf + (size_t)(((t*2 + kh)*2 + ks)*8)*32 + lane;
                #pragma unroll
                for (int nt = 0; nt < 8; nt++) bfr[nt] = wp[nt*32];

                const int k = ks*16 + t2;
                uint32_t ah[4], al[4];
                ah[0] = *(const uint32_t*)&s_hi[r0 + k];
                ah[1] = *(const uint32_t*)&s_hi[r1 + k];
                ah[2] = *(const uint32_t*)&s_hi[r0 + k + 8];
                ah[3] = *(const uint32_t*)&s_hi[r1 + k + 8];
                al[0] = *(const uint32_t*)&s_lo[r0 + k];
                al[1] = *(const uint32_t*)&s_lo[r1 + k];
                al[2] = *(const uint32_t*)&s_lo[r0 + k + 8];
                al[3] = *(const uint32_t*)&s_lo[r1 + k + 8];

                #pragma unroll
                for (int nt = 0; nt < 8; nt++) {
                    mma_bf16(d[nt], ah, bfr[nt].x, bfr[nt].y);
                    mma_bf16(d[nt], al, bfr[nt].x, bfr[nt].y);
                    mma_bf16(d[nt], ah, bfr[nt].z, bfr[nt].w);
                }
            }
        }
    }
    __syncthreads();

    uint16_t* f_hi = s_buf;
    uint16_t* f_lo = s_buf + 128*68;
    #pragma unroll
    for (int nt = 0; nt < 8; nt++) {
        int oc = nt*8 + t2;
        float b0v = s_b2[oc], b1v = s_b2[oc+1];
        float v00 = fmaxf(d[nt][0] + b0v, 0.f);
        float v01 = fmaxf(d[nt][1] + b1v, 0.f);
        float v10 = fmaxf(d[nt][2] + b0v, 0.f);
        float v11 = fmaxf(d[nt][3] + b1v, 0.f);
        __nv_bfloat16 h00 = __float2bfloat16(v00), h01 = __float2bfloat16(v01);
        __nv_bfloat16 h10 = __float2bfloat16(v10), h11 = __float2bfloat16(v11);
        *(uint32_t*)&f_hi[m0*68 + oc] =
            (uint32_t)(*(uint16_t*)&h00) | ((uint32_t)(*(uint16_t*)&h01) << 16);
        *(uint32_t*)&f_hi[m1*68 + oc] =
            (uint32_t)(*(uint16_t*)&h10) | ((uint32_t)(*(uint16_t*)&h11) << 16);
        *(uint32_t*)&f_lo[m0*68 + oc] =
            bfpack2(v00 - __bfloat162float(h00), v01 - __bfloat162float(h01));
        *(uint32_t*)&f_lo[m1*68 + oc] =
            bfpack2(v10 - __bfloat162float(h10), v11 - __bfloat162float(h11));
    }
    __syncthreads();

    float e[8][4];
    #pragma unroll
    for (int nt = 0; nt < 8; nt++)
        #pragma unroll
        for (int i = 0; i < 4; i++) e[nt][i] = 0.f;

    #pragma unroll
    for (int ks = 0; ks < 4; ks++) {
        uint4 bfr[8];
        const uint4* wp = fcf + (ks*8)*32 + lane;
        #pragma unroll
        for (int nt = 0; nt < 8; nt++) bfr[nt] = wp[nt*32];

        const int k = ks*16 + t2;
        uint32_t ah[4], al[4];
        ah[0] = *(const uint32_t*)&f_hi[m0*68 + k];
        ah[1] = *(const uint32_t*)&f_hi[m1*68 + k];
        ah[2] = *(const uint32_t*)&f_hi[m0*68 + k + 8];
        ah[3] = *(const uint32_t*)&f_hi[m1*68 + k + 8];
        al[0] = *(const uint32_t*)&f_lo[m0*68 + k];
        al[1] = *(const uint32_t*)&f_lo[m1*68 + k];
        al[2] = *(const uint32_t*)&f_lo[m0*68 + k + 8];
        al[3] = *(const uint32_t*)&f_lo[m1*68 + k + 8];

        #pragma unroll
        for (int nt = 0; nt < 8; nt++) {
            mma_bf16(e[nt], ah, bfr[nt].x, bfr[nt].y);
            mma_bf16(e[nt], al, bfr[nt].x, bfr[nt].y);
            mma_bf16(e[nt], ah, bfr[nt].z, bfr[nt].w);
        }
    }

    const size_t base = (size_t)b*64*HWSZ;
    const int p0 = (h0 + ph0)*WW + w0 + pw0;
    const int p1 = (h0 + ph1)*WW + w0 + pw1;
    #pragma unroll
    for (int nt = 0; nt < 8; nt++) {
        int oc = nt*8 + t2;
        size_t i00 = base + (size_t)oc*HWSZ + p0;
        size_t i01 = i00 + HWSZ;
        size_t i10 = base + (size_t)oc*HWSZ + p1;
        size_t i11 = i10 + HWSZ;
        out[i00] = e[nt][0] + s_fcb[oc]   + resid[i00];
        out[i01] = e[nt][1] + s_fcb[oc+1] + resid[i01];
        out[i10] = e[nt][2] + s_fcb[oc]   + resid[i10];
        out[i11] = e[nt][3] + s_fcb[oc+1] + resid[i11];
    }
}

// ---------------------------------------------------------------------------
extern "C" void kernel_launch(void* const* d_in, const int* in_sizes, int n_in,
                              void* d_out, int out_size)
{
    (void)in_sizes; (void)n_in; (void)out_size;
    const float* x     = (const float*)d_in[0];
    const float* ba_w1 = (const float*)d_in[1];
    const float* ba_b1 = (const float*)d_in[2];
    const float* ba_w2 = (const float*)d_in[3];
    const float* ba_b2 = (const float*)d_in[4];
    // d_in[5..12]: offset branch — dead code in the reference, skipped.
    const float* rk5w  = (const float*)d_in[13];
    const float* rk5b  = (const float*)d_in[14];
    const float* rk7w  = (const float*)d_in[15];
    const float* rk7b  = (const float*)d_in[16];
    const float* lk5w  = (const float*)d_in[17];
    const float* lk5b  = (const float*)d_in[18];
    const float* lk7w  = (const float*)d_in[19];
    const float* lk7b  = (const float*)d_in[20];
    const float* sfw   = (const float*)d_in[21];
    const float* sfb   = (const float*)d_in[22];
    const float* sfg   = (const float*)d_in[23];
    const float* sfbb  = (const float*)d_in[24];
    const float* sfm   = (const float*)d_in[25];
    const float* sfv   = (const float*)d_in[26];
    const float* fcw   = (const float*)d_in[27];
    const float* fcb   = (const float*)d_in[28];
    float* out = (float*)d_out;

    float *pFus, *pWeff, *pBeff, *pB2;
    uint4 *pWf, *pFcf, *pWf1;
    cudaGetSymbolAddress((void**)&pFus,  g_fusion);
    cudaGetSymbolAddress((void**)&pWeff, g_Weff);
    cudaGetSymbolAddress((void**)&pBeff, g_beff);
    cudaGetSymbolAddress((void**)&pB2,   g_b2);
    cudaGetSymbolAddress((void**)&pWf,   g_wf);
    cudaGetSymbolAddress((void**)&pFcf,  g_fcf);
    cudaGetSymbolAddress((void**)&pWf1,  g_wf1);

    build_weff<<<16, 256>>>(rk5w, rk5b, rk7w, rk7b, lk5w, lk5b, lk7w, lk7b);
    prep_b<<<1, 64>>>(sfb, sfg, sfbb, sfm, sfv);
    prep_frag<<<58, 256>>>(sfw, sfg, sfv, fcw, ba_w1);

    conv32_edge_mma<<<dim3(WW/32, HH/4, BB), 256>>>(x, pWf1, ba_b1, ba_w2, ba_b2);
    fusion_k<<<dim3(HWSZ/256, 2, BB), 256>>>(x, pWeff, pBeff, pFus);
    conv64fc_mma<<<dim3(WW/32, HH/4, BB), 256>>>(pFus, pWf, pB2, pFcf, fcb, x, out);
}

// round 12
// speedup vs baseline: 3.1952x; 1.1994x over previous
#include <cuda_runtime.h>
#include <cuda_bf16.h>
#include <cstdint>
#include <cstddef>

#define BB 4
#define HH 160
#define WW 160
#define HWSZ (HH*WW)
#define CPAD 40          // padded channel stride (u16) for conv staging
#define FPAD 72          // padded k stride (u16) for fc phase

typedef unsigned long long ull;

// ---------------- packed f32x2 helpers (fp32 kernels) ----------------------
__device__ __forceinline__ ull pk2(float lo, float hi) {
    ull r; asm("mov.b64 %0,{%1,%2};" : "=l"(r) : "f"(lo), "f"(hi)); return r;
}
__device__ __forceinline__ void upk2(ull v, float& lo, float& hi) {
    asm("mov.b64 {%0,%1},%2;" : "=f"(lo), "=f"(hi) : "l"(v));
}
__device__ __forceinline__ ull f2fma(ull a, ull b, ull c) {
    ull d; asm("fma.rn.f32x2 %0,%1,%2,%3;" : "=l"(d) : "l"(a), "l"(b), "l"(c)); return d;
}

// ---------------- bf16 mma.sync helpers ------------------------------------
__device__ __forceinline__ void mma_bf16(float d[4], const uint32_t a[4],
                                         uint32_t b0, uint32_t b1) {
    asm volatile(
        "mma.sync.aligned.m16n8k16.row.col.f32.bf16.bf16.f32 "
        "{%0,%1,%2,%3}, {%4,%5,%6,%7}, {%8,%9}, {%0,%1,%2,%3};"
        : "+f"(d[0]), "+f"(d[1]), "+f"(d[2]), "+f"(d[3])
        : "r"(a[0]), "r"(a[1]), "r"(a[2]), "r"(a[3]), "r"(b0), "r"(b1));
}
__device__ __forceinline__ uint32_t bfpack2(float x, float y) {
    __nv_bfloat162 h = __halves2bfloat162(__float2bfloat16(x), __float2bfloat16(y));
    return *(uint32_t*)&h;
}
__device__ __forceinline__ float bfunp_lo(uint32_t v) {
    __nv_bfloat162 h = *(__nv_bfloat162*)&v;
    return __bfloat162float(__low2bfloat16(h));
}
__device__ __forceinline__ float bfunp_hi(uint32_t v) {
    __nv_bfloat162 h = *(__nv_bfloat162*)&v;
    return __bfloat162float(__high2bfloat16(h));
}

// ---------------- scratch (device globals; no allocation allowed) ----------
__device__ __align__(128) float g_gmap[BB*HWSZ];
__device__ __align__(128) float g_smap[BB*HWSZ];
__device__ __align__(128) float g_fusion[BB*64*HWSZ];
__device__ __align__(128) float g_Weff[64*64];
__device__ __align__(128) float g_beff[64];
__device__ __align__(128) float g_b2[64];         // BN-folded bias
__device__ __align__(128) uint4 g_wf[9216];       // conv64 frags [t][kh][ks][nt8][lane]
__device__ __align__(128) uint4 g_fcf[1024];      // fc frags [ks][nt8][lane]
__device__ __align__(128) uint4 g_wf1[4608];      // conv32 frags [t][kh][ks][nt4][lane]

// ---------------- K0a: effective dyn1d weights (sum over K) ----------------
__global__ void build_weff(const float* __restrict__ rk5w, const float* __restrict__ rk5b,
                           const float* __restrict__ rk7w, const float* __restrict__ rk7b,
                           const float* __restrict__ lk5w, const float* __restrict__ lk5b,
                           const float* __restrict__ lk7w, const float* __restrict__ lk7b)
{
    int id = blockIdx.x*blockDim.x + threadIdx.x;
    if (id >= 64*64) return;
    int m = id >> 6, c = id & 63;
    const float* w; const float* bs; int K, o;
    if      (m < 16) { w = rk5w; bs = rk5b; K = 5; o = m;    }
    else if (m < 32) { w = rk7w; bs = rk7b; K = 7; o = m-16; }
    else if (m < 48) { w = lk5w; bs = lk5b; K = 5; o = m-32; }
    else             { w = lk7w; bs = lk7b; K = 7; o = m-48; }
    float acc = 0.f;
    for (int k = 0; k < K; k++) acc += w[(o*K + k)*64 + c];
    g_Weff[m*64 + c] = acc;
    if (c == 0) {
        float bacc = 0.f;
        for (int k = 0; k < K; k++) bacc += bs[o*K + k];
        g_beff[m] = bacc;
    }
}

// ---------------- K0b: BN-folded bias for conv64 ---------------------------
__global__ void prep_b(const float* __restrict__ b2s, const float* __restrict__ bg,
                       const float* __restrict__ bbta, const float* __restrict__ bm,
                       const float* __restrict__ bv)
{
    int id = blockIdx.x*blockDim.x + threadIdx.x;
    if (id < 64) {
        float scc = bg[id] * rsqrtf(bv[id] + 1e-5f);
        g_b2[id] = b2s[id]*scc + bbta[id] - bm[id]*scc;
    }
}

// ---------------- K0c: pack mma B-fragments (hi/lo split) ------------------
__global__ void prep_frag(const float* __restrict__ sfw, const float* __restrict__ bg,
                          const float* __restrict__ bv, const float* __restrict__ fcw,
                          const float* __restrict__ w1)
{
    int id = blockIdx.x*blockDim.x + threadIdx.x;
    if (id < 9216) {
        int lane = id & 31; int rem = id >> 5;
        int nt = rem & 7; rem >>= 3;
        int ks = rem & 1; rem >>= 1;
        int kh = rem & 1; int t = rem >> 1;
        int n  = nt*8 + (lane >> 2);
        int k0 = kh*32 + ks*16 + (lane & 3)*2;
        float sc = bg[n] * rsqrtf(bv[n] + 1e-5f);
        float w00 = sfw[(n*64 + k0    )*9 + t] * sc;
        float w01 = sfw[(n*64 + k0 + 1)*9 + t] * sc;
        float w08 = sfw[(n*64 + k0 + 8)*9 + t] * sc;
        float w09 = sfw[(n*64 + k0 + 9)*9 + t] * sc;
        __nv_bfloat16 h00 = __float2bfloat16(w00), h01 = __float2bfloat16(w01);
        __nv_bfloat16 h08 = __float2bfloat16(w08), h09 = __float2bfloat16(w09);
        uint4 rec;
        rec.x = (uint32_t)(*(uint16_t*)&h00) | ((uint32_t)(*(uint16_t*)&h01) << 16);
        rec.y = (uint32_t)(*(uint16_t*)&h08) | ((uint32_t)(*(uint16_t*)&h09) << 16);
        rec.z = bfpack2(w00 - __bfloat162float(h00), w01 - __bfloat162float(h01));
        rec.w = bfpack2(w08 - __bfloat162float(h08), w09 - __bfloat162float(h09));
        g_wf[id] = rec;
    } else if (id < 10240) {
        int fid = id - 9216;
        int lane = fid & 31; int rem = fid >> 5;
        int nt = rem & 7; int ks = rem >> 3;
        int n  = nt*8 + (lane >> 2);
        int k0 = ks*16 + (lane & 3)*2;
        float w00 = fcw[n*64 + k0    ];
        float w01 = fcw[n*64 + k0 + 1];
        float w08 = fcw[n*64 + k0 + 8];
        float w09 = fcw[n*64 + k0 + 9];
        __nv_bfloat16 h00 = __float2bfloat16(w00), h01 = __float2bfloat16(w01);
        __nv_bfloat16 h08 = __float2bfloat16(w08), h09 = __float2bfloat16(w09);
        uint4 rec;
        rec.x = (uint32_t)(*(uint16_t*)&h00) | ((uint32_t)(*(uint16_t*)&h01) << 16);
        rec.y = (uint32_t)(*(uint16_t*)&h08) | ((uint32_t)(*(uint16_t*)&h09) << 16);
        rec.z = bfpack2(w00 - __bfloat162float(h00), w01 - __bfloat162float(h01));
        rec.w = bfpack2(w08 - __bfloat162float(h08), w09 - __bfloat162float(h09));
        g_fcf[fid] = rec;
    } else if (id < 14848) {
        int fid = id - 10240;
        int lane = fid & 31; int rem = fid >> 5;
        int nt = rem & 3; rem >>= 2;
        int ks = rem & 1; rem >>= 1;
        int kh = rem & 1; int t = rem >> 1;
        int n  = nt*8 + (lane >> 2);          // oc 0..31
        int k0 = kh*32 + ks*16 + (lane & 3)*2;
        float w00 = w1[(n*64 + k0    )*9 + t];
        float w01 = w1[(n*64 + k0 + 1)*9 + t];
        float w08 = w1[(n*64 + k0 + 8)*9 + t];
        float w09 = w1[(n*64 + k0 + 9)*9 + t];
        __nv_bfloat16 h00 = __float2bfloat16(w00), h01 = __float2bfloat16(w01);
        __nv_bfloat16 h08 = __float2bfloat16(w08), h09 = __float2bfloat16(w09);
        uint4 rec;
        rec.x = (uint32_t)(*(uint16_t*)&h00) | ((uint32_t)(*(uint16_t*)&h01) << 16);
        rec.y = (uint32_t)(*(uint16_t*)&h08) | ((uint32_t)(*(uint16_t*)&h09) << 16);
        rec.z = bfpack2(w00 - __bfloat162float(h00), w01 - __bfloat162float(h01));
        rec.w = bfpack2(w08 - __bfloat162float(h08), w09 - __bfloat162float(h09));
        g_wf1[fid] = rec;
    }
}

// ---------------- K1: conv3x3<32> + sobel edge + attention via mma.sync ----
// Block = 32w x 4h (M=128 px), N=32 oc, 256 thr = 8 warps.
// Padded CPAD=40 channel stride: A-load position stride 80B -> bank-conflict free.
// conv uses (ah+al)*bh (2 MMAs); edge uses hi plane only (sigmoid-damped).
__global__ __launch_bounds__(256)
void conv32_edge_mma(const float* __restrict__ x,
                     const uint4* __restrict__ wf1, const float* __restrict__ b1,
                     const float* __restrict__ baw2, const float* __restrict__ bab2)
{
    __shared__ __align__(16) uint16_t s_hi[204*CPAD];   // [6*34][40]
    __shared__ __align__(16) uint16_t s_lo[204*CPAD];
    __shared__ float s_ep[2][128], s_sp[2][128];
    __shared__ float s_b1[32], s_w2[32];

    const int tid = threadIdx.x;
    const int wid = tid >> 5, lane = tid & 31;
    const int g = lane >> 2, t2 = (lane & 3) * 2;
    const int b  = blockIdx.z;
    const int w0 = blockIdx.x*32, h0 = blockIdx.y*4;

    if (tid < 32) { s_b1[tid] = b1[tid]; s_w2[tid] = baw2[tid]; }

    const int m0 = wid*16 + g, m1 = m0 + 8;
    const int ph0 = m0 >> 5, pw0 = m0 & 31;
    const int ph1 = m1 >> 5, pw1 = m1 & 31;

    const int ep  = tid & 127;
    const int cig = tid >> 7;
    const int eph = ep >> 5, epw = ep & 31;

    float d[4][4];
    #pragma unroll
    for (int nt = 0; nt < 4; nt++)
        #pragma unroll
        for (int i = 0; i < 4; i++) d[nt][i] = 0.f;
    float edge_acc = 0.f, sum_acc = 0.f;

    for (int kh = 0; kh < 2; kh++) {
        if (kh) __syncthreads();
        #pragma unroll
        for (int it = 0; it < 13; it++) {
            int idx = tid + it*256;
            if (idx < 3264) {
                int hw = idx >> 4, cp = idx & 15;
                int h = hw / 34, w = hw % 34;
                int gh = h0 - 1 + h, gw = w0 - 1 + w;
                bool inb = (gh >= 0 && gh < HH && gw >= 0 && gw < WW);
                int ci = kh*32 + cp*2;
                const float* fp = x + ((size_t)(b*64 + ci))*HWSZ + (inb ? gh*WW + gw : 0);
                float v0 = inb ? fp[0] : 0.f;
                float v1 = inb ? fp[HWSZ] : 0.f;
                __nv_bfloat16 h0b = __float2bfloat16(v0);
                __nv_bfloat16 h1b = __float2bfloat16(v1);
                uint32_t hiw = (uint32_t)(*(uint16_t*)&h0b) | ((uint32_t)(*(uint16_t*)&h1b) << 16);
                uint32_t low = bfpack2(v0 - __bfloat162float(h0b), v1 - __bfloat162float(h1b));
                *(uint32_t*)&s_hi[hw*CPAD + cp*2] = hiw;
                *(uint32_t*)&s_lo[hw*CPAD + cp*2] = low;
            }
        }
        __syncthreads();

        // ---- edge (hi-only) + channel-sum (hi+lo) partials ----
        {
            float v[7][16];
            const int base_h = eph, base_w = epw;
            #pragma unroll
            for (int ppos = 0; ppos < 7; ppos++) {
                int dh, dw;
                if (ppos < 6) {
                    if (kh == 0) { dh = ppos >> 1; dw = (ppos & 1) * 2; }
                    else         { dh = (ppos & 1) * 2; dw = ppos >> 1; }
                } else { dh = 1; dw = 1; }
                int hw = (base_h + dh)*34 + (base_w + dw);
                const uint4* ph_ = (const uint4*)&s_hi[hw*CPAD + cig*16];
                #pragma unroll
                for (int q = 0; q < 2; q++) {
                    uint4 hv = ph_[q];
                    const uint32_t hw_[4] = {hv.x, hv.y, hv.z, hv.w};
                    #pragma unroll
                    for (int r = 0; r < 4; r++) {
                        v[ppos][q*8 + r*2    ] = bfunp_lo(hw_[r]);
                        v[ppos][q*8 + r*2 + 1] = bfunp_hi(hw_[r]);
                    }
                }
                if (ppos == 6) {   // center needs full precision for sumx
                    const uint4* pl_ = (const uint4*)&s_lo[hw*CPAD + cig*16];
                    #pragma unroll
                    for (int q = 0; q < 2; q++) {
                        uint4 lv = pl_[q];
                        const uint32_t lw_[4] = {lv.x, lv.y, lv.z, lv.w};
                        #pragma unroll
                        for (int r = 0; r < 4; r++) {
                            v[6][q*8 + r*2    ] += bfunp_lo(lw_[r]);
                            v[6][q*8 + r*2 + 1] += bfunp_hi(lw_[r]);
                        }
                    }
                }
            }
            float e = 0.f, s = 0.f;
            #pragma unroll
            for (int c = 0; c < 16; c++) {
                s += v[6][c];
                float gsum = (v[1][c] - v[0][c]) + 2.f*(v[3][c] - v[2][c]) + (v[5][c] - v[4][c]);
                e += fabsf(gsum);
            }
            edge_acc += e;
            sum_acc  += s;
        }

        // ---- conv MMAs: (ah+al)*bh ----
        for (int t = 0; t < 9; t++) {
            const int dr = t/3, dc = t%3;
            const int r0 = ((ph0 + dr)*34 + pw0 + dc)*CPAD;
            const int r1 = ((ph1 + dr)*34 + pw1 + dc)*CPAD;
            #pragma unroll
            for (int ks = 0; ks < 2; ks++) {
                uint2 bfr[4];
                const uint2* wp = (const uint2*)(wf1 + (size_t)(((t*2 + kh)*2 + ks)*4)*32 + lane);
                #pragma unroll
                for (int nt = 0; nt < 4; nt++) bfr[nt] = wp[nt*64];

                const int k = ks*16 + t2;
                uint32_t ah[4], al[4];
                ah[0] = *(const uint32_t*)&s_hi[r0 + k];
                ah[1] = *(const uint32_t*)&s_hi[r1 + k];
                ah[2] = *(const uint32_t*)&s_hi[r0 + k + 8];
                ah[3] = *(const uint32_t*)&s_hi[r1 + k + 8];
                al[0] = *(const uint32_t*)&s_lo[r0 + k];
                al[1] = *(const uint32_t*)&s_lo[r1 + k];
                al[2] = *(const uint32_t*)&s_lo[r0 + k + 8];
                al[3] = *(const uint32_t*)&s_lo[r1 + k + 8];

                #pragma unroll
                for (int nt = 0; nt < 4; nt++) {
                    mma_bf16(d[nt], ah, bfr[nt].x, bfr[nt].y);
                    mma_bf16(d[nt], al, bfr[nt].x, bfr[nt].y);
                }
            }
        }
    }

    s_ep[cig][ep] = edge_acc;
    s_sp[cig][ep] = sum_acc;

    float att0 = 0.f, att1 = 0.f;
    #pragma unroll
    for (int nt = 0; nt < 4; nt++) {
        int oc = nt*8 + t2;
        float b0v = s_b1[oc], b1v = s_b1[oc+1];
        float w0v = s_w2[oc], w1v = s_w2[oc+1];
        att0 += w0v*fmaxf(d[nt][0] + b0v, 0.f) + w1v*fmaxf(d[nt][1] + b1v, 0.f);
        att1 += w0v*fmaxf(d[nt][2] + b0v, 0.f) + w1v*fmaxf(d[nt][3] + b1v, 0.f);
    }
    att0 += __shfl_xor_sync(0xFFFFFFFF, att0, 1);
    att0 += __shfl_xor_sync(0xFFFFFFFF, att0, 2);
    att1 += __shfl_xor_sync(0xFFFFFFFF, att1, 1);
    att1 += __shfl_xor_sync(0xFFFFFFFF, att1, 2);
    __syncthreads();

    if ((lane & 3) == 0) {
        float bb = bab2[0];
        #pragma unroll
        for (int r = 0; r < 2; r++) {
            int m = r ? m1 : m0;
            float att = (r ? att1 : att0) + bb;
            float ed = (s_ep[0][m] + s_ep[1][m]) * (1.f/32.f);
            float sx =  s_sp[0][m] + s_sp[1][m];
            float z = att + ed;
            float a = 1.f / (1.f + expf(-z));
            float gv = 1.f + a;
            int mh = m >> 5, mw = m & 31;
            size_t pix = (size_t)b*HWSZ + (size_t)(h0 + mh)*WW + (w0 + mw);
            g_gmap[pix] = gv;
            g_smap[pix] = gv * sx;
        }
    }
}

// ---------------- K3: fusion GEMM, m-split, prefetched loads (unchanged) ---
__global__ __launch_bounds__(256)
void fusion_k(const float* __restrict__ in, const float* __restrict__ wsrc,
              const float* __restrict__ bsrc, float* __restrict__ outp)
{
    __shared__ __align__(16) float s_w[64][32];
    __shared__ float s_b[32];
    const int tid = threadIdx.x;
    const int ms  = blockIdx.y;
    const int b   = blockIdx.z;
    for (int i = tid; i < 2048; i += 256) {
        int ci = i >> 5, m = i & 31;
        s_w[ci][m] = wsrc[(ms*32 + m)*64 + ci];
    }
    if (tid < 32) s_b[tid] = bsrc[ms*32 + tid];
    __syncthreads();

    const int mg    = tid >> 6;
    const int mbase = mg*8;
    const int slot  = tid & 63;
    const int pix   = blockIdx.x*256 + slot*4;
    const float* basep = in + (size_t)b*64*HWSZ + pix;

    ull acc[4][4];
    #pragma unroll
    for (int m = 0; m < 4; m++)
        #pragma unroll
        for (int p = 0; p < 4; p++) acc[m][p] = 0ULL;

    float4 xv[4];
    #pragma unroll
    for (int j = 0; j < 4; j++)
        xv[j] = *(const float4*)(basep + (size_t)j*HWSZ);

    #pragma unroll 1
    for (int c4 = 0; c4 < 16; c4++) {
        float4 xn[4];
        if (c4 < 15) {
            const float* bp = basep + (size_t)(c4+1)*4*HWSZ;
            #pragma unroll
            for (int j = 0; j < 4; j++)
                xn[j] = *(const float4*)(bp + (size_t)j*HWSZ);
        }
        #pragma unroll
        for (int j = 0; j < 4; j++) {
            ull xd0 = pk2(xv[j].x, xv[j].x);
            ull xd1 = pk2(xv[j].y, xv[j].y);
            ull xd2 = pk2(xv[j].z, xv[j].z);
            ull xd3 = pk2(xv[j].w, xv[j].w);
            const ulonglong2* wp = (const ulonglong2*)&s_w[c4*4 + j][mbase];
            ulonglong2 wA = wp[0], wB = wp[1];
            acc[0][0]=f2fma(wA.x,xd0,acc[0][0]); acc[0][1]=f2fma(wA.x,xd1,acc[0][1]);
            acc[0][2]=f2fma(wA.x,xd2,acc[0][2]); acc[0][3]=f2fma(wA.x,xd3,acc[0][3]);
            acc[1][0]=f2fma(wA.y,xd0,acc[1][0]); acc[1][1]=f2fma(wA.y,xd1,acc[1][1]);
            acc[1][2]=f2fma(wA.y,xd2,acc[1][2]); acc[1][3]=f2fma(wA.y,xd3,acc[1][3]);
            acc[2][0]=f2fma(wB.x,xd0,acc[2][0]); acc[2][1]=f2fma(wB.x,xd1,acc[2][1]);
            acc[2][2]=f2fma(wB.x,xd2,acc[2][2]); acc[2][3]=f2fma(wB.x,xd3,acc[2][3]);
            acc[3][0]=f2fma(wB.y,xd0,acc[3][0]); acc[3][1]=f2fma(wB.y,xd1,acc[3][1]);
            acc[3][2]=f2fma(wB.y,xd2,acc[3][2]); acc[3][3]=f2fma(wB.y,xd3,acc[3][3]);
        }
        if (c4 < 15) {
            #pragma unroll
            for (int j = 0; j < 4; j++) xv[j] = xn[j];
        }
    }

    float4 gv = *(const float4*)&g_gmap[(size_t)b*HWSZ + pix];
    float4 sv = *(const float4*)&g_smap[(size_t)b*HWSZ + pix];
    float gs[4] = {gv.x, gv.y, gv.z, gv.w};
    float ss[4] = {sv.x, sv.y, sv.z, sv.w};
    #pragma unroll
    for (int mp = 0; mp < 4; mp++) {
        int ch = ms*32 + mbase + 2*mp;
        float b0 = s_b[mbase + 2*mp], b1 = s_b[mbase + 2*mp + 1];
        float lo[4], hi[4];
        #pragma unroll
        for (int p = 0; p < 4; p++) {
            float alo, ahi;
            upk2(acc[mp][p], alo, ahi);
            lo[p] = ss[p] * (gs[p]*alo + b0);
            hi[p] = ss[p] * (gs[p]*ahi + b1);
        }
        float4 vlo = {lo[0], lo[1], lo[2], lo[3]};
        float4 vhi = {hi[0], hi[1], hi[2], hi[3]};
        *(float4*)&outp[((size_t)(b*64 + ch  ))*HWSZ + pix] = vlo;
        *(float4*)&outp[((size_t)(b*64 + ch+1))*HWSZ + pix] = vhi;
    }
}

// ---------------- K4: conv3x3<64> + fc + residual via bf16 mma.sync --------
// Padded strides: conv CPAD=40 (80B rows), fc FPAD=72 (144B rows) -> no conflicts.
__global__ __launch_bounds__(256)
void conv64fc_mma(const float* __restrict__ fus,
                  const uint4* __restrict__ wf, const float* __restrict__ b2,
                  const uint4* __restrict__ fcf, const float* __restrict__ fcb,
                  const float* __restrict__ resid, float* __restrict__ out)
{
    __shared__ __align__(16) uint16_t s_buf[2*128*FPAD];   // 36864B
    __shared__ float s_b2[64], s_fcb[64];

    const int tid = threadIdx.x;
    const int wid = tid >> 5, lane = tid & 31;
    const int g = lane >> 2, t2 = (lane & 3) * 2;
    const int b  = blockIdx.z;
    const int w0 = blockIdx.x*32, h0 = blockIdx.y*4;

    if (tid < 64) { s_b2[tid] = b2[tid]; s_fcb[tid] = fcb[tid]; }

    uint16_t* s_hi = s_buf;            // [204][CPAD] (8160 u16)
    uint16_t* s_lo = s_buf + 128*FPAD; // second half (9216 u16 region)

    const int m0 = wid*16 + g, m1 = m0 + 8;
    const int ph0 = m0 >> 5, pw0 = m0 & 31;
    const int ph1 = m1 >> 5, pw1 = m1 & 31;

    float d[8][4];
    #pragma unroll
    for (int nt = 0; nt < 8; nt++)
        #pragma unroll
        for (int i = 0; i < 4; i++) d[nt][i] = 0.f;

    for (int kh = 0; kh < 2; kh++) {
        if (kh) __syncthreads();
        #pragma unroll
        for (int it = 0; it < 13; it++) {
            int idx = tid + it*256;
            if (idx < 3264) {
                int hw = idx >> 4, cp = idx & 15;
                int h = hw / 34, w = hw % 34;
                int gh = h0 - 1 + h, gw = w0 - 1 + w;
                bool inb = (gh >= 0 && gh < HH && gw >= 0 && gw < WW);
                int ci = kh*32 + cp*2;
                const float* fp = fus + ((size_t)(b*64 + ci))*HWSZ + (inb ? gh*WW + gw : 0);
                float v0 = inb ? fp[0] : 0.f;
                float v1 = inb ? fp[HWSZ] : 0.f;
                __nv_bfloat16 h0b = __float2bfloat16(v0);
                __nv_bfloat16 h1b = __float2bfloat16(v1);
                uint32_t hiw = (uint32_t)(*(uint16_t*)&h0b) | ((uint32_t)(*(uint16_t*)&h1b) << 16);
                uint32_t low = bfpack2(v0 - __bfloat162float(h0b), v1 - __bfloat162float(h1b));
                *(uint32_t*)&s_hi[hw*CPAD + cp*2] = hiw;
                *(uint32_t*)&s_lo[hw*CPAD + cp*2] = low;
            }
        }
        __syncthreads();

        for (int t = 0; t < 9; t++) {
            const int dr = t/3, dc = t%3;
            const int r0 = ((ph0 + dr)*34 + pw0 + dc)*CPAD;
            const int r1 = ((ph1 + dr)*34 + pw1 + dc)*CPAD;
            #pragma unroll
            for (int ks = 0; ks < 2; ks++) {
                uint4 bfr[8];
                const uint4* wp = wf + (size_t)(((t*2 + kh)*2 + ks)*8)*32 + lane;
                #pragma unroll
                for (int nt = 0; nt < 8; nt++) bfr[nt] = wp[nt*32];

                const int k = ks*16 + t2;
                uint32_t ah[4], al[4];
                ah[0] = *(const uint32_t*)&s_hi[r0 + k];
                ah[1] = *(const uint32_t*)&s_hi[r1 + k];
                ah[2] = *(const uint32_t*)&s_hi[r0 + k + 8];
                ah[3] = *(const uint32_t*)&s_hi[r1 + k + 8];
                al[0] = *(const uint32_t*)&s_lo[r0 + k];
                al[1] = *(const uint32_t*)&s_lo[r1 + k];
                al[2] = *(const uint32_t*)&s_lo[r0 + k + 8];
                al[3] = *(const uint32_t*)&s_lo[r1 + k + 8];

                #pragma unroll
                for (int nt = 0; nt < 8; nt++) {
                    mma_bf16(d[nt], ah, bfr[nt].x, bfr[nt].y);
                    mma_bf16(d[nt], al, bfr[nt].x, bfr[nt].y);
                    mma_bf16(d[nt], ah, bfr[nt].z, bfr[nt].w);
                }
            }
        }
    }
    __syncthreads();

    uint16_t* f_hi = s_buf;
    uint16_t* f_lo = s_buf + 128*FPAD;
    #pragma unroll
    for (int nt = 0; nt < 8; nt++) {
        int oc = nt*8 + t2;
        float b0v = s_b2[oc], b1v = s_b2[oc+1];
        float v00 = fmaxf(d[nt][0] + b0v, 0.f);
        float v01 = fmaxf(d[nt][1] + b1v, 0.f);
        float v10 = fmaxf(d[nt][2] + b0v, 0.f);
        float v11 = fmaxf(d[nt][3] + b1v, 0.f);
        __nv_bfloat16 h00 = __float2bfloat16(v00), h01 = __float2bfloat16(v01);
        __nv_bfloat16 h10 = __float2bfloat16(v10), h11 = __float2bfloat16(v11);
        *(uint32_t*)&f_hi[m0*FPAD + oc] =
            (uint32_t)(*(uint16_t*)&h00) | ((uint32_t)(*(uint16_t*)&h01) << 16);
        *(uint32_t*)&f_hi[m1*FPAD + oc] =
            (uint32_t)(*(uint16_t*)&h10) | ((uint32_t)(*(uint16_t*)&h11) << 16);
        *(uint32_t*)&f_lo[m0*FPAD + oc] =
            bfpack2(v00 - __bfloat162float(h00), v01 - __bfloat162float(h01));
        *(uint32_t*)&f_lo[m1*FPAD + oc] =
            bfpack2(v10 - __bfloat162float(h10), v11 - __bfloat162float(h11));
    }
    __syncthreads();

    float e[8][4];
    #pragma unroll
    for (int nt = 0; nt < 8; nt++)
        #pragma unroll
        for (int i = 0; i < 4; i++) e[nt][i] = 0.f;

    #pragma unroll
    for (int ks = 0; ks < 4; ks++) {
        uint4 bfr[8];
        const uint4* wp = fcf + (ks*8)*32 + lane;
        #pragma unroll
        for (int nt = 0; nt < 8; nt++) bfr[nt] = wp[nt*32];

        const int k = ks*16 + t2;
        uint32_t ah[4], al[4];
        ah[0] = *(const uint32_t*)&f_hi[m0*FPAD + k];
        ah[1] = *(const uint32_t*)&f_hi[m1*FPAD + k];
        ah[2] = *(const uint32_t*)&f_hi[m0*FPAD + k + 8];
        ah[3] = *(const uint32_t*)&f_hi[m1*FPAD + k + 8];
        al[0] = *(const uint32_t*)&f_lo[m0*FPAD + k];
        al[1] = *(const uint32_t*)&f_lo[m1*FPAD + k];
        al[2] = *(const uint32_t*)&f_lo[m0*FPAD + k + 8];
        al[3] = *(const uint32_t*)&f_lo[m1*FPAD + k + 8];

        #pragma unroll
        for (int nt = 0; nt < 8; nt++) {
            mma_bf16(e[nt], ah, bfr[nt].x, bfr[nt].y);
            mma_bf16(e[nt], al, bfr[nt].x, bfr[nt].y);
            mma_bf16(e[nt], ah, bfr[nt].z, bfr[nt].w);
        }
    }

    const size_t base = (size_t)b*64*HWSZ;
    const int p0 = (h0 + ph0)*WW + w0 + pw0;
    const int p1 = (h0 + ph1)*WW + w0 + pw1;
    #pragma unroll
    for (int nt = 0; nt < 8; nt++) {
        int oc = nt*8 + t2;
        size_t i00 = base + (size_t)oc*HWSZ + p0;
        size_t i01 = i00 + HWSZ;
        size_t i10 = base + (size_t)oc*HWSZ + p1;
        size_t i11 = i10 + HWSZ;
        out[i00] = e[nt][0] + s_fcb[oc]   + resid[i00];
        out[i01] = e[nt][1] + s_fcb[oc+1] + resid[i01];
        out[i10] = e[nt][2] + s_fcb[oc]   + resid[i10];
        out[i11] = e[nt][3] + s_fcb[oc+1] + resid[i11];
    }
}

// ---------------------------------------------------------------------------
extern "C" void kernel_launch(void* const* d_in, const int* in_sizes, int n_in,
                              void* d_out, int out_size)
{
    (void)in_sizes; (void)n_in; (void)out_size;
    const float* x     = (const float*)d_in[0];
    const float* ba_w1 = (const float*)d_in[1];
    const float* ba_b1 = (const float*)d_in[2];
    const float* ba_w2 = (const float*)d_in[3];
    const float* ba_b2 = (const float*)d_in[4];
    // d_in[5..12]: offset branch — dead code in the reference, skipped.
    const float* rk5w  = (const float*)d_in[13];
    const float* rk5b  = (const float*)d_in[14];
    const float* rk7w  = (const float*)d_in[15];
    const float* rk7b  = (const float*)d_in[16];
    const float* lk5w  = (const float*)d_in[17];
    const float* lk5b  = (const float*)d_in[18];
    const float* lk7w  = (const float*)d_in[19];
    const float* lk7b  = (const float*)d_in[20];
    const float* sfw   = (const float*)d_in[21];
    const float* sfb   = (const float*)d_in[22];
    const float* sfg   = (const float*)d_in[23];
    const float* sfbb  = (const float*)d_in[24];
    const float* sfm   = (const float*)d_in[25];
    const float* sfv   = (const float*)d_in[26];
    const float* fcw   = (const float*)d_in[27];
    const float* fcb   = (const float*)d_in[28];
    float* out = (float*)d_out;

    float *pFus, *pWeff, *pBeff, *pB2;
    uint4 *pWf, *pFcf, *pWf1;
    cudaGetSymbolAddress((void**)&pFus,  g_fusion);
    cudaGetSymbolAddress((void**)&pWeff, g_Weff);
    cudaGetSymbolAddress((void**)&pBeff, g_beff);
    cudaGetSymbolAddress((void**)&pB2,   g_b2);
    cudaGetSymbolAddress((void**)&pWf,   g_wf);
    cudaGetSymbolAddress((void**)&pFcf,  g_fcf);
    cudaGetSymbolAddress((void**)&pWf1,  g_wf1);

    build_weff<<<16, 256>>>(rk5w, rk5b, rk7w, rk7b, lk5w, lk5b, lk7w, lk7b);
    prep_b<<<1, 64>>>(sfb, sfg, sfbb, sfm, sfv);
    prep_frag<<<58, 256>>>(sfw, sfg, sfv, fcw, ba_w1);

    conv32_edge_mma<<<dim3(WW/32, HH/4, BB), 256>>>(x, pWf1, ba_b1, ba_w2, ba_b2);
    fusion_k<<<dim3(HWSZ/256, 2, BB), 256>>>(x, pWeff, pBeff, pFus);
    conv64fc_mma<<<dim3(WW/32, HH/4, BB), 256>>>(pFus, pWf, pB2, pFcf, fcb, x, out);
}